// round 1
// baseline (speedup 1.0000x reference)
#include <cuda_runtime.h>
#include <math.h>

// ---------------- problem constants ----------------
constexpr int Bn  = 8;
constexpr int Tt  = 16;
constexpr int Hh  = 14;
constexpr int Ww  = 14;
constexpr int D   = 768;
constexpr int NHh = 12;
constexpr int HID = 3072;
constexpr int Np  = Hh * Ww * Tt;      // 3136 tokens per batch (no cls)
constexpr int MT  = Bn * Np;           // 25088 temporal tokens
constexpr int SSP = 1 + Hh * Ww;       // 197 spatial seq len
constexpr int MS  = Bn * Tt * SSP;     // 25216 spatial tokens
constexpr int MX  = Bn * (1 + Np);     // 25096 output tokens

// ---------------- scratch (device globals; no allocation allowed) ----------------
__device__ float g_xnc [MT * D];        // x without cls, contiguous
__device__ float g_ln  [MS * D];        // layernorm scratch (max rows)
__device__ float g_qkv [MS * 3 * D];    // qkv scratch (max rows)
__device__ float g_attn[MS * D];        // attention output scratch
__device__ float g_rt  [MS * D];        // rt / rs scratch
__device__ float g_xt2 [MT * D];
__device__ float g_xnew[MX * D];
__device__ float g_hid [MX * HID];
__device__ float g_cls [Bn * D];

// ---------------- helpers ----------------
__device__ __forceinline__ float gelu_exact(float v) {
    return 0.5f * v * (1.0f + erff(v * 0.70710678118654752440f));
}

// LayerNorm over one row of 768, 256 threads per block
__device__ __forceinline__ void ln_row(const float* __restrict__ src,
                                       const float* __restrict__ w,
                                       const float* __restrict__ bvec,
                                       float* __restrict__ dst) {
    int tid = threadIdx.x;
    float v0 = src[tid], v1 = src[tid + 256], v2 = src[tid + 512];
    float s  = v0 + v1 + v2;
    float ss = v0 * v0 + v1 * v1 + v2 * v2;
    __shared__ float red[18];
#pragma unroll
    for (int o = 16; o; o >>= 1) {
        s  += __shfl_down_sync(0xffffffffu, s,  o);
        ss += __shfl_down_sync(0xffffffffu, ss, o);
    }
    if ((tid & 31) == 0) { red[tid >> 5] = s; red[8 + (tid >> 5)] = ss; }
    __syncthreads();
    if (tid == 0) {
        float a = 0.f, b2 = 0.f;
#pragma unroll
        for (int i = 0; i < 8; i++) { a += red[i]; b2 += red[8 + i]; }
        red[16] = a * (1.0f / 768.0f);
        red[17] = b2 * (1.0f / 768.0f);
    }
    __syncthreads();
    float mean = red[16];
    float var  = red[17] - mean * mean;
    float rstd = rsqrtf(var + 1e-5f);
    dst[tid]       = (v0 - mean) * rstd * w[tid]       + bvec[tid];
    dst[tid + 256] = (v1 - mean) * rstd * w[tid + 256] + bvec[tid + 256];
    dst[tid + 512] = (v2 - mean) * rstd * w[tid + 512] + bvec[tid + 512];
}

__global__ void ln_rows_kernel(const float* __restrict__ src,
                               const float* __restrict__ w,
                               const float* __restrict__ bvec,
                               float* __restrict__ dst) {
    int r = blockIdx.x;
    ln_row(src + (size_t)r * D, w, bvec, dst + (size_t)r * D);
}

// LN over gathered spatial sequence: row r -> (bt = r/197, j = r%197)
// j==0: cls from x[b,0]; else xt2[b, (j-1)*16 + t]
__global__ void ln_xs_kernel(const float* __restrict__ x,
                             const float* __restrict__ xt2,
                             const float* __restrict__ w,
                             const float* __restrict__ bvec,
                             float* __restrict__ dst) {
    int r  = blockIdx.x;
    int bt = r / SSP, j = r % SSP;
    int b  = bt >> 4, t = bt & 15;
    const float* src = (j == 0)
        ? (x + (size_t)b * (1 + Np) * D)
        : (xt2 + ((size_t)(b * Np + (j - 1) * Tt + t)) * D);
    ln_row(src, w, bvec, dst + (size_t)r * D);
}

// gather x[:,1:,:] into contiguous buffer (float4 granularity)
__global__ void gather_xnc(const float* __restrict__ x, float* __restrict__ out) {
    int q = blockIdx.x * blockDim.x + threadIdx.x;
    if (q >= MT * (D / 4)) return;
    int r = q / (D / 4), c = q % (D / 4);
    int b = r / Np, n = r % Np;
    const float4* src = (const float4*)(x + ((size_t)(b * (1 + Np) + 1 + n)) * D) + c;
    ((float4*)(out + (size_t)r * D))[c] = *src;
}

// ---------------- SGEMM: C[M,N] = A[M,K] @ B[K,N] (+epilogue) ----------------
// EPI: 0=none, 1=+bias, 2=+bias+residual, 3=+bias+gelu
template <int EPI>
__global__ void sgemm_k(int M, int N, int K,
                        const float* __restrict__ A,
                        const float* __restrict__ Bw,
                        const float* __restrict__ bias,
                        const float* __restrict__ Res,
                        float* __restrict__ C) {
    __shared__ float As[8][128];
    __shared__ float Bs[8][128];
    const int tid  = threadIdx.x;
    const int cRow = blockIdx.y, cCol = blockIdx.x;
    const int tRow = (tid / 16) * 8, tCol = (tid % 16) * 8;
    const int aRow = tid >> 1, aCol = (tid & 1) * 4;
    const int bRow = tid >> 5, bCol = (tid & 31) * 4;

    float acc[8][8] = {};
    const int rowA = cRow * 128 + aRow;
    const bool aval = rowA < M;
    const float* Aptr = A + (size_t)rowA * K + aCol;
    const float* Bptr = Bw + (size_t)bRow * N + cCol * 128 + bCol;

    for (int k0 = 0; k0 < K; k0 += 8) {
        float4 av = aval ? *(const float4*)(Aptr + k0) : make_float4(0.f, 0.f, 0.f, 0.f);
        float4 bv = *(const float4*)(Bptr + (size_t)k0 * N);
        As[aCol + 0][aRow] = av.x;
        As[aCol + 1][aRow] = av.y;
        As[aCol + 2][aRow] = av.z;
        As[aCol + 3][aRow] = av.w;
        *(float4*)&Bs[bRow][bCol] = bv;
        __syncthreads();
#pragma unroll
        for (int k = 0; k < 8; k++) {
            float ra[8], rb[8];
#pragma unroll
            for (int i = 0; i < 8; i++) ra[i] = As[k][tRow + i];
#pragma unroll
            for (int j = 0; j < 8; j++) rb[j] = Bs[k][tCol + j];
#pragma unroll
            for (int i = 0; i < 8; i++)
#pragma unroll
                for (int j = 0; j < 8; j++)
                    acc[i][j] += ra[i] * rb[j];
        }
        __syncthreads();
    }

#pragma unroll
    for (int i = 0; i < 8; i++) {
        int row = cRow * 128 + tRow + i;
        if (row < M) {
#pragma unroll
            for (int j = 0; j < 8; j++) {
                int col = cCol * 128 + tCol + j;
                float v = acc[i][j];
                if (EPI >= 1) v += bias[col];
                if (EPI == 2) v += Res[(size_t)row * N + col];
                if (EPI == 3) v = gelu_exact(v);
                C[(size_t)row * N + col] = v;
            }
        }
    }
}

// ---------------- temporal attention: 1568 x 12 problems of (16 x 16 x 64) ----------------
__global__ void attn_t_kernel(const float* __restrict__ qkv, float* __restrict__ out) {
    int R = blockIdx.x;     // b*196 + s
    int h = blockIdx.y;
    __shared__ float Qs[16 * 64], Ks[16 * 65], Vs[16 * 64], Ps[16 * 17];
    int tid = threadIdx.x;  // 128 threads
    for (int idx = tid; idx < 1024; idx += 128) {
        int t = idx >> 6, d = idx & 63;
        const float* p = qkv + (size_t)(R * 16 + t) * (3 * D) + h * 64 + d;
        Qs[t * 64 + d] = p[0];
        Ks[t * 65 + d] = p[D];
        Vs[t * 64 + d] = p[2 * D];
    }
    __syncthreads();
    for (int idx = tid; idx < 256; idx += 128) {
        int i = idx >> 4, j = idx & 15;
        float s = 0.f;
#pragma unroll
        for (int d = 0; d < 64; d++) s += Qs[i * 64 + d] * Ks[j * 65 + d];
        Ps[i * 17 + j] = s * 0.125f;
    }
    __syncthreads();
    if (tid < 16) {
        float m = -1e30f;
#pragma unroll
        for (int j = 0; j < 16; j++) m = fmaxf(m, Ps[tid * 17 + j]);
        float sum = 0.f, e[16];
#pragma unroll
        for (int j = 0; j < 16; j++) { e[j] = __expf(Ps[tid * 17 + j] - m); sum += e[j]; }
        float inv = 1.0f / sum;
#pragma unroll
        for (int j = 0; j < 16; j++) Ps[tid * 17 + j] = e[j] * inv;
    }
    __syncthreads();
    for (int idx = tid; idx < 1024; idx += 128) {
        int i = idx >> 6, d = idx & 63;
        float a = 0.f;
#pragma unroll
        for (int j = 0; j < 16; j++) a += Ps[i * 17 + j] * Vs[j * 64 + d];
        out[(size_t)(R * 16 + i) * D + h * 64 + d] = a;
    }
}

// ---------------- spatial attention: 128 x 12 problems of (197 x 197 x 64) ----------------
constexpr int SKV    = SSP * 65;                     // padded K/V row stride
constexpr int SMEM_S = (2 * SKV + 8 * 64) * 4;       // bytes

__global__ void attn_s_kernel(const float* __restrict__ qkv, float* __restrict__ out) {
    int bt = blockIdx.x;   // b*16 + t
    int h  = blockIdx.y;
    extern __shared__ float sm[];
    float* Ks = sm;
    float* Vs = sm + SKV;
    float* Qs = Vs + SKV;  // 8 warps x 64
    int tid = threadIdx.x; // 256 threads

    for (int idx = tid; idx < SSP * 64; idx += 256) {
        int j = idx >> 6, d = idx & 63;
        const float* p = qkv + (size_t)(bt * SSP + j) * (3 * D) + h * 64 + d;
        Ks[j * 65 + d] = p[D];
        Vs[j * 65 + d] = p[2 * D];
    }
    __syncthreads();

    int warp = tid >> 5, lane = tid & 31;
    for (int q = warp; q < SSP; q += 8) {
        const float* qp = qkv + (size_t)(bt * SSP + q) * (3 * D) + h * 64;
        Qs[warp * 64 + lane]      = qp[lane];
        Qs[warp * 64 + lane + 32] = qp[lane + 32];
        __syncwarp();

        float sc[7];
        float m = -1e30f;
#pragma unroll
        for (int jj = 0; jj < 7; jj++) {
            int j = jj * 32 + lane;
            float s = -1e30f;
            if (j < SSP) {
                s = 0.f;
#pragma unroll
                for (int d = 0; d < 64; d++) s += Qs[warp * 64 + d] * Ks[j * 65 + d];
                s *= 0.125f;
            }
            sc[jj] = s;
            m = fmaxf(m, s);
        }
#pragma unroll
        for (int o = 16; o; o >>= 1) m = fmaxf(m, __shfl_xor_sync(0xffffffffu, m, o));
        float sum = 0.f;
#pragma unroll
        for (int jj = 0; jj < 7; jj++) {
            int j = jj * 32 + lane;
            float e = (j < SSP) ? __expf(sc[jj] - m) : 0.0f;
            sc[jj] = e;
            sum += e;
        }
#pragma unroll
        for (int o = 16; o; o >>= 1) sum += __shfl_xor_sync(0xffffffffu, sum, o);
        float inv = 1.0f / sum;

        float a0 = 0.f, a1 = 0.f;
#pragma unroll
        for (int jj = 0; jj < 7; jj++) {
            int jbase = jj * 32;
            int lim = min(32, SSP - jbase);
            for (int l = 0; l < lim; l++) {
                float p = __shfl_sync(0xffffffffu, sc[jj], l);
                int j = jbase + l;
                a0 += p * Vs[j * 65 + lane];
                a1 += p * Vs[j * 65 + lane + 32];
            }
        }
        float* op = out + (size_t)(bt * SSP + q) * D + h * 64;
        op[lane]      = a0 * inv;
        op[lane + 32] = a1 * inv;
        __syncwarp();
    }
}

// cls_out[b] = mean over t of rs[bt*197 + 0]
__global__ void cls_mean_kernel(const float* __restrict__ rs, float* __restrict__ cls) {
    int b = blockIdx.x;
    int c = threadIdx.x;  // 768 threads
    float s = 0.f;
#pragma unroll
    for (int t = 0; t < Tt; t++) s += rs[(size_t)((b * Tt + t) * SSP) * D + c];
    cls[b * D + c] = s * (1.0f / 16.0f);
}

// x_new = concat(init_cls, xt2) + concat(cls_out, rs_mapped)
__global__ void build_xnew_kernel(const float* __restrict__ x,
                                  const float* __restrict__ xt2,
                                  const float* __restrict__ rs,
                                  const float* __restrict__ cls,
                                  float* __restrict__ out) {
    int idx = blockIdx.x * blockDim.x + threadIdx.x;
    if (idx >= MX * D) return;
    int r = idx / D, c = idx % D;
    int b = r / (1 + Np), p = r % (1 + Np);
    float v;
    if (p == 0) {
        v = x[idx] + cls[b * D + c];
    } else {
        int n = p - 1;
        int s = n >> 4, t = n & 15;
        v = xt2[(size_t)(b * Np + n) * D + c]
          + rs[(size_t)((b * Tt + t) * SSP + 1 + s) * D + c];
    }
    out[idx] = v;
}

// ---------------- launch ----------------
extern "C" void kernel_launch(void* const* d_in, const int* in_sizes, int n_in,
                              void* d_out, int out_size) {
    const float* x        = (const float*)d_in[0];
    const float* tn1_w    = (const float*)d_in[1];
    const float* tn1_b    = (const float*)d_in[2];
    const float* t_qkv_w  = (const float*)d_in[3];
    const float* t_proj_w = (const float*)d_in[4];
    const float* t_proj_b = (const float*)d_in[5];
    const float* tfc_w    = (const float*)d_in[6];
    const float* tfc_b    = (const float*)d_in[7];
    const float* n1_w     = (const float*)d_in[8];
    const float* n1_b     = (const float*)d_in[9];
    const float* s_qkv_w  = (const float*)d_in[10];
    const float* s_proj_w = (const float*)d_in[11];
    const float* s_proj_b = (const float*)d_in[12];
    const float* n2_w     = (const float*)d_in[13];
    const float* n2_b     = (const float*)d_in[14];
    const float* fc1_w    = (const float*)d_in[15];
    const float* fc1_b    = (const float*)d_in[16];
    const float* fc2_w    = (const float*)d_in[17];
    const float* fc2_b    = (const float*)d_in[18];
    float* out = (float*)d_out;

    float *p_xnc, *p_ln, *p_qkv, *p_attn, *p_rt, *p_xt2, *p_xnew, *p_hid, *p_cls;
    cudaGetSymbolAddress((void**)&p_xnc,  g_xnc);
    cudaGetSymbolAddress((void**)&p_ln,   g_ln);
    cudaGetSymbolAddress((void**)&p_qkv,  g_qkv);
    cudaGetSymbolAddress((void**)&p_attn, g_attn);
    cudaGetSymbolAddress((void**)&p_rt,   g_rt);
    cudaGetSymbolAddress((void**)&p_xt2,  g_xt2);
    cudaGetSymbolAddress((void**)&p_xnew, g_xnew);
    cudaGetSymbolAddress((void**)&p_hid,  g_hid);
    cudaGetSymbolAddress((void**)&p_cls,  g_cls);

    cudaFuncSetAttribute(attn_s_kernel, cudaFuncAttributeMaxDynamicSharedMemorySize, SMEM_S);

    // 1) x[:,1:] -> contiguous
    gather_xnc<<<(MT * (D / 4) + 255) / 256, 256>>>(x, p_xnc);

    // 2) temporal LN
    ln_rows_kernel<<<MT, 256>>>(p_xnc, tn1_w, tn1_b, p_ln);

    // 3) temporal qkv
    sgemm_k<0><<<dim3(3 * D / 128, (MT + 127) / 128), 256>>>(MT, 3 * D, D, p_ln, t_qkv_w, nullptr, nullptr, p_qkv);

    // 4) temporal attention
    attn_t_kernel<<<dim3(Bn * Hh * Ww, NHh), 128>>>(p_qkv, p_attn);

    // 5) temporal proj
    sgemm_k<1><<<dim3(D / 128, (MT + 127) / 128), 256>>>(MT, D, D, p_attn, t_proj_w, t_proj_b, nullptr, p_rt);

    // 6) tfc + residual (x[:,1:]) -> xt2
    sgemm_k<2><<<dim3(D / 128, (MT + 127) / 128), 256>>>(MT, D, D, p_rt, tfc_w, tfc_b, p_xnc, p_xt2);

    // 7) spatial LN (with cls gather)
    ln_xs_kernel<<<MS, 256>>>(x, p_xt2, n1_w, n1_b, p_ln);

    // 8) spatial qkv
    sgemm_k<0><<<dim3(3 * D / 128, (MS + 127) / 128), 256>>>(MS, 3 * D, D, p_ln, s_qkv_w, nullptr, nullptr, p_qkv);

    // 9) spatial attention
    attn_s_kernel<<<dim3(Bn * Tt, NHh), 256, SMEM_S>>>(p_qkv, p_attn);

    // 10) spatial proj -> rs
    sgemm_k<1><<<dim3(D / 128, (MS + 127) / 128), 256>>>(MS, D, D, p_attn, s_proj_w, s_proj_b, nullptr, p_rt);

    // 11) cls mean over time
    cls_mean_kernel<<<Bn, D>>>(p_rt, p_cls);

    // 12) x_new assembly
    build_xnew_kernel<<<(MX * D + 255) / 256, 256>>>(x, p_xt2, p_rt, p_cls, p_xnew);

    // 13) final LN
    ln_rows_kernel<<<MX, 256>>>(p_xnew, n2_w, n2_b, p_ln);

    // 14) fc1 + gelu
    sgemm_k<3><<<dim3(HID / 128, (MX + 127) / 128), 256>>>(MX, HID, D, p_ln, fc1_w, fc1_b, nullptr, p_hid);

    // 15) fc2 + residual -> out
    sgemm_k<2><<<dim3(D / 128, (MX + 127) / 128), 256>>>(MX, D, HID, p_hid, fc2_w, fc2_b, p_xnew, out);
}

// round 3
// speedup vs baseline: 3.9058x; 3.9058x over previous
#include <cuda_runtime.h>
#include <cuda_fp16.h>
#include <math.h>
#include <stdint.h>

// ---------------- problem constants ----------------
constexpr int Bn  = 8;
constexpr int Tt  = 16;
constexpr int Hh  = 14;
constexpr int Ww  = 14;
constexpr int D   = 768;
constexpr int NHh = 12;
constexpr int HID = 3072;
constexpr int Np  = Hh * Ww * Tt;      // 3136
constexpr int MT  = Bn * Np;           // 25088 (=196*128)
constexpr int SSP = 1 + Hh * Ww;       // 197
constexpr int MS  = Bn * Tt * SSP;     // 25216 (=197*128)
constexpr int MX  = Bn * (1 + Np);     // 25096
constexpr int MXP = 25216;             // MX padded to 128

// ---------------- scratch ----------------
__device__ float  g_xnc [MT * D];
__device__ __half g_lnh [MS * D];
__device__ float  g_qkv [MS * 3 * D];
__device__ __half g_atth[MS * D];
__device__ __half g_rth [MT * D];
__device__ float  g_rs  [MS * D];
__device__ float  g_xt2 [MT * D];
__device__ float  g_xnew[MX * D];
__device__ __half g_hidh[MXP * HID];
__device__ float  g_cls [Bn * D];
__device__ __half g_wt  [HID * D];     // transposed half weights (max 3072*768)

// ---------------- PTX helpers ----------------
__device__ __forceinline__ uint32_t smem_u32(const void* p) {
    uint32_t a;
    asm("{ .reg .u64 t; cvta.to.shared.u64 t, %1; cvt.u32.u64 %0, t; }" : "=r"(a) : "l"(p));
    return a;
}
__device__ __forceinline__ float gelu_exact(float v) {
    return 0.5f * v * (1.0f + erff(v * 0.70710678118654752440f));
}

#define CP_ASYNC16(dst, src) \
    asm volatile("cp.async.cg.shared.global [%0], [%1], 16;" :: "r"(dst), "l"(src) : "memory")
#define CP_COMMIT() asm volatile("cp.async.commit_group;" ::: "memory")
#define CP_WAIT0()  asm volatile("cp.async.wait_group 0;" ::: "memory")
#define CP_WAIT1()  asm volatile("cp.async.wait_group 1;" ::: "memory")

#define LDSM4(r, addr) \
    asm volatile("ldmatrix.sync.aligned.m8n8.x4.shared.b16 {%0,%1,%2,%3}, [%4];" \
        : "=r"((r)[0]), "=r"((r)[1]), "=r"((r)[2]), "=r"((r)[3]) : "r"(addr))

#define MMA16816(c, a, b0, b1) \
    asm volatile("mma.sync.aligned.m16n8k16.row.col.f32.f16.f16.f32 " \
        "{%0,%1,%2,%3}, {%4,%5,%6,%7}, {%8,%9}, {%0,%1,%2,%3};" \
        : "+f"((c)[0]), "+f"((c)[1]), "+f"((c)[2]), "+f"((c)[3]) \
        : "r"((a)[0]), "r"((a)[1]), "r"((a)[2]), "r"((a)[3]), "r"(b0), "r"(b1))

// ---------------- weight transpose + fp16 round: Wt[N,K] = h(W[K,N]) ----------------
__global__ void transpose_h(const float* __restrict__ W, __half* __restrict__ Wt, int K, int N) {
    __shared__ float tile[32][33];
    int k0 = blockIdx.x * 32, n0 = blockIdx.y * 32;
    int tx = threadIdx.x, ty = threadIdx.y;  // 32 x 8
    for (int r = ty; r < 32; r += 8) tile[r][tx] = W[(size_t)(k0 + r) * N + n0 + tx];
    __syncthreads();
    for (int r = ty; r < 32; r += 8) Wt[(size_t)(n0 + r) * K + k0 + tx] = __float2half_rn(tile[tx][r]);
}

// ---------------- fp16 tensor-core GEMM: C[M,N] = A[M,K] * Bt[N,K]^T + epilogue ----------------
// EPI: 0=none 1=+bias 2=+bias+residual 3=+bias+gelu ; TO: float or __half output
constexpr int ROWB    = 80;                 // smem row pitch (bytes): (5r+c) mod 8 conflict-free
constexpr int TILE_B  = 128 * ROWB;         // 10240 per operand tile
constexpr int STAGE_B = 2 * TILE_B;         // 20480
constexpr int GS      = 3;
constexpr int GEMM_SMEM = GS * STAGE_B;     // 61440

template <int EPI, typename TO>
__global__ void __launch_bounds__(256, 2) gemm_hmma(
    int Mreal, int N, int K,
    const __half* __restrict__ A, const __half* __restrict__ Bt,
    const float* __restrict__ bias, const float* __restrict__ Res,
    TO* __restrict__ C)
{
    extern __shared__ char smbuf[];
    const uint32_t sb = smem_u32(smbuf);
    const int tid  = threadIdx.x;
    const int wid  = tid >> 5, lane = tid & 31;
    const int wm   = wid & 3,  wn   = wid >> 2;     // warp grid 4(M) x 2(N)
    const int n0   = blockIdx.x * 128, m0 = blockIdx.y * 128;

    auto load_stage = [&](int chunk, int st) {
        uint32_t base = sb + st * STAGE_B;
        const __half* asrc = A  + (size_t)m0 * K + chunk * 32;
        const __half* bsrc = Bt + (size_t)n0 * K + chunk * 32;
        #pragma unroll
        for (int i = 0; i < 2; i++) {
            int idx = tid + i * 256;          // 0..511
            int r = idx >> 2, c = idx & 3;
            CP_ASYNC16(base + r * ROWB + c * 16,          asrc + (size_t)r * K + c * 8);
            CP_ASYNC16(base + TILE_B + r * ROWB + c * 16, bsrc + (size_t)r * K + c * 8);
        }
    };

    const int NC = K / 32;
    load_stage(0, 0); CP_COMMIT();
    load_stage(1, 1); CP_COMMIT();

    float acc[2][8][4];
    #pragma unroll
    for (int i = 0; i < 2; i++)
        #pragma unroll
        for (int j = 0; j < 8; j++)
            #pragma unroll
            for (int q = 0; q < 4; q++) acc[i][j][q] = 0.f;

    const uint32_t lrow = lane & 15;
    const uint32_t lkb  = ((lane >> 4) & 1) * 16;   // byte offset for k-half

    for (int i = 0; i < NC; i++) {
        if (i == NC - 1) CP_WAIT0(); else CP_WAIT1();
        __syncthreads();
        if (i + 2 < NC) { load_stage(i + 2, (i + 2) % GS); CP_COMMIT(); }

        uint32_t As = sb + (i % GS) * STAGE_B;
        uint32_t Bs = As + TILE_B;
        uint32_t abase = As + (wm * 32 + lrow) * ROWB + lkb;
        uint32_t bbase = Bs + (wn * 64 + lrow) * ROWB + lkb;

        #pragma unroll
        for (int ks = 0; ks < 2; ks++) {
            uint32_t a0[4], a1[4];
            LDSM4(a0, abase + ks * 32);
            LDSM4(a1, abase + 16 * ROWB + ks * 32);
            uint32_t bf[4][4];
            #pragma unroll
            for (int p = 0; p < 4; p++)
                LDSM4(bf[p], bbase + p * 16 * ROWB + ks * 32);
            #pragma unroll
            for (int nt = 0; nt < 8; nt++) {
                uint32_t b0 = bf[nt >> 1][nt & 1];
                uint32_t b1 = bf[nt >> 1][(nt & 1) + 2];
                MMA16816(acc[0][nt], a0, b0, b1);
                MMA16816(acc[1][nt], a1, b0, b1);
            }
        }
    }

    // -------- epilogue --------
    const int rbase = m0 + wm * 32 + (lane >> 2);
    const int cbase = n0 + wn * 64 + (lane & 3) * 2;
    #pragma unroll
    for (int mt = 0; mt < 2; mt++) {
        #pragma unroll
        for (int half_r = 0; half_r < 2; half_r++) {
            int row = rbase + mt * 16 + half_r * 8;
            if (row >= Mreal) continue;
            #pragma unroll
            for (int nt = 0; nt < 8; nt++) {
                int col = cbase + nt * 8;
                float v0 = acc[mt][nt][half_r * 2 + 0];
                float v1 = acc[mt][nt][half_r * 2 + 1];
                if (EPI >= 1) { v0 += __ldg(&bias[col]); v1 += __ldg(&bias[col + 1]); }
                if (EPI == 2) {
                    const float2 rv = *(const float2*)(Res + (size_t)row * N + col);
                    v0 += rv.x; v1 += rv.y;
                }
                if (EPI == 3) { v0 = gelu_exact(v0); v1 = gelu_exact(v1); }
                if (sizeof(TO) == 2) {
                    *(__half2*)((__half*)C + (size_t)row * N + col) = __floats2half2_rn(v0, v1);
                } else {
                    *(float2*)((float*)C + (size_t)row * N + col) = make_float2(v0, v1);
                }
            }
        }
    }
}

// ---------------- LayerNorm (fp32 in, half out: always feeds a GEMM) ----------------
__device__ __forceinline__ void ln_row(const float* __restrict__ src,
                                       const float* __restrict__ w,
                                       const float* __restrict__ bvec,
                                       __half* __restrict__ dst) {
    int tid = threadIdx.x;
    float v0 = src[tid], v1 = src[tid + 256], v2 = src[tid + 512];
    float s  = v0 + v1 + v2;
    float ss = v0 * v0 + v1 * v1 + v2 * v2;
    __shared__ float red[18];
#pragma unroll
    for (int o = 16; o; o >>= 1) {
        s  += __shfl_down_sync(0xffffffffu, s,  o);
        ss += __shfl_down_sync(0xffffffffu, ss, o);
    }
    if ((tid & 31) == 0) { red[tid >> 5] = s; red[8 + (tid >> 5)] = ss; }
    __syncthreads();
    if (tid == 0) {
        float a = 0.f, b2 = 0.f;
#pragma unroll
        for (int i = 0; i < 8; i++) { a += red[i]; b2 += red[8 + i]; }
        red[16] = a * (1.0f / 768.0f);
        red[17] = b2 * (1.0f / 768.0f);
    }
    __syncthreads();
    float mean = red[16];
    float var  = red[17] - mean * mean;
    float rstd = rsqrtf(var + 1e-5f);
    dst[tid]       = __float2half_rn((v0 - mean) * rstd * w[tid]       + bvec[tid]);
    dst[tid + 256] = __float2half_rn((v1 - mean) * rstd * w[tid + 256] + bvec[tid + 256]);
    dst[tid + 512] = __float2half_rn((v2 - mean) * rstd * w[tid + 512] + bvec[tid + 512]);
}

__global__ void ln_rows_kernel(const float* __restrict__ src,
                               const float* __restrict__ w,
                               const float* __restrict__ bvec,
                               __half* __restrict__ dst) {
    int r = blockIdx.x;
    ln_row(src + (size_t)r * D, w, bvec, dst + (size_t)r * D);
}

__global__ void ln_xs_kernel(const float* __restrict__ x,
                             const float* __restrict__ xt2,
                             const float* __restrict__ w,
                             const float* __restrict__ bvec,
                             __half* __restrict__ dst) {
    int r  = blockIdx.x;
    int bt = r / SSP, j = r % SSP;
    int b  = bt >> 4, t = bt & 15;
    const float* src = (j == 0)
        ? (x + (size_t)b * (1 + Np) * D)
        : (xt2 + ((size_t)(b * Np + (j - 1) * Tt + t)) * D);
    ln_row(src, w, bvec, dst + (size_t)r * D);
}

__global__ void gather_xnc(const float* __restrict__ x, float* __restrict__ out) {
    int q = blockIdx.x * blockDim.x + threadIdx.x;
    if (q >= MT * (D / 4)) return;
    int r = q / (D / 4), c = q % (D / 4);
    int b = r / Np, n = r % Np;
    const float4* src = (const float4*)(x + ((size_t)(b * (1 + Np) + 1 + n)) * D) + c;
    ((float4*)(out + (size_t)r * D))[c] = *src;
}

// ---------------- temporal attention (fp32 qkv in, half out) ----------------
__global__ void attn_t_kernel(const float* __restrict__ qkv, __half* __restrict__ out) {
    int R = blockIdx.x;
    int h = blockIdx.y;
    __shared__ float Qs[16 * 64], Ks[16 * 65], Vs[16 * 64], Ps[16 * 17];
    int tid = threadIdx.x;
    for (int idx = tid; idx < 1024; idx += 128) {
        int t = idx >> 6, d = idx & 63;
        const float* p = qkv + (size_t)(R * 16 + t) * (3 * D) + h * 64 + d;
        Qs[t * 64 + d] = p[0];
        Ks[t * 65 + d] = p[D];
        Vs[t * 64 + d] = p[2 * D];
    }
    __syncthreads();
    for (int idx = tid; idx < 256; idx += 128) {
        int i = idx >> 4, j = idx & 15;
        float s = 0.f;
#pragma unroll
        for (int d = 0; d < 64; d++) s += Qs[i * 64 + d] * Ks[j * 65 + d];
        Ps[i * 17 + j] = s * 0.125f;
    }
    __syncthreads();
    if (tid < 16) {
        float m = -1e30f;
#pragma unroll
        for (int j = 0; j < 16; j++) m = fmaxf(m, Ps[tid * 17 + j]);
        float sum = 0.f, e[16];
#pragma unroll
        for (int j = 0; j < 16; j++) { e[j] = __expf(Ps[tid * 17 + j] - m); sum += e[j]; }
        float inv = 1.0f / sum;
#pragma unroll
        for (int j = 0; j < 16; j++) Ps[tid * 17 + j] = e[j] * inv;
    }
    __syncthreads();
    for (int idx = tid; idx < 1024; idx += 128) {
        int i = idx >> 6, d = idx & 63;
        float a = 0.f;
#pragma unroll
        for (int j = 0; j < 16; j++) a += Ps[i * 17 + j] * Vs[j * 64 + d];
        out[(size_t)(R * 16 + i) * D + h * 64 + d] = __float2half_rn(a);
    }
}

// ---------------- spatial attention (fp32 qkv in, half out) ----------------
constexpr int SKV    = SSP * 65;
constexpr int SMEM_S = (2 * SKV + 8 * 64) * 4;

__global__ void attn_s_kernel(const float* __restrict__ qkv, __half* __restrict__ out) {
    int bt = blockIdx.x;
    int h  = blockIdx.y;
    extern __shared__ float sm[];
    float* Ks = sm;
    float* Vs = sm + SKV;
    float* Qs = Vs + SKV;
    int tid = threadIdx.x;

    for (int idx = tid; idx < SSP * 64; idx += 256) {
        int j = idx >> 6, d = idx & 63;
        const float* p = qkv + (size_t)(bt * SSP + j) * (3 * D) + h * 64 + d;
        Ks[j * 65 + d] = p[D];
        Vs[j * 65 + d] = p[2 * D];
    }
    __syncthreads();

    int warp = tid >> 5, lane = tid & 31;
    for (int q = warp; q < SSP; q += 8) {
        const float* qp = qkv + (size_t)(bt * SSP + q) * (3 * D) + h * 64;
        Qs[warp * 64 + lane]      = qp[lane];
        Qs[warp * 64 + lane + 32] = qp[lane + 32];
        __syncwarp();

        float sc[7];
        float m = -1e30f;
#pragma unroll
        for (int jj = 0; jj < 7; jj++) {
            int j = jj * 32 + lane;
            float s = -1e30f;
            if (j < SSP) {
                s = 0.f;
#pragma unroll
                for (int d = 0; d < 64; d++) s += Qs[warp * 64 + d] * Ks[j * 65 + d];
                s *= 0.125f;
            }
            sc[jj] = s;
            m = fmaxf(m, s);
        }
#pragma unroll
        for (int o = 16; o; o >>= 1) m = fmaxf(m, __shfl_xor_sync(0xffffffffu, m, o));
        float sum = 0.f;
#pragma unroll
        for (int jj = 0; jj < 7; jj++) {
            int j = jj * 32 + lane;
            float e = (j < SSP) ? __expf(sc[jj] - m) : 0.0f;
            sc[jj] = e;
            sum += e;
        }
#pragma unroll
        for (int o = 16; o; o >>= 1) sum += __shfl_xor_sync(0xffffffffu, sum, o);
        float inv = 1.0f / sum;

        float a0 = 0.f, a1 = 0.f;
#pragma unroll
        for (int jj = 0; jj < 7; jj++) {
            int jbase = jj * 32;
            int lim = min(32, SSP - jbase);
            for (int l = 0; l < lim; l++) {
                float p = __shfl_sync(0xffffffffu, sc[jj], l);
                int j = jbase + l;
                a0 += p * Vs[j * 65 + lane];
                a1 += p * Vs[j * 65 + lane + 32];
            }
        }
        __half* op = out + (size_t)(bt * SSP + q) * D + h * 64;
        op[lane]      = __float2half_rn(a0 * inv);
        op[lane + 32] = __float2half_rn(a1 * inv);
        __syncwarp();
    }
}

__global__ void cls_mean_kernel(const float* __restrict__ rs, float* __restrict__ cls) {
    int b = blockIdx.x;
    int c = threadIdx.x;
    float s = 0.f;
#pragma unroll
    for (int t = 0; t < Tt; t++) s += rs[(size_t)((b * Tt + t) * SSP) * D + c];
    cls[b * D + c] = s * (1.0f / 16.0f);
}

__global__ void build_xnew_kernel(const float* __restrict__ x,
                                  const float* __restrict__ xt2,
                                  const float* __restrict__ rs,
                                  const float* __restrict__ cls,
                                  float* __restrict__ out) {
    int idx = blockIdx.x * blockDim.x + threadIdx.x;
    if (idx >= MX * D) return;
    int r = idx / D, c = idx % D;
    int b = r / (1 + Np), p = r % (1 + Np);
    float v;
    if (p == 0) {
        v = x[idx] + cls[b * D + c];
    } else {
        int n = p - 1;
        int s = n >> 4, t = n & 15;
        v = xt2[(size_t)(b * Np + n) * D + c]
          + rs[(size_t)((b * Tt + t) * SSP + 1 + s) * D + c];
    }
    out[idx] = v;
}

// ---------------- launch ----------------
extern "C" void kernel_launch(void* const* d_in, const int* in_sizes, int n_in,
                              void* d_out, int out_size) {
    const float* x        = (const float*)d_in[0];
    const float* tn1_w    = (const float*)d_in[1];
    const float* tn1_b    = (const float*)d_in[2];
    const float* t_qkv_w  = (const float*)d_in[3];
    const float* t_proj_w = (const float*)d_in[4];
    const float* t_proj_b = (const float*)d_in[5];
    const float* tfc_w    = (const float*)d_in[6];
    const float* tfc_b    = (const float*)d_in[7];
    const float* n1_w     = (const float*)d_in[8];
    const float* n1_b     = (const float*)d_in[9];
    const float* s_qkv_w  = (const float*)d_in[10];
    const float* s_proj_w = (const float*)d_in[11];
    const float* s_proj_b = (const float*)d_in[12];
    const float* n2_w     = (const float*)d_in[13];
    const float* n2_b     = (const float*)d_in[14];
    const float* fc1_w    = (const float*)d_in[15];
    const float* fc1_b    = (const float*)d_in[16];
    const float* fc2_w    = (const float*)d_in[17];
    const float* fc2_b    = (const float*)d_in[18];
    float* out = (float*)d_out;

    float  *p_xnc, *p_qkv, *p_rs, *p_xt2, *p_xnew, *p_cls;
    __half *p_lnh, *p_atth, *p_rth, *p_hidh, *p_wt;
    cudaGetSymbolAddress((void**)&p_xnc,  g_xnc);
    cudaGetSymbolAddress((void**)&p_lnh,  g_lnh);
    cudaGetSymbolAddress((void**)&p_qkv,  g_qkv);
    cudaGetSymbolAddress((void**)&p_atth, g_atth);
    cudaGetSymbolAddress((void**)&p_rth,  g_rth);
    cudaGetSymbolAddress((void**)&p_rs,   g_rs);
    cudaGetSymbolAddress((void**)&p_xt2,  g_xt2);
    cudaGetSymbolAddress((void**)&p_xnew, g_xnew);
    cudaGetSymbolAddress((void**)&p_hidh, g_hidh);
    cudaGetSymbolAddress((void**)&p_cls,  g_cls);
    cudaGetSymbolAddress((void**)&p_wt,   g_wt);

    cudaFuncSetAttribute(attn_s_kernel, cudaFuncAttributeMaxDynamicSharedMemorySize, SMEM_S);
    cudaFuncSetAttribute(gemm_hmma<0, float >, cudaFuncAttributeMaxDynamicSharedMemorySize, GEMM_SMEM);
    cudaFuncSetAttribute(gemm_hmma<1, __half>, cudaFuncAttributeMaxDynamicSharedMemorySize, GEMM_SMEM);
    cudaFuncSetAttribute(gemm_hmma<1, float >, cudaFuncAttributeMaxDynamicSharedMemorySize, GEMM_SMEM);
    cudaFuncSetAttribute(gemm_hmma<2, float >, cudaFuncAttributeMaxDynamicSharedMemorySize, GEMM_SMEM);
    cudaFuncSetAttribute(gemm_hmma<3, __half>, cudaFuncAttributeMaxDynamicSharedMemorySize, GEMM_SMEM);

    // 1) gather x[:,1:] contiguous
    gather_xnc<<<(MT * (D / 4) + 255) / 256, 256>>>(x, p_xnc);

    // 2) temporal LN -> half
    ln_rows_kernel<<<MT, 256>>>(p_xnc, tn1_w, tn1_b, p_lnh);

    // 3) temporal qkv (fp32 out, feeds attention)
    transpose_h<<<dim3(D / 32, 3 * D / 32), dim3(32, 8)>>>(t_qkv_w, p_wt, D, 3 * D);
    gemm_hmma<0, float><<<dim3(3 * D / 128, MT / 128), 256, GEMM_SMEM>>>(MT, 3 * D, D, p_lnh, p_wt, nullptr, nullptr, p_qkv);

    // 4) temporal attention -> half
    attn_t_kernel<<<dim3(Bn * Hh * Ww, NHh), 128>>>(p_qkv, p_atth);

    // 5) temporal proj -> half (feeds tfc GEMM)
    transpose_h<<<dim3(D / 32, D / 32), dim3(32, 8)>>>(t_proj_w, p_wt, D, D);
    gemm_hmma<1, __half><<<dim3(D / 128, MT / 128), 256, GEMM_SMEM>>>(MT, D, D, p_atth, p_wt, t_proj_b, nullptr, p_rth);

    // 6) tfc + residual(x[:,1:]) -> xt2 fp32
    transpose_h<<<dim3(D / 32, D / 32), dim3(32, 8)>>>(tfc_w, p_wt, D, D);
    gemm_hmma<2, float><<<dim3(D / 128, MT / 128), 256, GEMM_SMEM>>>(MT, D, D, p_rth, p_wt, tfc_b, p_xnc, p_xt2);

    // 7) spatial LN -> half
    ln_xs_kernel<<<MS, 256>>>(x, p_xt2, n1_w, n1_b, p_lnh);

    // 8) spatial qkv (fp32 out)
    transpose_h<<<dim3(D / 32, 3 * D / 32), dim3(32, 8)>>>(s_qkv_w, p_wt, D, 3 * D);
    gemm_hmma<0, float><<<dim3(3 * D / 128, MS / 128), 256, GEMM_SMEM>>>(MS, 3 * D, D, p_lnh, p_wt, nullptr, nullptr, p_qkv);

    // 9) spatial attention -> half
    attn_s_kernel<<<dim3(Bn * Tt, NHh), 256, SMEM_S>>>(p_qkv, p_atth);

    // 10) spatial proj -> rs fp32
    transpose_h<<<dim3(D / 32, D / 32), dim3(32, 8)>>>(s_proj_w, p_wt, D, D);
    gemm_hmma<1, float><<<dim3(D / 128, MS / 128), 256, GEMM_SMEM>>>(MS, D, D, p_atth, p_wt, s_proj_b, nullptr, p_rs);

    // 11) cls mean over time
    cls_mean_kernel<<<Bn, D>>>(p_rs, p_cls);

    // 12) x_new assembly
    build_xnew_kernel<<<(MX * D + 255) / 256, 256>>>(x, p_xt2, p_rs, p_cls, p_xnew);

    // 13) final LN -> half (rows beyond MX in p_lnh hold stale-but-finite spatial data)
    ln_rows_kernel<<<MX, 256>>>(p_xnew, n2_w, n2_b, p_lnh);

    // 14) fc1 + gelu -> half hid (compute padded rows so fc2's A is defined)
    transpose_h<<<dim3(D / 32, HID / 32), dim3(32, 8)>>>(fc1_w, p_wt, D, HID);
    gemm_hmma<3, __half><<<dim3(HID / 128, MXP / 128), 256, GEMM_SMEM>>>(MXP, HID, D, p_lnh, p_wt, fc1_b, nullptr, p_hidh);

    // 15) fc2 + residual -> out (stores guarded at MX)
    transpose_h<<<dim3(HID / 32, D / 32), dim3(32, 8)>>>(fc2_w, p_wt, HID, D);
    gemm_hmma<2, float><<<dim3(D / 128, MXP / 128), 256, GEMM_SMEM>>>(MX, D, HID, p_hidh, p_wt, fc2_b, p_xnew, out);
}

// round 4
// speedup vs baseline: 4.5180x; 1.1567x over previous
#include <cuda_runtime.h>
#include <cuda_fp16.h>
#include <math.h>
#include <stdint.h>

// ---------------- problem constants ----------------
constexpr int Bn  = 8;
constexpr int Tt  = 16;
constexpr int Hh  = 14;
constexpr int Ww  = 14;
constexpr int D   = 768;
constexpr int NHh = 12;
constexpr int HID = 3072;
constexpr int Np  = Hh * Ww * Tt;      // 3136
constexpr int MT  = Bn * Np;           // 25088 (=196*128)
constexpr int SSP = 1 + Hh * Ww;       // 197
constexpr int MS  = Bn * Tt * SSP;     // 25216 (=197*128)
constexpr int MX  = Bn * (1 + Np);     // 25096
constexpr int MXP = 25216;             // MX padded to 128

// ---------------- scratch ----------------
__device__ float  g_xnc [MT * D];
__device__ __half g_lnh [MS * D];
__device__ __half g_qkvh[MS * 3 * D];
__device__ __half g_atth[MS * D];
__device__ __half g_rth [MT * D];
__device__ float  g_rs  [MS * D];
__device__ float  g_xt2 [MT * D];
__device__ float  g_xnew[MX * D];
__device__ __half g_hidh[MXP * HID];
__device__ float  g_cls [Bn * D];
__device__ __half g_wt  [HID * D];     // transposed half weights (max 3072*768)

// ---------------- PTX helpers ----------------
__device__ __forceinline__ uint32_t smem_u32(const void* p) {
    uint32_t a;
    asm("{ .reg .u64 t; cvta.to.shared.u64 t, %1; cvt.u32.u64 %0, t; }" : "=r"(a) : "l"(p));
    return a;
}
__device__ __forceinline__ float gelu_exact(float v) {
    return 0.5f * v * (1.0f + erff(v * 0.70710678118654752440f));
}

#define CP_ASYNC16(dst, src) \
    asm volatile("cp.async.cg.shared.global [%0], [%1], 16;" :: "r"(dst), "l"(src) : "memory")
#define CP_COMMIT() asm volatile("cp.async.commit_group;" ::: "memory")
#define CP_WAIT0()  asm volatile("cp.async.wait_group 0;" ::: "memory")
#define CP_WAIT1()  asm volatile("cp.async.wait_group 1;" ::: "memory")

#define LDSM4(r, addr) \
    asm volatile("ldmatrix.sync.aligned.m8n8.x4.shared.b16 {%0,%1,%2,%3}, [%4];" \
        : "=r"((r)[0]), "=r"((r)[1]), "=r"((r)[2]), "=r"((r)[3]) : "r"(addr))

#define MMA16816(c, a, b0, b1) \
    asm volatile("mma.sync.aligned.m16n8k16.row.col.f32.f16.f16.f32 " \
        "{%0,%1,%2,%3}, {%4,%5,%6,%7}, {%8,%9}, {%0,%1,%2,%3};" \
        : "+f"((c)[0]), "+f"((c)[1]), "+f"((c)[2]), "+f"((c)[3]) \
        : "r"((a)[0]), "r"((a)[1]), "r"((a)[2]), "r"((a)[3]), "r"(b0), "r"(b1))

// ---------------- weight transpose + fp16 round: Wt[N,K] = h(W[K,N]) ----------------
__global__ void transpose_h(const float* __restrict__ W, __half* __restrict__ Wt, int K, int N) {
    __shared__ float tile[32][33];
    int k0 = blockIdx.x * 32, n0 = blockIdx.y * 32;
    int tx = threadIdx.x, ty = threadIdx.y;  // 32 x 8
    for (int r = ty; r < 32; r += 8) tile[r][tx] = W[(size_t)(k0 + r) * N + n0 + tx];
    __syncthreads();
    for (int r = ty; r < 32; r += 8) Wt[(size_t)(n0 + r) * K + k0 + tx] = __float2half_rn(tile[tx][r]);
}

// ---------------- fp16 tensor-core GEMM: C[M,N] = A[M,K] * Bt[N,K]^T + epilogue ----------------
// K-chunk = 64 halves (128B rows, XOR swizzle), 3-stage cp.async pipeline.
// EPI: 0=none 1=+bias 2=+bias+residual 3=+bias+gelu ; TO: float or __half output
constexpr int TILE_B    = 128 * 128;        // 16384 bytes per operand tile
constexpr int STAGE_B   = 2 * TILE_B;       // 32768
constexpr int GS        = 3;
constexpr int GEMM_SMEM = GS * STAGE_B;     // 98304

template <int EPI, typename TO>
__global__ void __launch_bounds__(256, 2) gemm_hmma(
    int Mreal, int N, int K,
    const __half* __restrict__ A, const __half* __restrict__ Bt,
    const float* __restrict__ bias, const float* __restrict__ Res,
    TO* __restrict__ C)
{
    extern __shared__ char smbuf[];
    const uint32_t sb = smem_u32(smbuf);
    const int tid  = threadIdx.x;
    const int wid  = tid >> 5, lane = tid & 31;
    const int wm   = wid & 3,  wn   = wid >> 2;     // warp grid 4(M) x 2(N)
    const int n0   = blockIdx.x * 128, m0 = blockIdx.y * 128;

    auto load_stage = [&](int chunk, int st) {
        uint32_t base = sb + st * STAGE_B;
        const __half* asrc = A  + (size_t)m0 * K + chunk * 64;
        const __half* bsrc = Bt + (size_t)n0 * K + chunk * 64;
        #pragma unroll
        for (int i = 0; i < 4; i++) {
            int idx = tid + i * 256;          // 0..1023
            int r = idx >> 3, c = idx & 7;
            uint32_t sw = (uint32_t)((c ^ (r & 7)) << 4);
            CP_ASYNC16(base + r * 128 + sw,          asrc + (size_t)r * K + c * 8);
            CP_ASYNC16(base + TILE_B + r * 128 + sw, bsrc + (size_t)r * K + c * 8);
        }
    };

    const int NC = K / 64;
    load_stage(0, 0); CP_COMMIT();
    load_stage(1, 1); CP_COMMIT();

    float acc[2][8][4];
    #pragma unroll
    for (int i = 0; i < 2; i++)
        #pragma unroll
        for (int j = 0; j < 8; j++)
            #pragma unroll
            for (int q = 0; q < 4; q++) acc[i][j][q] = 0.f;

    // per-lane ldmatrix row parameters
    const int arow = wm * 32 + (lane & 15);
    const int brow = wn * 64 + (lane & 15);
    const uint32_t aterm = arow * 128, axr = arow & 7;
    const uint32_t bterm = brow * 128, bxr = brow & 7;
    const uint32_t csel  = (lane >> 4) & 1;

    for (int i = 0; i < NC; i++) {
        if (i == NC - 1) CP_WAIT0(); else CP_WAIT1();
        __syncthreads();
        if (i + 2 < NC) { load_stage(i + 2, (i + 2) % GS); CP_COMMIT(); }

        uint32_t As = sb + (i % GS) * STAGE_B;
        uint32_t Bs = As + TILE_B;

        #pragma unroll
        for (int ks = 0; ks < 4; ks++) {
            uint32_t c   = ks * 2 + csel;
            uint32_t asw = ((c ^ axr) << 4);
            uint32_t bsw = ((c ^ bxr) << 4);
            uint32_t a0[4], a1[4];
            LDSM4(a0, As + aterm + asw);
            LDSM4(a1, As + aterm + 16 * 128 + asw);
            uint32_t bf[4][4];
            #pragma unroll
            for (int p = 0; p < 4; p++)
                LDSM4(bf[p], Bs + bterm + p * 16 * 128 + bsw);
            #pragma unroll
            for (int nt = 0; nt < 8; nt++) {
                uint32_t b0 = bf[nt >> 1][nt & 1];
                uint32_t b1 = bf[nt >> 1][(nt & 1) + 2];
                MMA16816(acc[0][nt], a0, b0, b1);
                MMA16816(acc[1][nt], a1, b0, b1);
            }
        }
    }

    // -------- epilogue --------
    const int rbase = m0 + wm * 32 + (lane >> 2);
    const int cbase = n0 + wn * 64 + (lane & 3) * 2;
    #pragma unroll
    for (int mt = 0; mt < 2; mt++) {
        #pragma unroll
        for (int half_r = 0; half_r < 2; half_r++) {
            int row = rbase + mt * 16 + half_r * 8;
            if (row >= Mreal) continue;
            #pragma unroll
            for (int nt = 0; nt < 8; nt++) {
                int col = cbase + nt * 8;
                float v0 = acc[mt][nt][half_r * 2 + 0];
                float v1 = acc[mt][nt][half_r * 2 + 1];
                if (EPI >= 1) { v0 += __ldg(&bias[col]); v1 += __ldg(&bias[col + 1]); }
                if (EPI == 2) {
                    const float2 rv = *(const float2*)(Res + (size_t)row * N + col);
                    v0 += rv.x; v1 += rv.y;
                }
                if (EPI == 3) { v0 = gelu_exact(v0); v1 = gelu_exact(v1); }
                if (sizeof(TO) == 2) {
                    *(__half2*)((__half*)C + (size_t)row * N + col) = __floats2half2_rn(v0, v1);
                } else {
                    *(float2*)((float*)C + (size_t)row * N + col) = make_float2(v0, v1);
                }
            }
        }
    }
}

// ---------------- LayerNorm (fp32 in, half out) ----------------
__device__ __forceinline__ void ln_row(const float* __restrict__ src,
                                       const float* __restrict__ w,
                                       const float* __restrict__ bvec,
                                       __half* __restrict__ dst) {
    int tid = threadIdx.x;
    float v0 = src[tid], v1 = src[tid + 256], v2 = src[tid + 512];
    float s  = v0 + v1 + v2;
    float ss = v0 * v0 + v1 * v1 + v2 * v2;
    __shared__ float red[18];
#pragma unroll
    for (int o = 16; o; o >>= 1) {
        s  += __shfl_down_sync(0xffffffffu, s,  o);
        ss += __shfl_down_sync(0xffffffffu, ss, o);
    }
    if ((tid & 31) == 0) { red[tid >> 5] = s; red[8 + (tid >> 5)] = ss; }
    __syncthreads();
    if (tid == 0) {
        float a = 0.f, b2 = 0.f;
#pragma unroll
        for (int i = 0; i < 8; i++) { a += red[i]; b2 += red[8 + i]; }
        red[16] = a * (1.0f / 768.0f);
        red[17] = b2 * (1.0f / 768.0f);
    }
    __syncthreads();
    float mean = red[16];
    float var  = red[17] - mean * mean;
    float rstd = rsqrtf(var + 1e-5f);
    dst[tid]       = __float2half_rn((v0 - mean) * rstd * w[tid]       + bvec[tid]);
    dst[tid + 256] = __float2half_rn((v1 - mean) * rstd * w[tid + 256] + bvec[tid + 256]);
    dst[tid + 512] = __float2half_rn((v2 - mean) * rstd * w[tid + 512] + bvec[tid + 512]);
}

__global__ void ln_rows_kernel(const float* __restrict__ src,
                               const float* __restrict__ w,
                               const float* __restrict__ bvec,
                               __half* __restrict__ dst) {
    int r = blockIdx.x;
    ln_row(src + (size_t)r * D, w, bvec, dst + (size_t)r * D);
}

__global__ void ln_xs_kernel(const float* __restrict__ x,
                             const float* __restrict__ xt2,
                             const float* __restrict__ w,
                             const float* __restrict__ bvec,
                             __half* __restrict__ dst) {
    int r  = blockIdx.x;
    int bt = r / SSP, j = r % SSP;
    int b  = bt >> 4, t = bt & 15;
    const float* src = (j == 0)
        ? (x + (size_t)b * (1 + Np) * D)
        : (xt2 + ((size_t)(b * Np + (j - 1) * Tt + t)) * D);
    ln_row(src, w, bvec, dst + (size_t)r * D);
}

__global__ void gather_xnc(const float* __restrict__ x, float* __restrict__ out) {
    int q = blockIdx.x * blockDim.x + threadIdx.x;
    if (q >= MT * (D / 4)) return;
    int r = q / (D / 4), c = q % (D / 4);
    int b = r / Np, n = r % Np;
    const float4* src = (const float4*)(x + ((size_t)(b * (1 + Np) + 1 + n)) * D) + c;
    ((float4*)(out + (size_t)r * D))[c] = *src;
}

// ---------------- temporal attention (half qkv in, half out, fp32 math) ----------------
__global__ void attn_t_kernel(const __half* __restrict__ qkv, __half* __restrict__ out) {
    int R = blockIdx.x;
    int h = blockIdx.y;
    __shared__ float Qs[16 * 64], Ks[16 * 65], Vs[16 * 64], Ps[16 * 17];
    int tid = threadIdx.x;  // 128
    for (int idx = tid; idx < 512; idx += 128) {
        int t = idx >> 5, d2 = idx & 31;
        const __half2* p = (const __half2*)(qkv + (size_t)(R * 16 + t) * (3 * D) + h * 64) + d2;
        float2 q2 = __half22float2(p[0]);
        float2 k2 = __half22float2(p[D / 2]);
        float2 v2 = __half22float2(p[D]);
        Qs[t * 64 + d2 * 2] = q2.x; Qs[t * 64 + d2 * 2 + 1] = q2.y;
        Ks[t * 65 + d2 * 2] = k2.x; Ks[t * 65 + d2 * 2 + 1] = k2.y;
        Vs[t * 64 + d2 * 2] = v2.x; Vs[t * 64 + d2 * 2 + 1] = v2.y;
    }
    __syncthreads();
    for (int idx = tid; idx < 256; idx += 128) {
        int i = idx >> 4, j = idx & 15;
        float s = 0.f;
#pragma unroll
        for (int d = 0; d < 64; d++) s += Qs[i * 64 + d] * Ks[j * 65 + d];
        Ps[i * 17 + j] = s * 0.125f;
    }
    __syncthreads();
    if (tid < 16) {
        float m = -1e30f;
#pragma unroll
        for (int j = 0; j < 16; j++) m = fmaxf(m, Ps[tid * 17 + j]);
        float sum = 0.f, e[16];
#pragma unroll
        for (int j = 0; j < 16; j++) { e[j] = __expf(Ps[tid * 17 + j] - m); sum += e[j]; }
        float inv = 1.0f / sum;
#pragma unroll
        for (int j = 0; j < 16; j++) Ps[tid * 17 + j] = e[j] * inv;
    }
    __syncthreads();
    for (int idx = tid; idx < 1024; idx += 128) {
        int i = idx >> 6, d = idx & 63;
        float a = 0.f;
#pragma unroll
        for (int j = 0; j < 16; j++) a += Ps[i * 17 + j] * Vs[j * 64 + d];
        out[(size_t)(R * 16 + i) * D + h * 64 + d] = __float2half_rn(a);
    }
}

// ---------------- spatial attention (half qkv in, half out, fp32 math) ----------------
constexpr int SKV    = SSP * 65;
constexpr int SMEM_S = (2 * SKV + 8 * 64) * 4;

__global__ void attn_s_kernel(const __half* __restrict__ qkv, __half* __restrict__ out) {
    int bt = blockIdx.x;
    int h  = blockIdx.y;
    extern __shared__ float sm[];
    float* Ks = sm;
    float* Vs = sm + SKV;
    float* Qs = Vs + SKV;
    int tid = threadIdx.x;  // 256

    for (int idx = tid; idx < SSP * 32; idx += 256) {
        int j = idx >> 5, d2 = idx & 31;
        const __half2* p = (const __half2*)(qkv + (size_t)(bt * SSP + j) * (3 * D) + h * 64) + d2;
        float2 k2 = __half22float2(p[D / 2]);
        float2 v2 = __half22float2(p[D]);
        Ks[j * 65 + d2 * 2] = k2.x; Ks[j * 65 + d2 * 2 + 1] = k2.y;
        Vs[j * 65 + d2 * 2] = v2.x; Vs[j * 65 + d2 * 2 + 1] = v2.y;
    }
    __syncthreads();

    int warp = tid >> 5, lane = tid & 31;
    for (int q = warp; q < SSP; q += 8) {
        const __half* qp = qkv + (size_t)(bt * SSP + q) * (3 * D) + h * 64;
        Qs[warp * 64 + lane]      = __half2float(qp[lane]);
        Qs[warp * 64 + lane + 32] = __half2float(qp[lane + 32]);
        __syncwarp();

        float sc[7];
        float m = -1e30f;
#pragma unroll
        for (int jj = 0; jj < 7; jj++) {
            int j = jj * 32 + lane;
            float s = -1e30f;
            if (j < SSP) {
                s = 0.f;
#pragma unroll
                for (int d = 0; d < 64; d++) s += Qs[warp * 64 + d] * Ks[j * 65 + d];
                s *= 0.125f;
            }
            sc[jj] = s;
            m = fmaxf(m, s);
        }
#pragma unroll
        for (int o = 16; o; o >>= 1) m = fmaxf(m, __shfl_xor_sync(0xffffffffu, m, o));
        float sum = 0.f;
#pragma unroll
        for (int jj = 0; jj < 7; jj++) {
            int j = jj * 32 + lane;
            float e = (j < SSP) ? __expf(sc[jj] - m) : 0.0f;
            sc[jj] = e;
            sum += e;
        }
#pragma unroll
        for (int o = 16; o; o >>= 1) sum += __shfl_xor_sync(0xffffffffu, sum, o);
        float inv = 1.0f / sum;

        float a0 = 0.f, a1 = 0.f;
#pragma unroll
        for (int jj = 0; jj < 7; jj++) {
            int jbase = jj * 32;
            int lim = min(32, SSP - jbase);
            for (int l = 0; l < lim; l++) {
                float p = __shfl_sync(0xffffffffu, sc[jj], l);
                int j = jbase + l;
                a0 += p * Vs[j * 65 + lane];
                a1 += p * Vs[j * 65 + lane + 32];
            }
        }
        __half* op = out + (size_t)(bt * SSP + q) * D + h * 64;
        op[lane]      = __float2half_rn(a0 * inv);
        op[lane + 32] = __float2half_rn(a1 * inv);
        __syncwarp();
    }
}

__global__ void cls_mean_kernel(const float* __restrict__ rs, float* __restrict__ cls) {
    int b = blockIdx.x;
    int c = threadIdx.x;
    float s = 0.f;
#pragma unroll
    for (int t = 0; t < Tt; t++) s += rs[(size_t)((b * Tt + t) * SSP) * D + c];
    cls[b * D + c] = s * (1.0f / 16.0f);
}

__global__ void build_xnew_kernel(const float* __restrict__ x,
                                  const float* __restrict__ xt2,
                                  const float* __restrict__ rs,
                                  const float* __restrict__ cls,
                                  float* __restrict__ out) {
    int idx = blockIdx.x * blockDim.x + threadIdx.x;
    if (idx >= MX * D) return;
    int r = idx / D, c = idx % D;
    int b = r / (1 + Np), p = r % (1 + Np);
    float v;
    if (p == 0) {
        v = x[idx] + cls[b * D + c];
    } else {
        int n = p - 1;
        int s = n >> 4, t = n & 15;
        v = xt2[(size_t)(b * Np + n) * D + c]
          + rs[(size_t)((b * Tt + t) * SSP + 1 + s) * D + c];
    }
    out[idx] = v;
}

// ---------------- launch ----------------
extern "C" void kernel_launch(void* const* d_in, const int* in_sizes, int n_in,
                              void* d_out, int out_size) {
    const float* x        = (const float*)d_in[0];
    const float* tn1_w    = (const float*)d_in[1];
    const float* tn1_b    = (const float*)d_in[2];
    const float* t_qkv_w  = (const float*)d_in[3];
    const float* t_proj_w = (const float*)d_in[4];
    const float* t_proj_b = (const float*)d_in[5];
    const float* tfc_w    = (const float*)d_in[6];
    const float* tfc_b    = (const float*)d_in[7];
    const float* n1_w     = (const float*)d_in[8];
    const float* n1_b     = (const float*)d_in[9];
    const float* s_qkv_w  = (const float*)d_in[10];
    const float* s_proj_w = (const float*)d_in[11];
    const float* s_proj_b = (const float*)d_in[12];
    const float* n2_w     = (const float*)d_in[13];
    const float* n2_b     = (const float*)d_in[14];
    const float* fc1_w    = (const float*)d_in[15];
    const float* fc1_b    = (const float*)d_in[16];
    const float* fc2_w    = (const float*)d_in[17];
    const float* fc2_b    = (const float*)d_in[18];
    float* out = (float*)d_out;

    float  *p_xnc, *p_rs, *p_xt2, *p_xnew, *p_cls;
    __half *p_lnh, *p_qkvh, *p_atth, *p_rth, *p_hidh, *p_wt;
    cudaGetSymbolAddress((void**)&p_xnc,  g_xnc);
    cudaGetSymbolAddress((void**)&p_lnh,  g_lnh);
    cudaGetSymbolAddress((void**)&p_qkvh, g_qkvh);
    cudaGetSymbolAddress((void**)&p_atth, g_atth);
    cudaGetSymbolAddress((void**)&p_rth,  g_rth);
    cudaGetSymbolAddress((void**)&p_rs,   g_rs);
    cudaGetSymbolAddress((void**)&p_xt2,  g_xt2);
    cudaGetSymbolAddress((void**)&p_xnew, g_xnew);
    cudaGetSymbolAddress((void**)&p_hidh, g_hidh);
    cudaGetSymbolAddress((void**)&p_cls,  g_cls);
    cudaGetSymbolAddress((void**)&p_wt,   g_wt);

    cudaFuncSetAttribute(attn_s_kernel, cudaFuncAttributeMaxDynamicSharedMemorySize, SMEM_S);
    cudaFuncSetAttribute(gemm_hmma<0, __half>, cudaFuncAttributeMaxDynamicSharedMemorySize, GEMM_SMEM);
    cudaFuncSetAttribute(gemm_hmma<1, __half>, cudaFuncAttributeMaxDynamicSharedMemorySize, GEMM_SMEM);
    cudaFuncSetAttribute(gemm_hmma<1, float >, cudaFuncAttributeMaxDynamicSharedMemorySize, GEMM_SMEM);
    cudaFuncSetAttribute(gemm_hmma<2, float >, cudaFuncAttributeMaxDynamicSharedMemorySize, GEMM_SMEM);
    cudaFuncSetAttribute(gemm_hmma<3, __half>, cudaFuncAttributeMaxDynamicSharedMemorySize, GEMM_SMEM);

    // 1) gather x[:,1:] contiguous
    gather_xnc<<<(MT * (D / 4) + 255) / 256, 256>>>(x, p_xnc);

    // 2) temporal LN -> half
    ln_rows_kernel<<<MT, 256>>>(p_xnc, tn1_w, tn1_b, p_lnh);

    // 3) temporal qkv -> half
    transpose_h<<<dim3(D / 32, 3 * D / 32), dim3(32, 8)>>>(t_qkv_w, p_wt, D, 3 * D);
    gemm_hmma<0, __half><<<dim3(3 * D / 128, MT / 128), 256, GEMM_SMEM>>>(MT, 3 * D, D, p_lnh, p_wt, nullptr, nullptr, p_qkvh);

    // 4) temporal attention -> half
    attn_t_kernel<<<dim3(Bn * Hh * Ww, NHh), 128>>>(p_qkvh, p_atth);

    // 5) temporal proj -> half (feeds tfc GEMM)
    transpose_h<<<dim3(D / 32, D / 32), dim3(32, 8)>>>(t_proj_w, p_wt, D, D);
    gemm_hmma<1, __half><<<dim3(D / 128, MT / 128), 256, GEMM_SMEM>>>(MT, D, D, p_atth, p_wt, t_proj_b, nullptr, p_rth);

    // 6) tfc + residual(x[:,1:]) -> xt2 fp32
    transpose_h<<<dim3(D / 32, D / 32), dim3(32, 8)>>>(tfc_w, p_wt, D, D);
    gemm_hmma<2, float><<<dim3(D / 128, MT / 128), 256, GEMM_SMEM>>>(MT, D, D, p_rth, p_wt, tfc_b, p_xnc, p_xt2);

    // 7) spatial LN -> half
    ln_xs_kernel<<<MS, 256>>>(x, p_xt2, n1_w, n1_b, p_lnh);

    // 8) spatial qkv -> half
    transpose_h<<<dim3(D / 32, 3 * D / 32), dim3(32, 8)>>>(s_qkv_w, p_wt, D, 3 * D);
    gemm_hmma<0, __half><<<dim3(3 * D / 128, MS / 128), 256, GEMM_SMEM>>>(MS, 3 * D, D, p_lnh, p_wt, nullptr, nullptr, p_qkvh);

    // 9) spatial attention -> half
    attn_s_kernel<<<dim3(Bn * Tt, NHh), 256, SMEM_S>>>(p_qkvh, p_atth);

    // 10) spatial proj -> rs fp32
    transpose_h<<<dim3(D / 32, D / 32), dim3(32, 8)>>>(s_proj_w, p_wt, D, D);
    gemm_hmma<1, float><<<dim3(D / 128, MS / 128), 256, GEMM_SMEM>>>(MS, D, D, p_atth, p_wt, s_proj_b, nullptr, p_rs);

    // 11) cls mean over time
    cls_mean_kernel<<<Bn, D>>>(p_rs, p_cls);

    // 12) x_new assembly
    build_xnew_kernel<<<(MX * D + 255) / 256, 256>>>(x, p_xt2, p_rs, p_cls, p_xnew);

    // 13) final LN -> half (rows beyond MX hold stale-but-finite data)
    ln_rows_kernel<<<MX, 256>>>(p_xnew, n2_w, n2_b, p_lnh);

    // 14) fc1 + gelu -> half hid (padded rows computed so fc2's A is defined)
    transpose_h<<<dim3(D / 32, HID / 32), dim3(32, 8)>>>(fc1_w, p_wt, D, HID);
    gemm_hmma<3, __half><<<dim3(HID / 128, MXP / 128), 256, GEMM_SMEM>>>(MXP, HID, D, p_lnh, p_wt, fc1_b, nullptr, p_hidh);

    // 15) fc2 + residual -> out (stores guarded at MX)
    transpose_h<<<dim3(HID / 32, D / 32), dim3(32, 8)>>>(fc2_w, p_wt, HID, D);
    gemm_hmma<2, float><<<dim3(D / 128, MXP / 128), 256, GEMM_SMEM>>>(MX, D, HID, p_hidh, p_wt, fc2_b, p_xnew, out);
}

// round 5
// speedup vs baseline: 7.5656x; 1.6746x over previous
#include <cuda_runtime.h>
#include <cuda_fp16.h>
#include <math.h>
#include <stdint.h>

// ---------------- problem constants ----------------
constexpr int Bn  = 8;
constexpr int Tt  = 16;
constexpr int Hh  = 14;
constexpr int Ww  = 14;
constexpr int D   = 768;
constexpr int NHh = 12;
constexpr int HID = 3072;
constexpr int Np  = Hh * Ww * Tt;      // 3136
constexpr int MT  = Bn * Np;           // 25088
constexpr int SSP = 1 + Hh * Ww;       // 197
constexpr int MS  = Bn * Tt * SSP;     // 25216
constexpr int MX  = Bn * (1 + Np);     // 25096
constexpr int MXP = 25216;

// ---------------- scratch ----------------
__device__ float  g_xnc [MT * D];
__device__ __half g_lnh [MS * D];
__device__ __half g_qkvh[MS * 3 * D];
__device__ __half g_atth[MS * D];
__device__ __half g_rth [MT * D];
__device__ float  g_rs  [MS * D];
__device__ float  g_xt2 [MT * D];
__device__ float  g_xnew[MX * D];
__device__ __half g_hidh[MXP * HID];
__device__ float  g_cls [Bn * D];
// transposed-weight buffers (dedicated, filled once per launch up front)
__device__ __half g_w_tqkv [3 * D * D];
__device__ __half g_w_tproj[D * D];
__device__ __half g_w_tfc  [D * D];
__device__ __half g_w_sqkv [3 * D * D];
__device__ __half g_w_sproj[D * D];
__device__ __half g_w_fc1  [HID * D];
__device__ __half g_w_fc2  [D * HID];

// ---------------- PTX helpers ----------------
__device__ __forceinline__ uint32_t smem_u32(const void* p) {
    uint32_t a;
    asm("{ .reg .u64 t; cvta.to.shared.u64 t, %1; cvt.u32.u64 %0, t; }" : "=r"(a) : "l"(p));
    return a;
}
__device__ __forceinline__ float gelu_exact(float v) {
    return 0.5f * v * (1.0f + erff(v * 0.70710678118654752440f));
}
__device__ __forceinline__ uint32_t pack_h2(float a, float b) {
    __half2 h = __floats2half2_rn(a, b);
    return *reinterpret_cast<uint32_t*>(&h);
}

#define CP_ASYNC16(dst, src) \
    asm volatile("cp.async.cg.shared.global [%0], [%1], 16;" :: "r"(dst), "l"(src) : "memory")
#define CP_COMMIT() asm volatile("cp.async.commit_group;" ::: "memory")
#define CP_WAIT0()  asm volatile("cp.async.wait_group 0;" ::: "memory")
#define CP_WAIT1()  asm volatile("cp.async.wait_group 1;" ::: "memory")

#define LDSM4(r, addr) \
    asm volatile("ldmatrix.sync.aligned.m8n8.x4.shared.b16 {%0,%1,%2,%3}, [%4];" \
        : "=r"((r)[0]), "=r"((r)[1]), "=r"((r)[2]), "=r"((r)[3]) : "r"(addr))
#define LDSM4T(r, addr) \
    asm volatile("ldmatrix.sync.aligned.m8n8.x4.trans.shared.b16 {%0,%1,%2,%3}, [%4];" \
        : "=r"((r)[0]), "=r"((r)[1]), "=r"((r)[2]), "=r"((r)[3]) : "r"(addr))

#define MMA16816(c, a, b0, b1) \
    asm volatile("mma.sync.aligned.m16n8k16.row.col.f32.f16.f16.f32 " \
        "{%0,%1,%2,%3}, {%4,%5,%6,%7}, {%8,%9}, {%0,%1,%2,%3};" \
        : "+f"((c)[0]), "+f"((c)[1]), "+f"((c)[2]), "+f"((c)[3]) \
        : "r"((a)[0]), "r"((a)[1]), "r"((a)[2]), "r"((a)[3]), "r"(b0), "r"(b1))

// ---------------- combined weight transpose (all 7 weights, one launch) ----------------
struct TransJob { const float* W; __half* Wt; int K, N, tile0; };
struct TransJobs { TransJob j[7]; int total; };

__global__ void transpose_all(TransJobs jobs) {
    __shared__ float tile[32][33];
    int t = blockIdx.x;
    int ji = 0;
    #pragma unroll
    for (int i = 1; i < 7; i++) if (t >= jobs.j[i].tile0) ji = i;
    const TransJob& J = jobs.j[ji];
    int lt = t - J.tile0;
    int ktiles = J.K / 32;
    int k0 = (lt % ktiles) * 32, n0 = (lt / ktiles) * 32;
    int tx = threadIdx.x, ty = threadIdx.y;  // 32 x 8
    for (int r = ty; r < 32; r += 8) tile[r][tx] = J.W[(size_t)(k0 + r) * J.N + n0 + tx];
    __syncthreads();
    for (int r = ty; r < 32; r += 8) J.Wt[(size_t)(n0 + r) * J.K + k0 + tx] = __float2half_rn(tile[tx][r]);
}

// ---------------- fp16 tensor-core GEMM (unchanged from R4) ----------------
constexpr int TILE_B    = 128 * 128;
constexpr int STAGE_B   = 2 * TILE_B;
constexpr int GS        = 3;
constexpr int GEMM_SMEM = GS * STAGE_B;

template <int EPI, typename TO>
__global__ void __launch_bounds__(256, 2) gemm_hmma(
    int Mreal, int N, int K,
    const __half* __restrict__ A, const __half* __restrict__ Bt,
    const float* __restrict__ bias, const float* __restrict__ Res,
    TO* __restrict__ C)
{
    extern __shared__ char smbuf[];
    const uint32_t sb = smem_u32(smbuf);
    const int tid  = threadIdx.x;
    const int wid  = tid >> 5, lane = tid & 31;
    const int wm   = wid & 3,  wn   = wid >> 2;
    const int n0   = blockIdx.x * 128, m0 = blockIdx.y * 128;

    auto load_stage = [&](int chunk, int st) {
        uint32_t base = sb + st * STAGE_B;
        const __half* asrc = A  + (size_t)m0 * K + chunk * 64;
        const __half* bsrc = Bt + (size_t)n0 * K + chunk * 64;
        #pragma unroll
        for (int i = 0; i < 4; i++) {
            int idx = tid + i * 256;
            int r = idx >> 3, c = idx & 7;
            uint32_t sw = (uint32_t)((c ^ (r & 7)) << 4);
            CP_ASYNC16(base + r * 128 + sw,          asrc + (size_t)r * K + c * 8);
            CP_ASYNC16(base + TILE_B + r * 128 + sw, bsrc + (size_t)r * K + c * 8);
        }
    };

    const int NC = K / 64;
    load_stage(0, 0); CP_COMMIT();
    load_stage(1, 1); CP_COMMIT();

    float acc[2][8][4];
    #pragma unroll
    for (int i = 0; i < 2; i++)
        #pragma unroll
        for (int j = 0; j < 8; j++)
            #pragma unroll
            for (int q = 0; q < 4; q++) acc[i][j][q] = 0.f;

    const int arow = wm * 32 + (lane & 15);
    const int brow = wn * 64 + (lane & 15);
    const uint32_t aterm = arow * 128, axr = arow & 7;
    const uint32_t bterm = brow * 128, bxr = brow & 7;
    const uint32_t csel  = (lane >> 4) & 1;

    for (int i = 0; i < NC; i++) {
        if (i == NC - 1) CP_WAIT0(); else CP_WAIT1();
        __syncthreads();
        if (i + 2 < NC) { load_stage(i + 2, (i + 2) % GS); CP_COMMIT(); }

        uint32_t As = sb + (i % GS) * STAGE_B;
        uint32_t Bs = As + TILE_B;

        #pragma unroll
        for (int ks = 0; ks < 4; ks++) {
            uint32_t c   = ks * 2 + csel;
            uint32_t asw = ((c ^ axr) << 4);
            uint32_t bsw = ((c ^ bxr) << 4);
            uint32_t a0[4], a1[4];
            LDSM4(a0, As + aterm + asw);
            LDSM4(a1, As + aterm + 16 * 128 + asw);
            uint32_t bf[4][4];
            #pragma unroll
            for (int p = 0; p < 4; p++)
                LDSM4(bf[p], Bs + bterm + p * 16 * 128 + bsw);
            #pragma unroll
            for (int nt = 0; nt < 8; nt++) {
                uint32_t b0 = bf[nt >> 1][nt & 1];
                uint32_t b1 = bf[nt >> 1][(nt & 1) + 2];
                MMA16816(acc[0][nt], a0, b0, b1);
                MMA16816(acc[1][nt], a1, b0, b1);
            }
        }
    }

    const int rbase = m0 + wm * 32 + (lane >> 2);
    const int cbase = n0 + wn * 64 + (lane & 3) * 2;
    #pragma unroll
    for (int mt = 0; mt < 2; mt++) {
        #pragma unroll
        for (int half_r = 0; half_r < 2; half_r++) {
            int row = rbase + mt * 16 + half_r * 8;
            if (row >= Mreal) continue;
            #pragma unroll
            for (int nt = 0; nt < 8; nt++) {
                int col = cbase + nt * 8;
                float v0 = acc[mt][nt][half_r * 2 + 0];
                float v1 = acc[mt][nt][half_r * 2 + 1];
                if (EPI >= 1) { v0 += __ldg(&bias[col]); v1 += __ldg(&bias[col + 1]); }
                if (EPI == 2) {
                    const float2 rv = *(const float2*)(Res + (size_t)row * N + col);
                    v0 += rv.x; v1 += rv.y;
                }
                if (EPI == 3) { v0 = gelu_exact(v0); v1 = gelu_exact(v1); }
                if (sizeof(TO) == 2) {
                    *(__half2*)((__half*)C + (size_t)row * N + col) = __floats2half2_rn(v0, v1);
                } else {
                    *(float2*)((float*)C + (size_t)row * N + col) = make_float2(v0, v1);
                }
            }
        }
    }
}

// ---------------- warp-per-row LayerNorm core ----------------
// 32 lanes handle one 768-row: 6 float4 per lane. Output half (uint2 pairs).
__device__ __forceinline__ void ln_warp(const float4 v[6],
                                        const float* __restrict__ w,
                                        const float* __restrict__ bvec,
                                        __half* __restrict__ dst, int lane) {
    float s = 0.f, ss = 0.f;
    #pragma unroll
    for (int i = 0; i < 6; i++) {
        s  += v[i].x + v[i].y + v[i].z + v[i].w;
        ss += v[i].x * v[i].x + v[i].y * v[i].y + v[i].z * v[i].z + v[i].w * v[i].w;
    }
    #pragma unroll
    for (int o = 16; o; o >>= 1) {
        s  += __shfl_xor_sync(0xffffffffu, s,  o);
        ss += __shfl_xor_sync(0xffffffffu, ss, o);
    }
    float mean = s * (1.0f / 768.0f);
    float var  = ss * (1.0f / 768.0f) - mean * mean;
    float rstd = rsqrtf(var + 1e-5f);
    #pragma unroll
    for (int i = 0; i < 6; i++) {
        int c4 = (lane + 32 * i) * 4;
        float4 wv = *(const float4*)(w + c4);
        float4 bv = *(const float4*)(bvec + c4);
        float o0 = (v[i].x - mean) * rstd * wv.x + bv.x;
        float o1 = (v[i].y - mean) * rstd * wv.y + bv.y;
        float o2 = (v[i].z - mean) * rstd * wv.z + bv.z;
        float o3 = (v[i].w - mean) * rstd * wv.w + bv.w;
        uint2 pk = make_uint2(pack_h2(o0, o1), pack_h2(o2, o3));
        *(uint2*)(dst + c4) = pk;
    }
}

// gather x[:,1:] -> xnc (fp32) + temporal LN -> lnh.  8 rows / 256-thr block.
__global__ void ln_gather_t(const float* __restrict__ x,
                            const float* __restrict__ w, const float* __restrict__ bvec,
                            float* __restrict__ xnc, __half* __restrict__ lnh) {
    int row = blockIdx.x * 8 + (threadIdx.x >> 5);
    int lane = threadIdx.x & 31;
    if (row >= MT) return;
    int b = row / Np, n = row % Np;
    const float4* src4 = (const float4*)(x + (size_t)(b * (1 + Np) + 1 + n) * D);
    float4 v[6];
    #pragma unroll
    for (int i = 0; i < 6; i++) v[i] = src4[lane + 32 * i];
    float4* dstx = (float4*)(xnc + (size_t)row * D);
    #pragma unroll
    for (int i = 0; i < 6; i++) dstx[lane + 32 * i] = v[i];
    ln_warp(v, w, bvec, lnh + (size_t)row * D, lane);
}

// spatial LN with scattered row sources
__global__ void ln_xs_kernel(const float* __restrict__ x,
                             const float* __restrict__ xt2,
                             const float* __restrict__ w, const float* __restrict__ bvec,
                             __half* __restrict__ lnh) {
    int row = blockIdx.x * 8 + (threadIdx.x >> 5);
    int lane = threadIdx.x & 31;
    if (row >= MS) return;
    int bt = row / SSP, j = row % SSP;
    int b = bt >> 4, t = bt & 15;
    const float* src = (j == 0)
        ? (x + (size_t)b * (1 + Np) * D)
        : (xt2 + (size_t)(b * Np + (j - 1) * Tt + t) * D);
    const float4* src4 = (const float4*)src;
    float4 v[6];
    #pragma unroll
    for (int i = 0; i < 6; i++) v[i] = src4[lane + 32 * i];
    ln_warp(v, w, bvec, lnh + (size_t)row * D, lane);
}

// build x_new + final LN (fused)
__global__ void ln_build(const float* __restrict__ x,
                         const float* __restrict__ xt2,
                         const float* __restrict__ rs,
                         const float* __restrict__ cls,
                         const float* __restrict__ w, const float* __restrict__ bvec,
                         float* __restrict__ xnew, __half* __restrict__ lnh) {
    int row = blockIdx.x * 8 + (threadIdx.x >> 5);
    int lane = threadIdx.x & 31;
    if (row >= MX) return;
    int b = row / (1 + Np), p = row % (1 + Np);
    float4 v[6];
    if (p == 0) {
        const float4* a4 = (const float4*)(x + (size_t)row * D);
        const float4* c4 = (const float4*)(cls + (size_t)b * D);
        #pragma unroll
        for (int i = 0; i < 6; i++) {
            float4 a = a4[lane + 32 * i], c = c4[lane + 32 * i];
            v[i] = make_float4(a.x + c.x, a.y + c.y, a.z + c.z, a.w + c.w);
        }
    } else {
        int n = p - 1, sI = n >> 4, t = n & 15;
        const float4* a4 = (const float4*)(xt2 + (size_t)(b * Np + n) * D);
        const float4* r4 = (const float4*)(rs + (size_t)((b * Tt + t) * SSP + 1 + sI) * D);
        #pragma unroll
        for (int i = 0; i < 6; i++) {
            float4 a = a4[lane + 32 * i], r = r4[lane + 32 * i];
            v[i] = make_float4(a.x + r.x, a.y + r.y, a.z + r.z, a.w + r.w);
        }
    }
    float4* dx = (float4*)(xnew + (size_t)row * D);
    #pragma unroll
    for (int i = 0; i < 6; i++) dx[lane + 32 * i] = v[i];
    ln_warp(v, w, bvec, lnh + (size_t)row * D, lane);
}

// ---------------- temporal attention (scalar, half in/out, fp32 math) ----------------
__global__ void attn_t_kernel(const __half* __restrict__ qkv, __half* __restrict__ out) {
    int R = blockIdx.x;
    int h = blockIdx.y;
    __shared__ float Qs[16 * 64], Ks[16 * 65], Vs[16 * 64], Ps[16 * 17];
    int tid = threadIdx.x;  // 128
    for (int idx = tid; idx < 512; idx += 128) {
        int t = idx >> 5, d2 = idx & 31;
        const __half2* p = (const __half2*)(qkv + (size_t)(R * 16 + t) * (3 * D) + h * 64) + d2;
        float2 q2 = __half22float2(p[0]);
        float2 k2 = __half22float2(p[D / 2]);
        float2 v2 = __half22float2(p[D]);
        Qs[t * 64 + d2 * 2] = q2.x; Qs[t * 64 + d2 * 2 + 1] = q2.y;
        Ks[t * 65 + d2 * 2] = k2.x; Ks[t * 65 + d2 * 2 + 1] = k2.y;
        Vs[t * 64 + d2 * 2] = v2.x; Vs[t * 64 + d2 * 2 + 1] = v2.y;
    }
    __syncthreads();
    for (int idx = tid; idx < 256; idx += 128) {
        int i = idx >> 4, j = idx & 15;
        float s = 0.f;
#pragma unroll
        for (int d = 0; d < 64; d++) s += Qs[i * 64 + d] * Ks[j * 65 + d];
        Ps[i * 17 + j] = s * 0.125f;
    }
    __syncthreads();
    if (tid < 16) {
        float m = -1e30f;
#pragma unroll
        for (int j = 0; j < 16; j++) m = fmaxf(m, Ps[tid * 17 + j]);
        float sum = 0.f, e[16];
#pragma unroll
        for (int j = 0; j < 16; j++) { e[j] = __expf(Ps[tid * 17 + j] - m); sum += e[j]; }
        float inv = 1.0f / sum;
#pragma unroll
        for (int j = 0; j < 16; j++) Ps[tid * 17 + j] = e[j] * inv;
    }
    __syncthreads();
    for (int idx = tid; idx < 1024; idx += 128) {
        int i = idx >> 6, d = idx & 63;
        float a = 0.f;
#pragma unroll
        for (int j = 0; j < 16; j++) a += Ps[i * 17 + j] * Vs[j * 64 + d];
        out[(size_t)(R * 16 + i) * D + h * 64 + d] = __float2half_rn(a);
    }
}

// ---------------- spatial attention: tensor-core FA2-style ----------------
// One block per (bt, h). 4 warps. K/V smem [208][64]h swizzled; q in 4 tiles of 64.
constexpr int Lp = 208;                        // 197 padded to 13*16
constexpr int ATTN_SMEM = Lp * 128 * 2 + 64 * 128;   // K + V + Qtile = 61440

__global__ void __launch_bounds__(128) attn_s_mma(const __half* __restrict__ qkv,
                                                  __half* __restrict__ out) {
    int bt = blockIdx.x, h = blockIdx.y;
    extern __shared__ char sm[];
    const uint32_t sK = smem_u32(sm);
    const uint32_t sV = sK + Lp * 128;
    const uint32_t sQ = sV + Lp * 128;
    const int tid = threadIdx.x, warp = tid >> 5, lane = tid & 31;

    const __half* base = qkv + (size_t)bt * SSP * (3 * D) + h * 64;

    // zero pad rows 197..207 of K and V
    for (int idx = tid; idx < 11 * 8; idx += 128) {
        int r = 197 + (idx >> 3), c = idx & 7;
        uint32_t sw = r * 128 + ((c ^ (r & 7)) << 4);
        *(uint4*)(sm + sw) = make_uint4(0, 0, 0, 0);
        *(uint4*)(sm + Lp * 128 + sw) = make_uint4(0, 0, 0, 0);
    }
    // async load K, V (197 rows x 8 chunks of 16B)
    for (int idx = tid; idx < 197 * 8; idx += 128) {
        int r = idx >> 3, c = idx & 7;
        uint32_t sw = r * 128 + ((c ^ (r & 7)) << 4);
        CP_ASYNC16(sK + sw, base + (size_t)r * (3 * D) + D + c * 8);
        CP_ASYNC16(sV + sw, base + (size_t)r * (3 * D) + 2 * D + c * 8);
    }
    CP_COMMIT();

    const uint32_t csel = (lane >> 4) & 1;
    const float scale = 0.125f;

    for (int qt = 0; qt < 4; qt++) {
        int q0 = qt * 64;
        __syncthreads();  // all warps done with previous Q tile
        // load Q tile (64 rows, clamped)
        for (int idx = tid; idx < 64 * 8; idx += 128) {
            int r = idx >> 3, c = idx & 7;
            int gr = min(q0 + r, 196);
            uint32_t sw = r * 128 + ((c ^ (r & 7)) << 4);
            CP_ASYNC16(sQ + sw, base + (size_t)gr * (3 * D) + c * 8);
        }
        CP_COMMIT(); CP_WAIT0();
        __syncthreads();

        // Q fragments: warp owns 16 rows
        uint32_t aq[4][4];
        {
            int arow = warp * 16 + (lane & 15);
            uint32_t aterm = arow * 128, axr = arow & 7;
            #pragma unroll
            for (int kc = 0; kc < 4; kc++) {
                uint32_t c = kc * 2 + csel;
                LDSM4(aq[kc], sQ + aterm + ((c ^ axr) << 4));
            }
        }

        // S = Q K^T  (26 n-tiles of 8 cols)
        float s[26][4];
        #pragma unroll
        for (int t = 0; t < 26; t++)
            #pragma unroll
            for (int q = 0; q < 4; q++) s[t][q] = 0.f;

        for (int nt2 = 0; nt2 < 13; nt2++) {
            int brow = nt2 * 16 + (lane & 15);
            uint32_t bterm = brow * 128, bxr = brow & 7;
            #pragma unroll
            for (int kc = 0; kc < 4; kc++) {
                uint32_t c = kc * 2 + csel;
                uint32_t bf[4];
                LDSM4(bf, sK + bterm + ((c ^ bxr) << 4));
                MMA16816(s[2 * nt2],     aq[kc], bf[0], bf[2]);
                MMA16816(s[2 * nt2 + 1], aq[kc], bf[1], bf[3]);
            }
        }

        // mask + scale + softmax (two rows per lane: r and r+8)
        float mx0 = -1e30f, mx1 = -1e30f;
        #pragma unroll
        for (int t = 0; t < 26; t++) {
            int col = t * 8 + (lane & 3) * 2;
            if (col     >= 197) { s[t][0] = -1e30f; s[t][2] = -1e30f; } else { s[t][0] *= scale; s[t][2] *= scale; }
            if (col + 1 >= 197) { s[t][1] = -1e30f; s[t][3] = -1e30f; } else { s[t][1] *= scale; s[t][3] *= scale; }
            mx0 = fmaxf(mx0, fmaxf(s[t][0], s[t][1]));
            mx1 = fmaxf(mx1, fmaxf(s[t][2], s[t][3]));
        }
        #pragma unroll
        for (int o = 1; o <= 2; o <<= 1) {
            mx0 = fmaxf(mx0, __shfl_xor_sync(0xffffffffu, mx0, o));
            mx1 = fmaxf(mx1, __shfl_xor_sync(0xffffffffu, mx1, o));
        }
        float sum0 = 0.f, sum1 = 0.f;
        #pragma unroll
        for (int t = 0; t < 26; t++) {
            s[t][0] = __expf(s[t][0] - mx0); sum0 += s[t][0];
            s[t][1] = __expf(s[t][1] - mx0); sum0 += s[t][1];
            s[t][2] = __expf(s[t][2] - mx1); sum1 += s[t][2];
            s[t][3] = __expf(s[t][3] - mx1); sum1 += s[t][3];
        }
        #pragma unroll
        for (int o = 1; o <= 2; o <<= 1) {
            sum0 += __shfl_xor_sync(0xffffffffu, sum0, o);
            sum1 += __shfl_xor_sync(0xffffffffu, sum1, o);
        }
        float inv0 = 1.0f / sum0, inv1 = 1.0f / sum1;

        // P fragments (fp16) — accumulator layout == A-operand layout
        uint32_t pa[13][4];
        #pragma unroll
        for (int k = 0; k < 13; k++) {
            pa[k][0] = pack_h2(s[2 * k][0],     s[2 * k][1]);
            pa[k][1] = pack_h2(s[2 * k][2],     s[2 * k][3]);
            pa[k][2] = pack_h2(s[2 * k + 1][0], s[2 * k + 1][1]);
            pa[k][3] = pack_h2(s[2 * k + 1][2], s[2 * k + 1][3]);
        }

        // O = P V   (8 n-tiles of 8 d-cols)
        float o[8][4];
        #pragma unroll
        for (int t = 0; t < 8; t++)
            #pragma unroll
            for (int q = 0; q < 4; q++) o[t][q] = 0.f;

        for (int kc = 0; kc < 13; kc++) {
            int vrow = kc * 16 + (lane & 15);
            uint32_t vterm = vrow * 128, vxr = vrow & 7;
            #pragma unroll
            for (int dt2 = 0; dt2 < 4; dt2++) {
                uint32_t c = dt2 * 2 + csel;          // 16B chunk (8 d-cols)
                uint32_t vf[4];
                LDSM4T(vf, sV + vterm + ((c ^ vxr) << 4));
                MMA16816(o[2 * dt2],     pa[kc], vf[0], vf[1]);
                MMA16816(o[2 * dt2 + 1], pa[kc], vf[2], vf[3]);
            }
        }

        // store (rows q0 + warp*16 + lane/4 and +8)
        int r0 = q0 + warp * 16 + (lane >> 2);
        #pragma unroll
        for (int dt = 0; dt < 8; dt++) {
            int col = h * 64 + dt * 8 + (lane & 3) * 2;
            if (r0 < 197)
                *(__half2*)(out + (size_t)(bt * SSP + r0) * D + col) =
                    __floats2half2_rn(o[dt][0] * inv0, o[dt][1] * inv0);
            if (r0 + 8 < 197)
                *(__half2*)(out + (size_t)(bt * SSP + r0 + 8) * D + col) =
                    __floats2half2_rn(o[dt][2] * inv1, o[dt][3] * inv1);
        }
    }
}

__global__ void cls_mean_kernel(const float* __restrict__ rs, float* __restrict__ cls) {
    int b = blockIdx.x;
    int c = threadIdx.x;
    float s = 0.f;
#pragma unroll
    for (int t = 0; t < Tt; t++) s += rs[(size_t)((b * Tt + t) * SSP) * D + c];
    cls[b * D + c] = s * (1.0f / 16.0f);
}

// ---------------- launch ----------------
extern "C" void kernel_launch(void* const* d_in, const int* in_sizes, int n_in,
                              void* d_out, int out_size) {
    const float* x        = (const float*)d_in[0];
    const float* tn1_w    = (const float*)d_in[1];
    const float* tn1_b    = (const float*)d_in[2];
    const float* t_qkv_w  = (const float*)d_in[3];
    const float* t_proj_w = (const float*)d_in[4];
    const float* t_proj_b = (const float*)d_in[5];
    const float* tfc_w    = (const float*)d_in[6];
    const float* tfc_b    = (const float*)d_in[7];
    const float* n1_w     = (const float*)d_in[8];
    const float* n1_b     = (const float*)d_in[9];
    const float* s_qkv_w  = (const float*)d_in[10];
    const float* s_proj_w = (const float*)d_in[11];
    const float* s_proj_b = (const float*)d_in[12];
    const float* n2_w     = (const float*)d_in[13];
    const float* n2_b     = (const float*)d_in[14];
    const float* fc1_w    = (const float*)d_in[15];
    const float* fc1_b    = (const float*)d_in[16];
    const float* fc2_w    = (const float*)d_in[17];
    const float* fc2_b    = (const float*)d_in[18];
    float* out = (float*)d_out;

    float  *p_xnc, *p_rs, *p_xt2, *p_xnew, *p_cls;
    __half *p_lnh, *p_qkvh, *p_atth, *p_rth, *p_hidh;
    __half *w_tqkv, *w_tproj, *w_tfc, *w_sqkv, *w_sproj, *w_fc1, *w_fc2;
    cudaGetSymbolAddress((void**)&p_xnc,  g_xnc);
    cudaGetSymbolAddress((void**)&p_lnh,  g_lnh);
    cudaGetSymbolAddress((void**)&p_qkvh, g_qkvh);
    cudaGetSymbolAddress((void**)&p_atth, g_atth);
    cudaGetSymbolAddress((void**)&p_rth,  g_rth);
    cudaGetSymbolAddress((void**)&p_rs,   g_rs);
    cudaGetSymbolAddress((void**)&p_xt2,  g_xt2);
    cudaGetSymbolAddress((void**)&p_xnew, g_xnew);
    cudaGetSymbolAddress((void**)&p_hidh, g_hidh);
    cudaGetSymbolAddress((void**)&p_cls,  g_cls);
    cudaGetSymbolAddress((void**)&w_tqkv, g_w_tqkv);
    cudaGetSymbolAddress((void**)&w_tproj,g_w_tproj);
    cudaGetSymbolAddress((void**)&w_tfc,  g_w_tfc);
    cudaGetSymbolAddress((void**)&w_sqkv, g_w_sqkv);
    cudaGetSymbolAddress((void**)&w_sproj,g_w_sproj);
    cudaGetSymbolAddress((void**)&w_fc1,  g_w_fc1);
    cudaGetSymbolAddress((void**)&w_fc2,  g_w_fc2);

    cudaFuncSetAttribute(attn_s_mma, cudaFuncAttributeMaxDynamicSharedMemorySize, ATTN_SMEM);
    cudaFuncSetAttribute(gemm_hmma<0, __half>, cudaFuncAttributeMaxDynamicSharedMemorySize, GEMM_SMEM);
    cudaFuncSetAttribute(gemm_hmma<1, __half>, cudaFuncAttributeMaxDynamicSharedMemorySize, GEMM_SMEM);
    cudaFuncSetAttribute(gemm_hmma<1, float >, cudaFuncAttributeMaxDynamicSharedMemorySize, GEMM_SMEM);
    cudaFuncSetAttribute(gemm_hmma<2, float >, cudaFuncAttributeMaxDynamicSharedMemorySize, GEMM_SMEM);
    cudaFuncSetAttribute(gemm_hmma<3, __half>, cudaFuncAttributeMaxDynamicSharedMemorySize, GEMM_SMEM);

    // 0) all weight transposes, one launch
    TransJobs jobs;
    auto mkjob = [](const float* W, __half* Wt, int K, int N, int tile0) {
        TransJob j; j.W = W; j.Wt = Wt; j.K = K; j.N = N; j.tile0 = tile0; return j;
    };
    int t0 = 0;
    jobs.j[0] = mkjob(t_qkv_w,  w_tqkv,  D,   3 * D, t0); t0 += (D / 32) * (3 * D / 32);
    jobs.j[1] = mkjob(t_proj_w, w_tproj, D,   D,     t0); t0 += (D / 32) * (D / 32);
    jobs.j[2] = mkjob(tfc_w,    w_tfc,   D,   D,     t0); t0 += (D / 32) * (D / 32);
    jobs.j[3] = mkjob(s_qkv_w,  w_sqkv,  D,   3 * D, t0); t0 += (D / 32) * (3 * D / 32);
    jobs.j[4] = mkjob(s_proj_w, w_sproj, D,   D,     t0); t0 += (D / 32) * (D / 32);
    jobs.j[5] = mkjob(fc1_w,    w_fc1,   D,   HID,   t0); t0 += (D / 32) * (HID / 32);
    jobs.j[6] = mkjob(fc2_w,    w_fc2,   HID, D,     t0); t0 += (HID / 32) * (D / 32);
    jobs.total = t0;
    transpose_all<<<t0, dim3(32, 8)>>>(jobs);

    // 1) gather + temporal LN (fused)
    ln_gather_t<<<(MT + 7) / 8, 256>>>(x, tn1_w, tn1_b, p_xnc, p_lnh);

    // 2) temporal qkv -> half
    gemm_hmma<0, __half><<<dim3(3 * D / 128, MT / 128), 256, GEMM_SMEM>>>(MT, 3 * D, D, p_lnh, w_tqkv, nullptr, nullptr, p_qkvh);

    // 3) temporal attention -> half
    attn_t_kernel<<<dim3(Bn * Hh * Ww, NHh), 128>>>(p_qkvh, p_atth);

    // 4) temporal proj -> half
    gemm_hmma<1, __half><<<dim3(D / 128, MT / 128), 256, GEMM_SMEM>>>(MT, D, D, p_atth, w_tproj, t_proj_b, nullptr, p_rth);

    // 5) tfc + residual(xnc) -> xt2 fp32
    gemm_hmma<2, float><<<dim3(D / 128, MT / 128), 256, GEMM_SMEM>>>(MT, D, D, p_rth, w_tfc, tfc_b, p_xnc, p_xt2);

    // 6) spatial LN -> half
    ln_xs_kernel<<<(MS + 7) / 8, 256>>>(x, p_xt2, n1_w, n1_b, p_lnh);

    // 7) spatial qkv -> half
    gemm_hmma<0, __half><<<dim3(3 * D / 128, MS / 128), 256, GEMM_SMEM>>>(MS, 3 * D, D, p_lnh, w_sqkv, nullptr, nullptr, p_qkvh);

    // 8) spatial attention (tensor cores) -> half
    attn_s_mma<<<dim3(Bn * Tt, NHh), 128, ATTN_SMEM>>>(p_qkvh, p_atth);

    // 9) spatial proj -> rs fp32
    gemm_hmma<1, float><<<dim3(D / 128, MS / 128), 256, GEMM_SMEM>>>(MS, D, D, p_atth, w_sproj, s_proj_b, nullptr, p_rs);

    // 10) cls mean over time
    cls_mean_kernel<<<Bn, D>>>(p_rs, p_cls);

    // 11) build x_new + final LN (fused)
    ln_build<<<(MX + 7) / 8, 256>>>(x, p_xt2, p_rs, p_cls, n2_w, n2_b, p_xnew, p_lnh);

    // 12) fc1 + gelu -> half hid (padded rows hold stale-but-finite data)
    gemm_hmma<3, __half><<<dim3(HID / 128, MXP / 128), 256, GEMM_SMEM>>>(MXP, HID, D, p_lnh, w_fc1, fc1_b, nullptr, p_hidh);

    // 13) fc2 + residual -> out (stores guarded at MX)
    gemm_hmma<2, float><<<dim3(D / 128, MXP / 128), 256, GEMM_SMEM>>>(MX, D, HID, p_hidh, w_fc2, fc2_b, p_xnew, out);
}

// round 6
// speedup vs baseline: 8.1363x; 1.0754x over previous
#include <cuda_runtime.h>
#include <cuda_fp16.h>
#include <math.h>
#include <stdint.h>

// ---------------- problem constants ----------------
constexpr int Bn  = 8;
constexpr int Tt  = 16;
constexpr int Hh  = 14;
constexpr int Ww  = 14;
constexpr int D   = 768;
constexpr int NHh = 12;
constexpr int HID = 3072;
constexpr int Np  = Hh * Ww * Tt;      // 3136
constexpr int MT  = Bn * Np;           // 25088
constexpr int SSP = 1 + Hh * Ww;       // 197
constexpr int MS  = Bn * Tt * SSP;     // 25216
constexpr int MX  = Bn * (1 + Np);     // 25096
constexpr int MXP = 25216;

// ---------------- scratch ----------------
__device__ float  g_xnc [MT * D];
__device__ __half g_lnh [MS * D];
__device__ __half g_qkvh[MS * 3 * D];
__device__ __half g_atth[MS * D];
__device__ float  g_rs  [MS * D];
__device__ float  g_xt2 [MT * D];
__device__ float  g_xnew[MX * D];
__device__ __half g_hidh[MXP * HID];
__device__ float  g_cls [Bn * D];
__device__ float  g_bcomb[D];
// transposed-weight buffers
__device__ __half g_w_tqkv [3 * D * D];
__device__ __half g_w_comb [D * D];       // composite (proj@tfc) transposed [n,k]
__device__ __half g_w_tfc  [D * D];       // tfc transposed
__device__ __half g_projw_h[D * D];       // proj_w untransposed half
__device__ __half g_w_sqkv [3 * D * D];
__device__ __half g_w_sproj[D * D];
__device__ __half g_w_fc1  [HID * D];
__device__ __half g_w_fc2  [D * HID];

// ---------------- PTX helpers ----------------
__device__ __forceinline__ uint32_t smem_u32(const void* p) {
    uint32_t a;
    asm("{ .reg .u64 t; cvta.to.shared.u64 t, %1; cvt.u32.u64 %0, t; }" : "=r"(a) : "l"(p));
    return a;
}
__device__ __forceinline__ float gelu_exact(float v) {
    return 0.5f * v * (1.0f + erff(v * 0.70710678118654752440f));
}
__device__ __forceinline__ uint32_t pack_h2(float a, float b) {
    __half2 h = __floats2half2_rn(a, b);
    return *reinterpret_cast<uint32_t*>(&h);
}

#define CP_ASYNC16(dst, src) \
    asm volatile("cp.async.cg.shared.global [%0], [%1], 16;" :: "r"(dst), "l"(src) : "memory")
#define CP_COMMIT() asm volatile("cp.async.commit_group;" ::: "memory")
#define CP_WAIT0()  asm volatile("cp.async.wait_group 0;" ::: "memory")
#define CP_WAIT1()  asm volatile("cp.async.wait_group 1;" ::: "memory")

#define LDSM4(r, addr) \
    asm volatile("ldmatrix.sync.aligned.m8n8.x4.shared.b16 {%0,%1,%2,%3}, [%4];" \
        : "=r"((r)[0]), "=r"((r)[1]), "=r"((r)[2]), "=r"((r)[3]) : "r"(addr))
#define LDSM4T(r, addr) \
    asm volatile("ldmatrix.sync.aligned.m8n8.x4.trans.shared.b16 {%0,%1,%2,%3}, [%4];" \
        : "=r"((r)[0]), "=r"((r)[1]), "=r"((r)[2]), "=r"((r)[3]) : "r"(addr))

#define MMA16816(c, a, b0, b1) \
    asm volatile("mma.sync.aligned.m16n8k16.row.col.f32.f16.f16.f32 " \
        "{%0,%1,%2,%3}, {%4,%5,%6,%7}, {%8,%9}, {%0,%1,%2,%3};" \
        : "+f"((c)[0]), "+f"((c)[1]), "+f"((c)[2]), "+f"((c)[3]) \
        : "r"((a)[0]), "r"((a)[1]), "r"((a)[2]), "r"((a)[3]), "r"(b0), "r"(b1))

// ---------------- combined weight transpose ----------------
struct TransJob { const float* W; __half* Wt; int K, N, tile0; };
struct TransJobs { TransJob j[6]; int total; };

__global__ void transpose_all(TransJobs jobs) {
    __shared__ float tile[32][33];
    int t = blockIdx.x;
    int ji = 0;
    #pragma unroll
    for (int i = 1; i < 6; i++) if (t >= jobs.j[i].tile0) ji = i;
    const TransJob& J = jobs.j[ji];
    int lt = t - J.tile0;
    int ktiles = J.K / 32;
    int k0 = (lt % ktiles) * 32, n0 = (lt / ktiles) * 32;
    int tx = threadIdx.x, ty = threadIdx.y;  // 32 x 8
    for (int r = ty; r < 32; r += 8) tile[r][tx] = J.W[(size_t)(k0 + r) * J.N + n0 + tx];
    __syncthreads();
    for (int r = ty; r < 32; r += 8) J.Wt[(size_t)(n0 + r) * J.K + k0 + tx] = __float2half_rn(tile[tx][r]);
}

// elementwise float -> half copy (no transpose)
__global__ void copyround_h(const float* __restrict__ W, __half* __restrict__ Wh, int n) {
    int i = blockIdx.x * blockDim.x + threadIdx.x;
    if (i < n) Wh[i] = __float2half_rn(W[i]);
}

// bcomb[n] = sum_j proj_b[j] * tfc_w[j,n] + tfc_b[n]
__global__ void bias_comb(const float* __restrict__ proj_b, const float* __restrict__ tfc_w,
                          const float* __restrict__ tfc_b, float* __restrict__ bcomb) {
    int n = blockIdx.x * blockDim.x + threadIdx.x;
    if (n >= D) return;
    float s = 0.f;
    for (int j = 0; j < D; j++) s += proj_b[j] * tfc_w[(size_t)j * D + n];
    bcomb[n] = s + tfc_b[n];
}

// ---------------- fp16 tensor-core GEMM (proven R4 mainloop) ----------------
constexpr int TILE_B    = 128 * 128;
constexpr int STAGE_B   = 2 * TILE_B;
constexpr int GS        = 3;
constexpr int GEMM_SMEM = GS * STAGE_B;

template <int EPI, typename TO>
__global__ void __launch_bounds__(256, 2) gemm_hmma(
    int Mreal, int N, int K,
    const __half* __restrict__ A, const __half* __restrict__ Bt,
    const float* __restrict__ bias, const float* __restrict__ Res,
    TO* __restrict__ C)
{
    extern __shared__ char smbuf[];
    const uint32_t sb = smem_u32(smbuf);
    const int tid  = threadIdx.x;
    const int wid  = tid >> 5, lane = tid & 31;
    const int wm   = wid & 3,  wn   = wid >> 2;
    const int n0   = blockIdx.x * 128, m0 = blockIdx.y * 128;

    auto load_stage = [&](int chunk, int st) {
        uint32_t base = sb + st * STAGE_B;
        const __half* asrc = A  + (size_t)m0 * K + chunk * 64;
        const __half* bsrc = Bt + (size_t)n0 * K + chunk * 64;
        #pragma unroll
        for (int i = 0; i < 4; i++) {
            int idx = tid + i * 256;
            int r = idx >> 3, c = idx & 7;
            uint32_t sw = (uint32_t)((c ^ (r & 7)) << 4);
            CP_ASYNC16(base + r * 128 + sw,          asrc + (size_t)r * K + c * 8);
            CP_ASYNC16(base + TILE_B + r * 128 + sw, bsrc + (size_t)r * K + c * 8);
        }
    };

    const int NC = K / 64;
    load_stage(0, 0); CP_COMMIT();
    load_stage(1, 1); CP_COMMIT();

    float acc[2][8][4];
    #pragma unroll
    for (int i = 0; i < 2; i++)
        #pragma unroll
        for (int j = 0; j < 8; j++)
            #pragma unroll
            for (int q = 0; q < 4; q++) acc[i][j][q] = 0.f;

    const int arow = wm * 32 + (lane & 15);
    const int brow = wn * 64 + (lane & 15);
    const uint32_t aterm = arow * 128, axr = arow & 7;
    const uint32_t bterm = brow * 128, bxr = brow & 7;
    const uint32_t csel  = (lane >> 4) & 1;

    for (int i = 0; i < NC; i++) {
        if (i == NC - 1) CP_WAIT0(); else CP_WAIT1();
        __syncthreads();
        if (i + 2 < NC) { load_stage(i + 2, (i + 2) % GS); CP_COMMIT(); }

        uint32_t As = sb + (i % GS) * STAGE_B;
        uint32_t Bs = As + TILE_B;

        #pragma unroll
        for (int ks = 0; ks < 4; ks++) {
            uint32_t c   = ks * 2 + csel;
            uint32_t asw = ((c ^ axr) << 4);
            uint32_t bsw = ((c ^ bxr) << 4);
            uint32_t a0[4], a1[4];
            LDSM4(a0, As + aterm + asw);
            LDSM4(a1, As + aterm + 16 * 128 + asw);
            uint32_t bf[4][4];
            #pragma unroll
            for (int p = 0; p < 4; p++)
                LDSM4(bf[p], Bs + bterm + p * 16 * 128 + bsw);
            #pragma unroll
            for (int nt = 0; nt < 8; nt++) {
                uint32_t b0 = bf[nt >> 1][nt & 1];
                uint32_t b1 = bf[nt >> 1][(nt & 1) + 2];
                MMA16816(acc[0][nt], a0, b0, b1);
                MMA16816(acc[1][nt], a1, b0, b1);
            }
        }
    }

    const int rbase = m0 + wm * 32 + (lane >> 2);
    const int cbase = n0 + wn * 64 + (lane & 3) * 2;
    #pragma unroll
    for (int mt = 0; mt < 2; mt++) {
        #pragma unroll
        for (int half_r = 0; half_r < 2; half_r++) {
            int row = rbase + mt * 16 + half_r * 8;
            if (row >= Mreal) continue;
            #pragma unroll
            for (int nt = 0; nt < 8; nt++) {
                int col = cbase + nt * 8;
                float v0 = acc[mt][nt][half_r * 2 + 0];
                float v1 = acc[mt][nt][half_r * 2 + 1];
                if (EPI >= 1) { v0 += __ldg(&bias[col]); v1 += __ldg(&bias[col + 1]); }
                if (EPI == 2) {
                    const float2 rv = *(const float2*)(Res + (size_t)row * N + col);
                    v0 += rv.x; v1 += rv.y;
                }
                if (EPI == 3) { v0 = gelu_exact(v0); v1 = gelu_exact(v1); }
                if (sizeof(TO) == 2) {
                    *(__half2*)((__half*)C + (size_t)row * N + col) = __floats2half2_rn(v0, v1);
                } else {
                    *(float2*)((float*)C + (size_t)row * N + col) = make_float2(v0, v1);
                }
            }
        }
    }
}

// ---------------- warp-per-row LayerNorm core ----------------
__device__ __forceinline__ void ln_warp(const float4 v[6],
                                        const float* __restrict__ w,
                                        const float* __restrict__ bvec,
                                        __half* __restrict__ dst, int lane) {
    float s = 0.f, ss = 0.f;
    #pragma unroll
    for (int i = 0; i < 6; i++) {
        s  += v[i].x + v[i].y + v[i].z + v[i].w;
        ss += v[i].x * v[i].x + v[i].y * v[i].y + v[i].z * v[i].z + v[i].w * v[i].w;
    }
    #pragma unroll
    for (int o = 16; o; o >>= 1) {
        s  += __shfl_xor_sync(0xffffffffu, s,  o);
        ss += __shfl_xor_sync(0xffffffffu, ss, o);
    }
    float mean = s * (1.0f / 768.0f);
    float var  = ss * (1.0f / 768.0f) - mean * mean;
    float rstd = rsqrtf(var + 1e-5f);
    #pragma unroll
    for (int i = 0; i < 6; i++) {
        int c4 = (lane + 32 * i) * 4;
        float4 wv = *(const float4*)(w + c4);
        float4 bv = *(const float4*)(bvec + c4);
        float o0 = (v[i].x - mean) * rstd * wv.x + bv.x;
        float o1 = (v[i].y - mean) * rstd * wv.y + bv.y;
        float o2 = (v[i].z - mean) * rstd * wv.z + bv.z;
        float o3 = (v[i].w - mean) * rstd * wv.w + bv.w;
        uint2 pk = make_uint2(pack_h2(o0, o1), pack_h2(o2, o3));
        *(uint2*)(dst + c4) = pk;
    }
}

__global__ void ln_gather_t(const float* __restrict__ x,
                            const float* __restrict__ w, const float* __restrict__ bvec,
                            float* __restrict__ xnc, __half* __restrict__ lnh) {
    int row = blockIdx.x * 8 + (threadIdx.x >> 5);
    int lane = threadIdx.x & 31;
    if (row >= MT) return;
    int b = row / Np, n = row % Np;
    const float4* src4 = (const float4*)(x + (size_t)(b * (1 + Np) + 1 + n) * D);
    float4 v[6];
    #pragma unroll
    for (int i = 0; i < 6; i++) v[i] = src4[lane + 32 * i];
    float4* dstx = (float4*)(xnc + (size_t)row * D);
    #pragma unroll
    for (int i = 0; i < 6; i++) dstx[lane + 32 * i] = v[i];
    ln_warp(v, w, bvec, lnh + (size_t)row * D, lane);
}

__global__ void ln_xs_kernel(const float* __restrict__ x,
                             const float* __restrict__ xt2,
                             const float* __restrict__ w, const float* __restrict__ bvec,
                             __half* __restrict__ lnh) {
    int row = blockIdx.x * 8 + (threadIdx.x >> 5);
    int lane = threadIdx.x & 31;
    if (row >= MS) return;
    int bt = row / SSP, j = row % SSP;
    int b = bt >> 4, t = bt & 15;
    const float* src = (j == 0)
        ? (x + (size_t)b * (1 + Np) * D)
        : (xt2 + (size_t)(b * Np + (j - 1) * Tt + t) * D);
    const float4* src4 = (const float4*)src;
    float4 v[6];
    #pragma unroll
    for (int i = 0; i < 6; i++) v[i] = src4[lane + 32 * i];
    ln_warp(v, w, bvec, lnh + (size_t)row * D, lane);
}

__global__ void ln_build(const float* __restrict__ x,
                         const float* __restrict__ xt2,
                         const float* __restrict__ rs,
                         const float* __restrict__ cls,
                         const float* __restrict__ w, const float* __restrict__ bvec,
                         float* __restrict__ xnew, __half* __restrict__ lnh) {
    int row = blockIdx.x * 8 + (threadIdx.x >> 5);
    int lane = threadIdx.x & 31;
    if (row >= MX) return;
    int b = row / (1 + Np), p = row % (1 + Np);
    float4 v[6];
    if (p == 0) {
        const float4* a4 = (const float4*)(x + (size_t)row * D);
        const float4* c4 = (const float4*)(cls + (size_t)b * D);
        #pragma unroll
        for (int i = 0; i < 6; i++) {
            float4 a = a4[lane + 32 * i], c = c4[lane + 32 * i];
            v[i] = make_float4(a.x + c.x, a.y + c.y, a.z + c.z, a.w + c.w);
        }
    } else {
        int n = p - 1, sI = n >> 4, t = n & 15;
        const float4* a4 = (const float4*)(xt2 + (size_t)(b * Np + n) * D);
        const float4* r4 = (const float4*)(rs + (size_t)((b * Tt + t) * SSP + 1 + sI) * D);
        #pragma unroll
        for (int i = 0; i < 6; i++) {
            float4 a = a4[lane + 32 * i], r = r4[lane + 32 * i];
            v[i] = make_float4(a.x + r.x, a.y + r.y, a.z + r.z, a.w + r.w);
        }
    }
    float4* dx = (float4*)(xnew + (size_t)row * D);
    #pragma unroll
    for (int i = 0; i < 6; i++) dx[lane + 32 * i] = v[i];
    ln_warp(v, w, bvec, lnh + (size_t)row * D, lane);
}

// ---------------- temporal attention: tensor-core, warp per (R,h) ----------------
// block 128 thr = 4 warps; grid (1568, 3); h = by*4 + warp.
__global__ void __launch_bounds__(128) attn_t_mma(const __half* __restrict__ qkv,
                                                  __half* __restrict__ out) {
    __shared__ char sm[4 * 6144];
    const int warp = threadIdx.x >> 5, lane = threadIdx.x & 31;
    const int R = blockIdx.x;
    const int h = blockIdx.y * 4 + warp;
    const uint32_t sQ = smem_u32(sm) + warp * 6144;
    const uint32_t sK = sQ + 2048;
    const uint32_t sV = sQ + 4096;

    const __half* base = qkv + (size_t)(R * 16) * (3 * D) + h * 64;
    // 16 rows x 8 chunks per tensor, 4 chunks per lane per tensor
    #pragma unroll
    for (int i = 0; i < 4; i++) {
        int idx = lane + i * 32;
        int r = idx >> 3, c = idx & 7;
        uint32_t sw = r * 128 + ((c ^ (r & 7)) << 4);
        const __half* rp = base + (size_t)r * (3 * D) + c * 8;
        CP_ASYNC16(sQ + sw, rp);
        CP_ASYNC16(sK + sw, rp + D);
        CP_ASYNC16(sV + sw, rp + 2 * D);
    }
    CP_COMMIT(); CP_WAIT0();
    __syncwarp();

    const uint32_t csel = (lane >> 4) & 1;
    const int fr = lane & 15;
    const uint32_t fterm = fr * 128, fxr = fr & 7;

    // S = Q K^T (16x16)
    uint32_t aq[4][4];
    float s[2][4] = {};
    #pragma unroll
    for (int kc = 0; kc < 4; kc++) {
        uint32_t c = kc * 2 + csel;
        LDSM4(aq[kc], sQ + fterm + ((c ^ fxr) << 4));
        uint32_t bf[4];
        LDSM4(bf, sK + fterm + ((c ^ fxr) << 4));
        MMA16816(s[0], aq[kc], bf[0], bf[2]);
        MMA16816(s[1], aq[kc], bf[1], bf[3]);
    }

    // softmax (rows r=lane>>2 and r+8; 16 cols, no masking)
    const float scale = 0.125f;
    #pragma unroll
    for (int t = 0; t < 2; t++)
        #pragma unroll
        for (int q = 0; q < 4; q++) s[t][q] *= scale;
    float mx0 = fmaxf(fmaxf(s[0][0], s[0][1]), fmaxf(s[1][0], s[1][1]));
    float mx1 = fmaxf(fmaxf(s[0][2], s[0][3]), fmaxf(s[1][2], s[1][3]));
    #pragma unroll
    for (int o = 1; o <= 2; o <<= 1) {
        mx0 = fmaxf(mx0, __shfl_xor_sync(0xffffffffu, mx0, o));
        mx1 = fmaxf(mx1, __shfl_xor_sync(0xffffffffu, mx1, o));
    }
    float sum0 = 0.f, sum1 = 0.f;
    #pragma unroll
    for (int t = 0; t < 2; t++) {
        s[t][0] = __expf(s[t][0] - mx0); sum0 += s[t][0];
        s[t][1] = __expf(s[t][1] - mx0); sum0 += s[t][1];
        s[t][2] = __expf(s[t][2] - mx1); sum1 += s[t][2];
        s[t][3] = __expf(s[t][3] - mx1); sum1 += s[t][3];
    }
    #pragma unroll
    for (int o = 1; o <= 2; o <<= 1) {
        sum0 += __shfl_xor_sync(0xffffffffu, sum0, o);
        sum1 += __shfl_xor_sync(0xffffffffu, sum1, o);
    }
    float inv0 = 1.0f / sum0, inv1 = 1.0f / sum1;

    // P as fp16 A-fragment
    uint32_t pa[4];
    pa[0] = pack_h2(s[0][0], s[0][1]);
    pa[1] = pack_h2(s[0][2], s[0][3]);
    pa[2] = pack_h2(s[1][0], s[1][1]);
    pa[3] = pack_h2(s[1][2], s[1][3]);

    // O = P V (16x64)
    float o[8][4] = {};
    #pragma unroll
    for (int dt2 = 0; dt2 < 4; dt2++) {
        uint32_t c = dt2 * 2 + csel;
        uint32_t vf[4];
        LDSM4T(vf, sV + fterm + ((c ^ fxr) << 4));
        MMA16816(o[2 * dt2],     pa, vf[0], vf[1]);
        MMA16816(o[2 * dt2 + 1], pa, vf[2], vf[3]);
    }

    // store
    int r0 = lane >> 2;
    #pragma unroll
    for (int dt = 0; dt < 8; dt++) {
        int col = h * 64 + dt * 8 + (lane & 3) * 2;
        *(__half2*)(out + (size_t)(R * 16 + r0) * D + col) =
            __floats2half2_rn(o[dt][0] * inv0, o[dt][1] * inv0);
        *(__half2*)(out + (size_t)(R * 16 + r0 + 8) * D + col) =
            __floats2half2_rn(o[dt][2] * inv1, o[dt][3] * inv1);
    }
}

// ---------------- spatial attention: tensor-core FA2-style (proven R5) ----------------
constexpr int Lp = 208;
constexpr int ATTN_SMEM = Lp * 128 * 2 + 64 * 128;

__global__ void __launch_bounds__(128) attn_s_mma(const __half* __restrict__ qkv,
                                                  __half* __restrict__ out) {
    int bt = blockIdx.x, h = blockIdx.y;
    extern __shared__ char sm[];
    const uint32_t sK = smem_u32(sm);
    const uint32_t sV = sK + Lp * 128;
    const uint32_t sQ = sV + Lp * 128;
    const int tid = threadIdx.x, warp = tid >> 5, lane = tid & 31;

    const __half* base = qkv + (size_t)bt * SSP * (3 * D) + h * 64;

    for (int idx = tid; idx < 11 * 8; idx += 128) {
        int r = 197 + (idx >> 3), c = idx & 7;
        uint32_t sw = r * 128 + ((c ^ (r & 7)) << 4);
        *(uint4*)(sm + sw) = make_uint4(0, 0, 0, 0);
        *(uint4*)(sm + Lp * 128 + sw) = make_uint4(0, 0, 0, 0);
    }
    for (int idx = tid; idx < 197 * 8; idx += 128) {
        int r = idx >> 3, c = idx & 7;
        uint32_t sw = r * 128 + ((c ^ (r & 7)) << 4);
        CP_ASYNC16(sK + sw, base + (size_t)r * (3 * D) + D + c * 8);
        CP_ASYNC16(sV + sw, base + (size_t)r * (3 * D) + 2 * D + c * 8);
    }
    CP_COMMIT();

    const uint32_t csel = (lane >> 4) & 1;
    const float scale = 0.125f;

    for (int qt = 0; qt < 4; qt++) {
        int q0 = qt * 64;
        __syncthreads();
        for (int idx = tid; idx < 64 * 8; idx += 128) {
            int r = idx >> 3, c = idx & 7;
            int gr = min(q0 + r, 196);
            uint32_t sw = r * 128 + ((c ^ (r & 7)) << 4);
            CP_ASYNC16(sQ + sw, base + (size_t)gr * (3 * D) + c * 8);
        }
        CP_COMMIT(); CP_WAIT0();
        __syncthreads();

        uint32_t aq[4][4];
        {
            int arow = warp * 16 + (lane & 15);
            uint32_t aterm = arow * 128, axr = arow & 7;
            #pragma unroll
            for (int kc = 0; kc < 4; kc++) {
                uint32_t c = kc * 2 + csel;
                LDSM4(aq[kc], sQ + aterm + ((c ^ axr) << 4));
            }
        }

        float s[26][4];
        #pragma unroll
        for (int t = 0; t < 26; t++)
            #pragma unroll
            for (int q = 0; q < 4; q++) s[t][q] = 0.f;

        for (int nt2 = 0; nt2 < 13; nt2++) {
            int brow = nt2 * 16 + (lane & 15);
            uint32_t bterm = brow * 128, bxr = brow & 7;
            #pragma unroll
            for (int kc = 0; kc < 4; kc++) {
                uint32_t c = kc * 2 + csel;
                uint32_t bf[4];
                LDSM4(bf, sK + bterm + ((c ^ bxr) << 4));
                MMA16816(s[2 * nt2],     aq[kc], bf[0], bf[2]);
                MMA16816(s[2 * nt2 + 1], aq[kc], bf[1], bf[3]);
            }
        }

        float mx0 = -1e30f, mx1 = -1e30f;
        #pragma unroll
        for (int t = 0; t < 26; t++) {
            int col = t * 8 + (lane & 3) * 2;
            if (col     >= 197) { s[t][0] = -1e30f; s[t][2] = -1e30f; } else { s[t][0] *= scale; s[t][2] *= scale; }
            if (col + 1 >= 197) { s[t][1] = -1e30f; s[t][3] = -1e30f; } else { s[t][1] *= scale; s[t][3] *= scale; }
            mx0 = fmaxf(mx0, fmaxf(s[t][0], s[t][1]));
            mx1 = fmaxf(mx1, fmaxf(s[t][2], s[t][3]));
        }
        #pragma unroll
        for (int o = 1; o <= 2; o <<= 1) {
            mx0 = fmaxf(mx0, __shfl_xor_sync(0xffffffffu, mx0, o));
            mx1 = fmaxf(mx1, __shfl_xor_sync(0xffffffffu, mx1, o));
        }
        float sum0 = 0.f, sum1 = 0.f;
        #pragma unroll
        for (int t = 0; t < 26; t++) {
            s[t][0] = __expf(s[t][0] - mx0); sum0 += s[t][0];
            s[t][1] = __expf(s[t][1] - mx0); sum0 += s[t][1];
            s[t][2] = __expf(s[t][2] - mx1); sum1 += s[t][2];
            s[t][3] = __expf(s[t][3] - mx1); sum1 += s[t][3];
        }
        #pragma unroll
        for (int o = 1; o <= 2; o <<= 1) {
            sum0 += __shfl_xor_sync(0xffffffffu, sum0, o);
            sum1 += __shfl_xor_sync(0xffffffffu, sum1, o);
        }
        float inv0 = 1.0f / sum0, inv1 = 1.0f / sum1;

        uint32_t pa[13][4];
        #pragma unroll
        for (int k = 0; k < 13; k++) {
            pa[k][0] = pack_h2(s[2 * k][0],     s[2 * k][1]);
            pa[k][1] = pack_h2(s[2 * k][2],     s[2 * k][3]);
            pa[k][2] = pack_h2(s[2 * k + 1][0], s[2 * k + 1][1]);
            pa[k][3] = pack_h2(s[2 * k + 1][2], s[2 * k + 1][3]);
        }

        float o[8][4];
        #pragma unroll
        for (int t = 0; t < 8; t++)
            #pragma unroll
            for (int q = 0; q < 4; q++) o[t][q] = 0.f;

        for (int kc = 0; kc < 13; kc++) {
            int vrow = kc * 16 + (lane & 15);
            uint32_t vterm = vrow * 128, vxr = vrow & 7;
            #pragma unroll
            for (int dt2 = 0; dt2 < 4; dt2++) {
                uint32_t c = dt2 * 2 + csel;
                uint32_t vf[4];
                LDSM4T(vf, sV + vterm + ((c ^ vxr) << 4));
                MMA16816(o[2 * dt2],     pa[kc], vf[0], vf[1]);
                MMA16816(o[2 * dt2 + 1], pa[kc], vf[2], vf[3]);
            }
        }

        int r0 = q0 + warp * 16 + (lane >> 2);
        #pragma unroll
        for (int dt = 0; dt < 8; dt++) {
            int col = h * 64 + dt * 8 + (lane & 3) * 2;
            if (r0 < 197)
                *(__half2*)(out + (size_t)(bt * SSP + r0) * D + col) =
                    __floats2half2_rn(o[dt][0] * inv0, o[dt][1] * inv0);
            if (r0 + 8 < 197)
                *(__half2*)(out + (size_t)(bt * SSP + r0 + 8) * D + col) =
                    __floats2half2_rn(o[dt][2] * inv1, o[dt][3] * inv1);
        }
    }
}

__global__ void cls_mean_kernel(const float* __restrict__ rs, float* __restrict__ cls) {
    int b = blockIdx.x;
    int c = threadIdx.x;
    float s = 0.f;
#pragma unroll
    for (int t = 0; t < Tt; t++) s += rs[(size_t)((b * Tt + t) * SSP) * D + c];
    cls[b * D + c] = s * (1.0f / 16.0f);
}

// ---------------- launch ----------------
extern "C" void kernel_launch(void* const* d_in, const int* in_sizes, int n_in,
                              void* d_out, int out_size) {
    const float* x        = (const float*)d_in[0];
    const float* tn1_w    = (const float*)d_in[1];
    const float* tn1_b    = (const float*)d_in[2];
    const float* t_qkv_w  = (const float*)d_in[3];
    const float* t_proj_w = (const float*)d_in[4];
    const float* t_proj_b = (const float*)d_in[5];
    const float* tfc_w    = (const float*)d_in[6];
    const float* tfc_b    = (const float*)d_in[7];
    const float* n1_w     = (const float*)d_in[8];
    const float* n1_b     = (const float*)d_in[9];
    const float* s_qkv_w  = (const float*)d_in[10];
    const float* s_proj_w = (const float*)d_in[11];
    const float* s_proj_b = (const float*)d_in[12];
    const float* n2_w     = (const float*)d_in[13];
    const float* n2_b     = (const float*)d_in[14];
    const float* fc1_w    = (const float*)d_in[15];
    const float* fc1_b    = (const float*)d_in[16];
    const float* fc2_w    = (const float*)d_in[17];
    const float* fc2_b    = (const float*)d_in[18];
    float* out = (float*)d_out;

    float  *p_xnc, *p_rs, *p_xt2, *p_xnew, *p_cls, *p_bcomb;
    __half *p_lnh, *p_qkvh, *p_atth, *p_hidh;
    __half *w_tqkv, *w_comb, *w_tfc, *w_projh, *w_sqkv, *w_sproj, *w_fc1, *w_fc2;
    cudaGetSymbolAddress((void**)&p_xnc,  g_xnc);
    cudaGetSymbolAddress((void**)&p_lnh,  g_lnh);
    cudaGetSymbolAddress((void**)&p_qkvh, g_qkvh);
    cudaGetSymbolAddress((void**)&p_atth, g_atth);
    cudaGetSymbolAddress((void**)&p_rs,   g_rs);
    cudaGetSymbolAddress((void**)&p_xt2,  g_xt2);
    cudaGetSymbolAddress((void**)&p_xnew, g_xnew);
    cudaGetSymbolAddress((void**)&p_hidh, g_hidh);
    cudaGetSymbolAddress((void**)&p_cls,  g_cls);
    cudaGetSymbolAddress((void**)&p_bcomb,g_bcomb);
    cudaGetSymbolAddress((void**)&w_tqkv, g_w_tqkv);
    cudaGetSymbolAddress((void**)&w_comb, g_w_comb);
    cudaGetSymbolAddress((void**)&w_tfc,  g_w_tfc);
    cudaGetSymbolAddress((void**)&w_projh,g_projw_h);
    cudaGetSymbolAddress((void**)&w_sqkv, g_w_sqkv);
    cudaGetSymbolAddress((void**)&w_sproj,g_w_sproj);
    cudaGetSymbolAddress((void**)&w_fc1,  g_w_fc1);
    cudaGetSymbolAddress((void**)&w_fc2,  g_w_fc2);

    cudaFuncSetAttribute(attn_s_mma, cudaFuncAttributeMaxDynamicSharedMemorySize, ATTN_SMEM);
    cudaFuncSetAttribute(gemm_hmma<0, __half>, cudaFuncAttributeMaxDynamicSharedMemorySize, GEMM_SMEM);
    cudaFuncSetAttribute(gemm_hmma<1, float >, cudaFuncAttributeMaxDynamicSharedMemorySize, GEMM_SMEM);
    cudaFuncSetAttribute(gemm_hmma<2, float >, cudaFuncAttributeMaxDynamicSharedMemorySize, GEMM_SMEM);
    cudaFuncSetAttribute(gemm_hmma<3, __half>, cudaFuncAttributeMaxDynamicSharedMemorySize, GEMM_SMEM);

    // 0) weight transposes (one launch; proj_w handled separately)
    TransJobs jobs;
    auto mkjob = [](const float* W, __half* Wt, int K, int N, int tile0) {
        TransJob j; j.W = W; j.Wt = Wt; j.K = K; j.N = N; j.tile0 = tile0; return j;
    };
    int t0 = 0;
    jobs.j[0] = mkjob(t_qkv_w, w_tqkv, D,   3 * D, t0); t0 += (D / 32) * (3 * D / 32);
    jobs.j[1] = mkjob(tfc_w,   w_tfc,  D,   D,     t0); t0 += (D / 32) * (D / 32);
    jobs.j[2] = mkjob(s_qkv_w, w_sqkv, D,   3 * D, t0); t0 += (D / 32) * (3 * D / 32);
    jobs.j[3] = mkjob(s_proj_w,w_sproj,D,   D,     t0); t0 += (D / 32) * (D / 32);
    jobs.j[4] = mkjob(fc1_w,   w_fc1,  D,   HID,   t0); t0 += (D / 32) * (HID / 32);
    jobs.j[5] = mkjob(fc2_w,   w_fc2,  HID, D,     t0); t0 += (HID / 32) * (D / 32);
    jobs.total = t0;
    transpose_all<<<t0, dim3(32, 8)>>>(jobs);

    // 0b) composite weight: w_comb[n,k] = sum_j tfc_w[j,n] * proj_w[k,j]
    copyround_h<<<(D * D + 255) / 256, 256>>>(t_proj_w, w_projh, D * D);
    gemm_hmma<0, __half><<<dim3(D / 128, D / 128), 256, GEMM_SMEM>>>(D, D, D, w_tfc, w_projh, nullptr, nullptr, w_comb);
    bias_comb<<<(D + 255) / 256, 256>>>(t_proj_b, tfc_w, tfc_b, p_bcomb);

    // 1) gather + temporal LN
    ln_gather_t<<<(MT + 7) / 8, 256>>>(x, tn1_w, tn1_b, p_xnc, p_lnh);

    // 2) temporal qkv -> half
    gemm_hmma<0, __half><<<dim3(3 * D / 128, MT / 128), 256, GEMM_SMEM>>>(MT, 3 * D, D, p_lnh, w_tqkv, nullptr, nullptr, p_qkvh);

    // 3) temporal attention (tensor cores) -> half
    attn_t_mma<<<dim3(Bn * Hh * Ww, 3), 128>>>(p_qkvh, p_atth);

    // 4) combined proj+tfc + residual(xnc) -> xt2 fp32 (one GEMM instead of two)
    gemm_hmma<2, float><<<dim3(D / 128, MT / 128), 256, GEMM_SMEM>>>(MT, D, D, p_atth, w_comb, p_bcomb, p_xnc, p_xt2);

    // 5) spatial LN -> half
    ln_xs_kernel<<<(MS + 7) / 8, 256>>>(x, p_xt2, n1_w, n1_b, p_lnh);

    // 6) spatial qkv -> half
    gemm_hmma<0, __half><<<dim3(3 * D / 128, MS / 128), 256, GEMM_SMEM>>>(MS, 3 * D, D, p_lnh, w_sqkv, nullptr, nullptr, p_qkvh);

    // 7) spatial attention (tensor cores) -> half
    attn_s_mma<<<dim3(Bn * Tt, NHh), 128, ATTN_SMEM>>>(p_qkvh, p_atth);

    // 8) spatial proj -> rs fp32
    gemm_hmma<1, float><<<dim3(D / 128, MS / 128), 256, GEMM_SMEM>>>(MS, D, D, p_atth, w_sproj, s_proj_b, nullptr, p_rs);

    // 9) cls mean over time
    cls_mean_kernel<<<Bn, D>>>(p_rs, p_cls);

    // 10) build x_new + final LN
    ln_build<<<(MX + 7) / 8, 256>>>(x, p_xt2, p_rs, p_cls, n2_w, n2_b, p_xnew, p_lnh);

    // 11) fc1 + gelu -> half hid
    gemm_hmma<3, __half><<<dim3(HID / 128, MXP / 128), 256, GEMM_SMEM>>>(MXP, HID, D, p_lnh, w_fc1, fc1_b, nullptr, p_hidh);

    // 12) fc2 + residual -> out
    gemm_hmma<2, float><<<dim3(D / 128, MXP / 128), 256, GEMM_SMEM>>>(MX, D, HID, p_hidh, w_fc2, fc2_b, p_xnew, out);
}

// round 11
// speedup vs baseline: 8.3293x; 1.0237x over previous
#include <cuda_runtime.h>
#include <cuda_fp16.h>
#include <math.h>
#include <stdint.h>

// ---------------- problem constants ----------------
constexpr int Bn  = 8;
constexpr int Tt  = 16;
constexpr int Hh  = 14;
constexpr int Ww  = 14;
constexpr int D   = 768;
constexpr int NHh = 12;
constexpr int HID = 3072;
constexpr int Np  = Hh * Ww * Tt;      // 3136
constexpr int MT  = Bn * Np;           // 25088
constexpr int SSP = 1 + Hh * Ww;       // 197
constexpr int MS  = Bn * Tt * SSP;     // 25216
constexpr int MX  = Bn * (1 + Np);     // 25096
constexpr int MXP = 25216;

// ---------------- scratch ----------------
__device__ float  g_xnc [MT * D];
__device__ __half g_lnh [MS * D];
__device__ __half g_qkvh[MS * 3 * D];
__device__ __half g_atth[MS * D];
__device__ float  g_rs  [MS * D];
__device__ float  g_xt2 [MT * D];
__device__ float  g_xnew[MX * D];
__device__ __half g_hidh[MXP * HID];
__device__ float  g_bcomb[D];
// transposed-weight buffers
__device__ __half g_w_tqkv [3 * D * D];
__device__ __half g_w_comb [D * D];
__device__ __half g_w_tfc  [D * D];
__device__ __half g_projw_h[D * D];
__device__ __half g_w_sqkv [3 * D * D];
__device__ __half g_w_sproj[D * D];
__device__ __half g_w_fc1  [HID * D];
__device__ __half g_w_fc2  [D * HID];

// ---------------- PTX helpers ----------------
__device__ __forceinline__ uint32_t smem_u32(const void* p) {
    uint32_t a;
    asm("{ .reg .u64 t; cvta.to.shared.u64 t, %1; cvt.u32.u64 %0, t; }" : "=r"(a) : "l"(p));
    return a;
}
__device__ __forceinline__ float gelu_exact(float v) {
    return 0.5f * v * (1.0f + erff(v * 0.70710678118654752440f));
}
__device__ __forceinline__ uint32_t pack_h2(float a, float b) {
    __half2 h = __floats2half2_rn(a, b);
    return *reinterpret_cast<uint32_t*>(&h);
}

#define CP_ASYNC16(dst, src) \
    asm volatile("cp.async.cg.shared.global [%0], [%1], 16;" :: "r"(dst), "l"(src) : "memory")
#define CP_COMMIT() asm volatile("cp.async.commit_group;" ::: "memory")
#define CP_WAIT0()  asm volatile("cp.async.wait_group 0;" ::: "memory")
#define CP_WAIT1()  asm volatile("cp.async.wait_group 1;" ::: "memory")

#define LDSM4(r, addr) \
    asm volatile("ldmatrix.sync.aligned.m8n8.x4.shared.b16 {%0,%1,%2,%3}, [%4];" \
        : "=r"((r)[0]), "=r"((r)[1]), "=r"((r)[2]), "=r"((r)[3]) : "r"(addr))
#define LDSM4T(r, addr) \
    asm volatile("ldmatrix.sync.aligned.m8n8.x4.trans.shared.b16 {%0,%1,%2,%3}, [%4];" \
        : "=r"((r)[0]), "=r"((r)[1]), "=r"((r)[2]), "=r"((r)[3]) : "r"(addr))

#define MMA16816(c, a, b0, b1) \
    asm volatile("mma.sync.aligned.m16n8k16.row.col.f32.f16.f16.f32 " \
        "{%0,%1,%2,%3}, {%4,%5,%6,%7}, {%8,%9}, {%0,%1,%2,%3};" \
        : "+f"((c)[0]), "+f"((c)[1]), "+f"((c)[2]), "+f"((c)[3]) \
        : "r"((a)[0]), "r"((a)[1]), "r"((a)[2]), "r"((a)[3]), "r"(b0), "r"(b1))

// ---------------- combined weight transpose ----------------
struct TransJob { const float* W; __half* Wt; int K, N, tile0; };
struct TransJobs { TransJob j[6]; int total; };

__global__ void transpose_all(TransJobs jobs) {
    __shared__ float tile[32][33];
    int t = blockIdx.x;
    int ji = 0;
    #pragma unroll
    for (int i = 1; i < 6; i++) if (t >= jobs.j[i].tile0) ji = i;
    const TransJob& J = jobs.j[ji];
    int lt = t - J.tile0;
    int ktiles = J.K / 32;
    int k0 = (lt % ktiles) * 32, n0 = (lt / ktiles) * 32;
    int tx = threadIdx.x, ty = threadIdx.y;  // 32 x 8
    for (int r = ty; r < 32; r += 8) tile[r][tx] = J.W[(size_t)(k0 + r) * J.N + n0 + tx];
    __syncthreads();
    for (int r = ty; r < 32; r += 8) J.Wt[(size_t)(n0 + r) * J.K + k0 + tx] = __float2half_rn(tile[tx][r]);
}

__global__ void copyround_h(const float* __restrict__ W, __half* __restrict__ Wh, int n) {
    int i = blockIdx.x * blockDim.x + threadIdx.x;
    if (i < n) Wh[i] = __float2half_rn(W[i]);
}

// bcomb[n] = sum_j proj_b[j] * tfc_w[j,n] + tfc_b[n]  — warp per n
__global__ void bias_comb(const float* __restrict__ proj_b, const float* __restrict__ tfc_w,
                          const float* __restrict__ tfc_b, float* __restrict__ bcomb) {
    int warp = (blockIdx.x * blockDim.x + threadIdx.x) >> 5;
    int lane = threadIdx.x & 31;
    if (warp >= D) return;
    float s = 0.f;
    for (int j = lane; j < D; j += 32) s += proj_b[j] * tfc_w[(size_t)j * D + warp];
    #pragma unroll
    for (int o = 16; o; o >>= 1) s += __shfl_xor_sync(0xffffffffu, s, o);
    if (lane == 0) bcomb[warp] = s + tfc_b[warp];
}

// ---------------- fp16 tensor-core GEMM (proven mainloop) ----------------
constexpr int TILE_B    = 128 * 128;
constexpr int STAGE_B   = 2 * TILE_B;
constexpr int GS        = 3;
constexpr int GEMM_SMEM = GS * STAGE_B;

template <int EPI, typename TO>
__global__ void __launch_bounds__(256, 2) gemm_hmma(
    int Mreal, int N, int K,
    const __half* __restrict__ A, const __half* __restrict__ Bt,
    const float* __restrict__ bias, const float* __restrict__ Res,
    TO* __restrict__ C)
{
    extern __shared__ char smbuf[];
    const uint32_t sb = smem_u32(smbuf);
    const int tid  = threadIdx.x;
    const int wid  = tid >> 5, lane = tid & 31;
    const int wm   = wid & 3,  wn   = wid >> 2;
    const int n0   = blockIdx.x * 128, m0 = blockIdx.y * 128;

    auto load_stage = [&](int chunk, int st) {
        uint32_t base = sb + st * STAGE_B;
        const __half* asrc = A  + (size_t)m0 * K + chunk * 64;
        const __half* bsrc = Bt + (size_t)n0 * K + chunk * 64;
        #pragma unroll
        for (int i = 0; i < 4; i++) {
            int idx = tid + i * 256;
            int r = idx >> 3, c = idx & 7;
            uint32_t sw = (uint32_t)((c ^ (r & 7)) << 4);
            CP_ASYNC16(base + r * 128 + sw,          asrc + (size_t)r * K + c * 8);
            CP_ASYNC16(base + TILE_B + r * 128 + sw, bsrc + (size_t)r * K + c * 8);
        }
    };

    const int NC = K / 64;
    load_stage(0, 0); CP_COMMIT();
    load_stage(1, 1); CP_COMMIT();

    float acc[2][8][4];
    #pragma unroll
    for (int i = 0; i < 2; i++)
        #pragma unroll
        for (int j = 0; j < 8; j++)
            #pragma unroll
            for (int q = 0; q < 4; q++) acc[i][j][q] = 0.f;

    const int arow = wm * 32 + (lane & 15);
    const int brow = wn * 64 + (lane & 15);
    const uint32_t aterm = arow * 128, axr = arow & 7;
    const uint32_t bterm = brow * 128, bxr = brow & 7;
    const uint32_t csel  = (lane >> 4) & 1;

    for (int i = 0; i < NC; i++) {
        if (i == NC - 1) CP_WAIT0(); else CP_WAIT1();
        __syncthreads();
        if (i + 2 < NC) { load_stage(i + 2, (i + 2) % GS); CP_COMMIT(); }

        uint32_t As = sb + (i % GS) * STAGE_B;
        uint32_t Bs = As + TILE_B;

        #pragma unroll
        for (int ks = 0; ks < 4; ks++) {
            uint32_t c   = ks * 2 + csel;
            uint32_t asw = ((c ^ axr) << 4);
            uint32_t bsw = ((c ^ bxr) << 4);
            uint32_t a0[4], a1[4];
            LDSM4(a0, As + aterm + asw);
            LDSM4(a1, As + aterm + 16 * 128 + asw);
            uint32_t bf[4][4];
            #pragma unroll
            for (int p = 0; p < 4; p++)
                LDSM4(bf[p], Bs + bterm + p * 16 * 128 + bsw);
            #pragma unroll
            for (int nt = 0; nt < 8; nt++) {
                uint32_t b0 = bf[nt >> 1][nt & 1];
                uint32_t b1 = bf[nt >> 1][(nt & 1) + 2];
                MMA16816(acc[0][nt], a0, b0, b1);
                MMA16816(acc[1][nt], a1, b0, b1);
            }
        }
    }

    const int rbase = m0 + wm * 32 + (lane >> 2);
    const int cbase = n0 + wn * 64 + (lane & 3) * 2;
    #pragma unroll
    for (int mt = 0; mt < 2; mt++) {
        #pragma unroll
        for (int half_r = 0; half_r < 2; half_r++) {
            int row = rbase + mt * 16 + half_r * 8;
            if (row >= Mreal) continue;
            #pragma unroll
            for (int nt = 0; nt < 8; nt++) {
                int col = cbase + nt * 8;
                float v0 = acc[mt][nt][half_r * 2 + 0];
                float v1 = acc[mt][nt][half_r * 2 + 1];
                if (EPI >= 1) { v0 += __ldg(&bias[col]); v1 += __ldg(&bias[col + 1]); }
                if (EPI == 2) {
                    const float2 rv = *(const float2*)(Res + (size_t)row * N + col);
                    v0 += rv.x; v1 += rv.y;
                }
                if (EPI == 3) { v0 = gelu_exact(v0); v1 = gelu_exact(v1); }
                if (sizeof(TO) == 2) {
                    *(__half2*)((__half*)C + (size_t)row * N + col) = __floats2half2_rn(v0, v1);
                } else {
                    *(float2*)((float*)C + (size_t)row * N + col) = make_float2(v0, v1);
                }
            }
        }
    }
}

// ---------------- warp-per-row LayerNorm core ----------------
__device__ __forceinline__ void ln_warp(const float4 v[6],
                                        const float* __restrict__ w,
                                        const float* __restrict__ bvec,
                                        __half* __restrict__ dst, int lane) {
    float s = 0.f, ss = 0.f;
    #pragma unroll
    for (int i = 0; i < 6; i++) {
        s  += v[i].x + v[i].y + v[i].z + v[i].w;
        ss += v[i].x * v[i].x + v[i].y * v[i].y + v[i].z * v[i].z + v[i].w * v[i].w;
    }
    #pragma unroll
    for (int o = 16; o; o >>= 1) {
        s  += __shfl_xor_sync(0xffffffffu, s,  o);
        ss += __shfl_xor_sync(0xffffffffu, ss, o);
    }
    float mean = s * (1.0f / 768.0f);
    float var  = ss * (1.0f / 768.0f) - mean * mean;
    float rstd = rsqrtf(var + 1e-5f);
    #pragma unroll
    for (int i = 0; i < 6; i++) {
        int c4 = (lane + 32 * i) * 4;
        float4 wv = *(const float4*)(w + c4);
        float4 bv = *(const float4*)(bvec + c4);
        float o0 = (v[i].x - mean) * rstd * wv.x + bv.x;
        float o1 = (v[i].y - mean) * rstd * wv.y + bv.y;
        float o2 = (v[i].z - mean) * rstd * wv.z + bv.z;
        float o3 = (v[i].w - mean) * rstd * wv.w + bv.w;
        uint2 pk = make_uint2(pack_h2(o0, o1), pack_h2(o2, o3));
        *(uint2*)(dst + c4) = pk;
    }
}

__global__ void ln_gather_t(const float* __restrict__ x,
                            const float* __restrict__ w, const float* __restrict__ bvec,
                            float* __restrict__ xnc, __half* __restrict__ lnh) {
    int row = blockIdx.x * 8 + (threadIdx.x >> 5);
    int lane = threadIdx.x & 31;
    if (row >= MT) return;
    int b = row / Np, n = row % Np;
    const float4* src4 = (const float4*)(x + (size_t)(b * (1 + Np) + 1 + n) * D);
    float4 v[6];
    #pragma unroll
    for (int i = 0; i < 6; i++) v[i] = src4[lane + 32 * i];
    float4* dstx = (float4*)(xnc + (size_t)row * D);
    #pragma unroll
    for (int i = 0; i < 6; i++) dstx[lane + 32 * i] = v[i];
    ln_warp(v, w, bvec, lnh + (size_t)row * D, lane);
}

__global__ void ln_xs_kernel(const float* __restrict__ x,
                             const float* __restrict__ xt2,
                             const float* __restrict__ w, const float* __restrict__ bvec,
                             __half* __restrict__ lnh) {
    int row = blockIdx.x * 8 + (threadIdx.x >> 5);
    int lane = threadIdx.x & 31;
    if (row >= MS) return;
    int bt = row / SSP, j = row % SSP;
    int b = bt >> 4, t = bt & 15;
    const float* src = (j == 0)
        ? (x + (size_t)b * (1 + Np) * D)
        : (xt2 + (size_t)(b * Np + (j - 1) * Tt + t) * D);
    const float4* src4 = (const float4*)src;
    float4 v[6];
    #pragma unroll
    for (int i = 0; i < 6; i++) v[i] = src4[lane + 32 * i];
    ln_warp(v, w, bvec, lnh + (size_t)row * D, lane);
}

// build x_new + final LN; cls mean computed inline for p==0 rows
__global__ void ln_build(const float* __restrict__ x,
                         const float* __restrict__ xt2,
                         const float* __restrict__ rs,
                         const float* __restrict__ w, const float* __restrict__ bvec,
                         float* __restrict__ xnew, __half* __restrict__ lnh) {
    int row = blockIdx.x * 8 + (threadIdx.x >> 5);
    int lane = threadIdx.x & 31;
    if (row >= MX) return;
    int b = row / (1 + Np), p = row % (1 + Np);
    float4 v[6];
    if (p == 0) {
        const float4* a4 = (const float4*)(x + (size_t)row * D);
        #pragma unroll
        for (int i = 0; i < 6; i++) {
            float4 a = a4[lane + 32 * i];
            float4 c = make_float4(0.f, 0.f, 0.f, 0.f);
            for (int t = 0; t < Tt; t++) {
                const float4* r4 = (const float4*)(rs + (size_t)((b * Tt + t) * SSP) * D);
                float4 r = r4[lane + 32 * i];
                c.x += r.x; c.y += r.y; c.z += r.z; c.w += r.w;
            }
            const float inv16 = 1.0f / 16.0f;
            v[i] = make_float4(a.x + c.x * inv16, a.y + c.y * inv16,
                               a.z + c.z * inv16, a.w + c.w * inv16);
        }
    } else {
        int n = p - 1, sI = n >> 4, t = n & 15;
        const float4* a4 = (const float4*)(xt2 + (size_t)(b * Np + n) * D);
        const float4* r4 = (const float4*)(rs + (size_t)((b * Tt + t) * SSP + 1 + sI) * D);
        #pragma unroll
        for (int i = 0; i < 6; i++) {
            float4 a = a4[lane + 32 * i], r = r4[lane + 32 * i];
            v[i] = make_float4(a.x + r.x, a.y + r.y, a.z + r.z, a.w + r.w);
        }
    }
    float4* dx = (float4*)(xnew + (size_t)row * D);
    #pragma unroll
    for (int i = 0; i < 6; i++) dx[lane + 32 * i] = v[i];
    ln_warp(v, w, bvec, lnh + (size_t)row * D, lane);
}

// ---------------- temporal attention: tensor-core, warp per (R,h) ----------------
__global__ void __launch_bounds__(128) attn_t_mma(const __half* __restrict__ qkv,
                                                  __half* __restrict__ out) {
    __shared__ char sm[4 * 6144];
    const int warp = threadIdx.x >> 5, lane = threadIdx.x & 31;
    const int R = blockIdx.x;
    const int h = blockIdx.y * 4 + warp;
    const uint32_t sQ = smem_u32(sm) + warp * 6144;
    const uint32_t sK = sQ + 2048;
    const uint32_t sV = sQ + 4096;

    const __half* base = qkv + (size_t)(R * 16) * (3 * D) + h * 64;
    #pragma unroll
    for (int i = 0; i < 4; i++) {
        int idx = lane + i * 32;
        int r = idx >> 3, c = idx & 7;
        uint32_t sw = r * 128 + ((c ^ (r & 7)) << 4);
        const __half* rp = base + (size_t)r * (3 * D) + c * 8;
        CP_ASYNC16(sQ + sw, rp);
        CP_ASYNC16(sK + sw, rp + D);
        CP_ASYNC16(sV + sw, rp + 2 * D);
    }
    CP_COMMIT(); CP_WAIT0();
    __syncwarp();

    const uint32_t csel = (lane >> 4) & 1;
    const int fr = lane & 15;
    const uint32_t fterm = fr * 128, fxr = fr & 7;

    uint32_t aq[4][4];
    float s[2][4] = {};
    #pragma unroll
    for (int kc = 0; kc < 4; kc++) {
        uint32_t c = kc * 2 + csel;
        LDSM4(aq[kc], sQ + fterm + ((c ^ fxr) << 4));
        uint32_t bf[4];
        LDSM4(bf, sK + fterm + ((c ^ fxr) << 4));
        MMA16816(s[0], aq[kc], bf[0], bf[2]);
        MMA16816(s[1], aq[kc], bf[1], bf[3]);
    }

    const float scale = 0.125f;
    #pragma unroll
    for (int t = 0; t < 2; t++)
        #pragma unroll
        for (int q = 0; q < 4; q++) s[t][q] *= scale;
    float mx0 = fmaxf(fmaxf(s[0][0], s[0][1]), fmaxf(s[1][0], s[1][1]));
    float mx1 = fmaxf(fmaxf(s[0][2], s[0][3]), fmaxf(s[1][2], s[1][3]));
    #pragma unroll
    for (int o = 1; o <= 2; o <<= 1) {
        mx0 = fmaxf(mx0, __shfl_xor_sync(0xffffffffu, mx0, o));
        mx1 = fmaxf(mx1, __shfl_xor_sync(0xffffffffu, mx1, o));
    }
    float sum0 = 0.f, sum1 = 0.f;
    #pragma unroll
    for (int t = 0; t < 2; t++) {
        s[t][0] = __expf(s[t][0] - mx0); sum0 += s[t][0];
        s[t][1] = __expf(s[t][1] - mx0); sum0 += s[t][1];
        s[t][2] = __expf(s[t][2] - mx1); sum1 += s[t][2];
        s[t][3] = __expf(s[t][3] - mx1); sum1 += s[t][3];
    }
    #pragma unroll
    for (int o = 1; o <= 2; o <<= 1) {
        sum0 += __shfl_xor_sync(0xffffffffu, sum0, o);
        sum1 += __shfl_xor_sync(0xffffffffu, sum1, o);
    }
    float inv0 = 1.0f / sum0, inv1 = 1.0f / sum1;

    uint32_t pa[4];
    pa[0] = pack_h2(s[0][0], s[0][1]);
    pa[1] = pack_h2(s[0][2], s[0][3]);
    pa[2] = pack_h2(s[1][0], s[1][1]);
    pa[3] = pack_h2(s[1][2], s[1][3]);

    float o[8][4] = {};
    #pragma unroll
    for (int dt2 = 0; dt2 < 4; dt2++) {
        uint32_t c = dt2 * 2 + csel;
        uint32_t vf[4];
        LDSM4T(vf, sV + fterm + ((c ^ fxr) << 4));
        MMA16816(o[2 * dt2],     pa, vf[0], vf[1]);
        MMA16816(o[2 * dt2 + 1], pa, vf[2], vf[3]);
    }

    int r0 = lane >> 2;
    #pragma unroll
    for (int dt = 0; dt < 8; dt++) {
        int col = h * 64 + dt * 8 + (lane & 3) * 2;
        *(__half2*)(out + (size_t)(R * 16 + r0) * D + col) =
            __floats2half2_rn(o[dt][0] * inv0, o[dt][1] * inv0);
        *(__half2*)(out + (size_t)(R * 16 + r0 + 8) * D + col) =
            __floats2half2_rn(o[dt][2] * inv1, o[dt][3] * inv1);
    }
}

// ---------------- spatial attention: tensor-core FA2-style ----------------
constexpr int Lp = 208;
constexpr int ATTN_SMEM = Lp * 128 * 2 + 64 * 128;

__global__ void __launch_bounds__(128) attn_s_mma(const __half* __restrict__ qkv,
                                                  __half* __restrict__ out) {
    int bt = blockIdx.x, h = blockIdx.y;
    extern __shared__ char sm[];
    const uint32_t sK = smem_u32(sm);
    const uint32_t sV = sK + Lp * 128;
    const uint32_t sQ = sV + Lp * 128;
    const int tid = threadIdx.x, warp = tid >> 5, lane = tid & 31;

    const __half* base = qkv + (size_t)bt * SSP * (3 * D) + h * 64;

    for (int idx = tid; idx < 11 * 8; idx += 128) {
        int r = 197 + (idx >> 3), c = idx & 7;
        uint32_t sw = r * 128 + ((c ^ (r & 7)) << 4);
        *(uint4*)(sm + sw) = make_uint4(0, 0, 0, 0);
        *(uint4*)(sm + Lp * 128 + sw) = make_uint4(0, 0, 0, 0);
    }
    for (int idx = tid; idx < 197 * 8; idx += 128) {
        int r = idx >> 3, c = idx & 7;
        uint32_t sw = r * 128 + ((c ^ (r & 7)) << 4);
        CP_ASYNC16(sK + sw, base + (size_t)r * (3 * D) + D + c * 8);
        CP_ASYNC16(sV + sw, base + (size_t)r * (3 * D) + 2 * D + c * 8);
    }
    CP_COMMIT();

    const uint32_t csel = (lane >> 4) & 1;
    const float scale = 0.125f;

    for (int qt = 0; qt < 4; qt++) {
        int q0 = qt * 64;
        __syncthreads();
        for (int idx = tid; idx < 64 * 8; idx += 128) {
            int r = idx >> 3, c = idx & 7;
            int gr = min(q0 + r, 196);
            uint32_t sw = r * 128 + ((c ^ (r & 7)) << 4);
            CP_ASYNC16(sQ + sw, base + (size_t)gr * (3 * D) + c * 8);
        }
        CP_COMMIT(); CP_WAIT0();
        __syncthreads();

        uint32_t aq[4][4];
        {
            int arow = warp * 16 + (lane & 15);
            uint32_t aterm = arow * 128, axr = arow & 7;
            #pragma unroll
            for (int kc = 0; kc < 4; kc++) {
                uint32_t c = kc * 2 + csel;
                LDSM4(aq[kc], sQ + aterm + ((c ^ axr) << 4));
            }
        }

        float s[26][4];
        #pragma unroll
        for (int t = 0; t < 26; t++)
            #pragma unroll
            for (int q = 0; q < 4; q++) s[t][q] = 0.f;

        for (int nt2 = 0; nt2 < 13; nt2++) {
            int brow = nt2 * 16 + (lane & 15);
            uint32_t bterm = brow * 128, bxr = brow & 7;
            #pragma unroll
            for (int kc = 0; kc < 4; kc++) {
                uint32_t c = kc * 2 + csel;
                uint32_t bf[4];
                LDSM4(bf, sK + bterm + ((c ^ bxr) << 4));
                MMA16816(s[2 * nt2],     aq[kc], bf[0], bf[2]);
                MMA16816(s[2 * nt2 + 1], aq[kc], bf[1], bf[3]);
            }
        }

        float mx0 = -1e30f, mx1 = -1e30f;
        #pragma unroll
        for (int t = 0; t < 26; t++) {
            int col = t * 8 + (lane & 3) * 2;
            if (col     >= 197) { s[t][0] = -1e30f; s[t][2] = -1e30f; } else { s[t][0] *= scale; s[t][2] *= scale; }
            if (col + 1 >= 197) { s[t][1] = -1e30f; s[t][3] = -1e30f; } else { s[t][1] *= scale; s[t][3] *= scale; }
            mx0 = fmaxf(mx0, fmaxf(s[t][0], s[t][1]));
            mx1 = fmaxf(mx1, fmaxf(s[t][2], s[t][3]));
        }
        #pragma unroll
        for (int o = 1; o <= 2; o <<= 1) {
            mx0 = fmaxf(mx0, __shfl_xor_sync(0xffffffffu, mx0, o));
            mx1 = fmaxf(mx1, __shfl_xor_sync(0xffffffffu, mx1, o));
        }
        float sum0 = 0.f, sum1 = 0.f;
        #pragma unroll
        for (int t = 0; t < 26; t++) {
            s[t][0] = __expf(s[t][0] - mx0); sum0 += s[t][0];
            s[t][1] = __expf(s[t][1] - mx0); sum0 += s[t][1];
            s[t][2] = __expf(s[t][2] - mx1); sum1 += s[t][2];
            s[t][3] = __expf(s[t][3] - mx1); sum1 += s[t][3];
        }
        #pragma unroll
        for (int o = 1; o <= 2; o <<= 1) {
            sum0 += __shfl_xor_sync(0xffffffffu, sum0, o);
            sum1 += __shfl_xor_sync(0xffffffffu, sum1, o);
        }
        float inv0 = 1.0f / sum0, inv1 = 1.0f / sum1;

        uint32_t pa[13][4];
        #pragma unroll
        for (int k = 0; k < 13; k++) {
            pa[k][0] = pack_h2(s[2 * k][0],     s[2 * k][1]);
            pa[k][1] = pack_h2(s[2 * k][2],     s[2 * k][3]);
            pa[k][2] = pack_h2(s[2 * k + 1][0], s[2 * k + 1][1]);
            pa[k][3] = pack_h2(s[2 * k + 1][2], s[2 * k + 1][3]);
        }

        float o[8][4];
        #pragma unroll
        for (int t = 0; t < 8; t++)
            #pragma unroll
            for (int q = 0; q < 4; q++) o[t][q] = 0.f;

        for (int kc = 0; kc < 13; kc++) {
            int vrow = kc * 16 + (lane & 15);
            uint32_t vterm = vrow * 128, vxr = vrow & 7;
            #pragma unroll
            for (int dt2 = 0; dt2 < 4; dt2++) {
                uint32_t c = dt2 * 2 + csel;
                uint32_t vf[4];
                LDSM4T(vf, sV + vterm + ((c ^ vxr) << 4));
                MMA16816(o[2 * dt2],     pa[kc], vf[0], vf[1]);
                MMA16816(o[2 * dt2 + 1], pa[kc], vf[2], vf[3]);
            }
        }

        int r0 = q0 + warp * 16 + (lane >> 2);
        #pragma unroll
        for (int dt = 0; dt < 8; dt++) {
            int col = h * 64 + dt * 8 + (lane & 3) * 2;
            if (r0 < 197)
                *(__half2*)(out + (size_t)(bt * SSP + r0) * D + col) =
                    __floats2half2_rn(o[dt][0] * inv0, o[dt][1] * inv0);
            if (r0 + 8 < 197)
                *(__half2*)(out + (size_t)(bt * SSP + r0 + 8) * D + col) =
                    __floats2half2_rn(o[dt][2] * inv1, o[dt][3] * inv1);
        }
    }
}

// ---------------- launch ----------------
extern "C" void kernel_launch(void* const* d_in, const int* in_sizes, int n_in,
                              void* d_out, int out_size) {
    const float* x        = (const float*)d_in[0];
    const float* tn1_w    = (const float*)d_in[1];
    const float* tn1_b    = (const float*)d_in[2];
    const float* t_qkv_w  = (const float*)d_in[3];
    const float* t_proj_w = (const float*)d_in[4];
    const float* t_proj_b = (const float*)d_in[5];
    const float* tfc_w    = (const float*)d_in[6];
    const float* tfc_b    = (const float*)d_in[7];
    const float* n1_w     = (const float*)d_in[8];
    const float* n1_b     = (const float*)d_in[9];
    const float* s_qkv_w  = (const float*)d_in[10];
    const float* s_proj_w = (const float*)d_in[11];
    const float* s_proj_b = (const float*)d_in[12];
    const float* n2_w     = (const float*)d_in[13];
    const float* n2_b     = (const float*)d_in[14];
    const float* fc1_w    = (const float*)d_in[15];
    const float* fc1_b    = (const float*)d_in[16];
    const float* fc2_w    = (const float*)d_in[17];
    const float* fc2_b    = (const float*)d_in[18];
    float* out = (float*)d_out;

    float  *p_xnc, *p_rs, *p_xt2, *p_xnew, *p_bcomb;
    __half *p_lnh, *p_qkvh, *p_atth, *p_hidh;
    __half *w_tqkv, *w_comb, *w_tfc, *w_projh, *w_sqkv, *w_sproj, *w_fc1, *w_fc2;
    cudaGetSymbolAddress((void**)&p_xnc,  g_xnc);
    cudaGetSymbolAddress((void**)&p_lnh,  g_lnh);
    cudaGetSymbolAddress((void**)&p_qkvh, g_qkvh);
    cudaGetSymbolAddress((void**)&p_atth, g_atth);
    cudaGetSymbolAddress((void**)&p_rs,   g_rs);
    cudaGetSymbolAddress((void**)&p_xt2,  g_xt2);
    cudaGetSymbolAddress((void**)&p_xnew, g_xnew);
    cudaGetSymbolAddress((void**)&p_hidh, g_hidh);
    cudaGetSymbolAddress((void**)&p_bcomb,g_bcomb);
    cudaGetSymbolAddress((void**)&w_tqkv, g_w_tqkv);
    cudaGetSymbolAddress((void**)&w_comb, g_w_comb);
    cudaGetSymbolAddress((void**)&w_tfc,  g_w_tfc);
    cudaGetSymbolAddress((void**)&w_projh,g_projw_h);
    cudaGetSymbolAddress((void**)&w_sqkv, g_w_sqkv);
    cudaGetSymbolAddress((void**)&w_sproj,g_w_sproj);
    cudaGetSymbolAddress((void**)&w_fc1,  g_w_fc1);
    cudaGetSymbolAddress((void**)&w_fc2,  g_w_fc2);

    cudaFuncSetAttribute(attn_s_mma, cudaFuncAttributeMaxDynamicSharedMemorySize, ATTN_SMEM);
    cudaFuncSetAttribute(gemm_hmma<0, __half>, cudaFuncAttributeMaxDynamicSharedMemorySize, GEMM_SMEM);
    cudaFuncSetAttribute(gemm_hmma<1, float >, cudaFuncAttributeMaxDynamicSharedMemorySize, GEMM_SMEM);
    cudaFuncSetAttribute(gemm_hmma<2, float >, cudaFuncAttributeMaxDynamicSharedMemorySize, GEMM_SMEM);
    cudaFuncSetAttribute(gemm_hmma<3, __half>, cudaFuncAttributeMaxDynamicSharedMemorySize, GEMM_SMEM);

    // side stream + events for prologue overlap (created once; capture-legal fork/join)
    static cudaStream_t s2 = nullptr;
    static cudaEvent_t evFork = nullptr, evJoin = nullptr;
    if (!s2) {
        cudaStreamCreateWithFlags(&s2, cudaStreamNonBlocking);
        cudaEventCreateWithFlags(&evFork, cudaEventDisableTiming);
        cudaEventCreateWithFlags(&evJoin, cudaEventDisableTiming);
    }

    // 0) weight transposes (one launch)
    TransJobs jobs;
    auto mkjob = [](const float* W, __half* Wt, int K, int N, int tile0) {
        TransJob j; j.W = W; j.Wt = Wt; j.K = K; j.N = N; j.tile0 = tile0; return j;
    };
    int t0 = 0;
    jobs.j[0] = mkjob(t_qkv_w, w_tqkv, D,   3 * D, t0); t0 += (D / 32) * (3 * D / 32);
    jobs.j[1] = mkjob(tfc_w,   w_tfc,  D,   D,     t0); t0 += (D / 32) * (D / 32);
    jobs.j[2] = mkjob(s_qkv_w, w_sqkv, D,   3 * D, t0); t0 += (D / 32) * (3 * D / 32);
    jobs.j[3] = mkjob(s_proj_w,w_sproj,D,   D,     t0); t0 += (D / 32) * (D / 32);
    jobs.j[4] = mkjob(fc1_w,   w_fc1,  D,   HID,   t0); t0 += (D / 32) * (HID / 32);
    jobs.j[5] = mkjob(fc2_w,   w_fc2,  HID, D,     t0); t0 += (HID / 32) * (D / 32);
    jobs.total = t0;
    transpose_all<<<t0, dim3(32, 8)>>>(jobs);

    // fork: composite-weight chain on s2, overlapping steps 1-3
    cudaEventRecord(evFork, 0);
    cudaStreamWaitEvent(s2, evFork, 0);
    copyround_h<<<(D * D + 255) / 256, 256, 0, s2>>>(t_proj_w, w_projh, D * D);
    gemm_hmma<0, __half><<<dim3(D / 128, D / 128), 256, GEMM_SMEM, s2>>>(D, D, D, w_tfc, w_projh, nullptr, nullptr, w_comb);
    bias_comb<<<(D * 32 + 255) / 256, 256, 0, s2>>>(t_proj_b, tfc_w, tfc_b, p_bcomb);
    cudaEventRecord(evJoin, s2);

    // 1) gather + temporal LN
    ln_gather_t<<<(MT + 7) / 8, 256>>>(x, tn1_w, tn1_b, p_xnc, p_lnh);

    // 2) temporal qkv -> half
    gemm_hmma<0, __half><<<dim3(3 * D / 128, MT / 128), 256, GEMM_SMEM>>>(MT, 3 * D, D, p_lnh, w_tqkv, nullptr, nullptr, p_qkvh);

    // 3) temporal attention (tensor cores) -> half
    attn_t_mma<<<dim3(Bn * Hh * Ww, 3), 128>>>(p_qkvh, p_atth);

    // join before using w_comb / bcomb
    cudaStreamWaitEvent(0, evJoin, 0);

    // 4) combined proj+tfc + residual(xnc) -> xt2 fp32
    gemm_hmma<2, float><<<dim3(D / 128, MT / 128), 256, GEMM_SMEM>>>(MT, D, D, p_atth, w_comb, p_bcomb, p_xnc, p_xt2);

    // 5) spatial LN -> half
    ln_xs_kernel<<<(MS + 7) / 8, 256>>>(x, p_xt2, n1_w, n1_b, p_lnh);

    // 6) spatial qkv -> half
    gemm_hmma<0, __half><<<dim3(3 * D / 128, MS / 128), 256, GEMM_SMEM>>>(MS, 3 * D, D, p_lnh, w_sqkv, nullptr, nullptr, p_qkvh);

    // 7) spatial attention (tensor cores) -> half
    attn_s_mma<<<dim3(Bn * Tt, NHh), 128, ATTN_SMEM>>>(p_qkvh, p_atth);

    // 8) spatial proj -> rs fp32
    gemm_hmma<1, float><<<dim3(D / 128, MS / 128), 256, GEMM_SMEM>>>(MS, D, D, p_atth, w_sproj, s_proj_b, nullptr, p_rs);

    // 9) build x_new (+inline cls mean) + final LN
    ln_build<<<(MX + 7) / 8, 256>>>(x, p_xt2, p_rs, n2_w, n2_b, p_xnew, p_lnh);

    // 10) fc1 + gelu -> half hid
    gemm_hmma<3, __half><<<dim3(HID / 128, MXP / 128), 256, GEMM_SMEM>>>(MXP, HID, D, p_lnh, w_fc1, fc1_b, nullptr, p_hidh);

    // 11) fc2 + residual -> out
    gemm_hmma<2, float><<<dim3(D / 128, MXP / 128), 256, GEMM_SMEM>>>(MX, D, HID, p_hidh, w_fc2, fc2_b, p_xnew, out);
}

// round 12
// speedup vs baseline: 8.4402x; 1.0133x over previous
#include <cuda_runtime.h>
#include <cuda_fp16.h>
#include <math.h>
#include <stdint.h>

// ---------------- problem constants ----------------
constexpr int Bn  = 8;
constexpr int Tt  = 16;
constexpr int Hh  = 14;
constexpr int Ww  = 14;
constexpr int D   = 768;
constexpr int NHh = 12;
constexpr int HID = 3072;
constexpr int Np  = Hh * Ww * Tt;      // 3136
constexpr int MT  = Bn * Np;           // 25088
constexpr int SSP = 1 + Hh * Ww;       // 197
constexpr int MS  = Bn * Tt * SSP;     // 25216
constexpr int MX  = Bn * (1 + Np);     // 25096
constexpr int MXP = 25216;

// ---------------- scratch ----------------
__device__ float  g_xnc [MT * D];
__device__ __half g_lnh [MS * D];
__device__ __half g_qkvh[MS * 3 * D];
__device__ __half g_atth[MS * D];
__device__ float  g_xt2 [MT * D];
__device__ float  g_xnew[MX * D];
__device__ __half g_hidh[MXP * HID];
__device__ float  g_clsb[Bn * Tt * D];   // cls rows of spatial-proj output
__device__ float  g_bcomb[D];
// transposed-weight buffers
__device__ __half g_w_tqkv [3 * D * D];
__device__ __half g_w_comb [D * D];
__device__ __half g_w_tfc  [D * D];
__device__ __half g_projw_h[D * D];
__device__ __half g_w_sqkv [3 * D * D];
__device__ __half g_w_sproj[D * D];
__device__ __half g_w_fc1  [HID * D];
__device__ __half g_w_fc2  [D * HID];

// ---------------- PTX helpers ----------------
__device__ __forceinline__ uint32_t smem_u32(const void* p) {
    uint32_t a;
    asm("{ .reg .u64 t; cvta.to.shared.u64 t, %1; cvt.u32.u64 %0, t; }" : "=r"(a) : "l"(p));
    return a;
}
__device__ __forceinline__ float gelu_exact(float v) {
    return 0.5f * v * (1.0f + erff(v * 0.70710678118654752440f));
}
__device__ __forceinline__ uint32_t pack_h2(float a, float b) {
    __half2 h = __floats2half2_rn(a, b);
    return *reinterpret_cast<uint32_t*>(&h);
}

#define CP_ASYNC16(dst, src) \
    asm volatile("cp.async.cg.shared.global [%0], [%1], 16;" :: "r"(dst), "l"(src) : "memory")
#define CP_COMMIT() asm volatile("cp.async.commit_group;" ::: "memory")
#define CP_WAIT0()  asm volatile("cp.async.wait_group 0;" ::: "memory")
#define CP_WAIT1()  asm volatile("cp.async.wait_group 1;" ::: "memory")

#define LDSM4(r, addr) \
    asm volatile("ldmatrix.sync.aligned.m8n8.x4.shared.b16 {%0,%1,%2,%3}, [%4];" \
        : "=r"((r)[0]), "=r"((r)[1]), "=r"((r)[2]), "=r"((r)[3]) : "r"(addr))
#define LDSM4T(r, addr) \
    asm volatile("ldmatrix.sync.aligned.m8n8.x4.trans.shared.b16 {%0,%1,%2,%3}, [%4];" \
        : "=r"((r)[0]), "=r"((r)[1]), "=r"((r)[2]), "=r"((r)[3]) : "r"(addr))

#define MMA16816(c, a, b0, b1) \
    asm volatile("mma.sync.aligned.m16n8k16.row.col.f32.f16.f16.f32 " \
        "{%0,%1,%2,%3}, {%4,%5,%6,%7}, {%8,%9}, {%0,%1,%2,%3};" \
        : "+f"((c)[0]), "+f"((c)[1]), "+f"((c)[2]), "+f"((c)[3]) \
        : "r"((a)[0]), "r"((a)[1]), "r"((a)[2]), "r"((a)[3]), "r"(b0), "r"(b1))

// ---------------- combined weight transpose ----------------
struct TransJob { const float* W; __half* Wt; int K, N, tile0; };
struct TransJobs { TransJob j[6]; int total; };

__global__ void transpose_all(TransJobs jobs) {
    __shared__ float tile[32][33];
    int t = blockIdx.x;
    int ji = 0;
    #pragma unroll
    for (int i = 1; i < 6; i++) if (t >= jobs.j[i].tile0) ji = i;
    const TransJob& J = jobs.j[ji];
    int lt = t - J.tile0;
    int ktiles = J.K / 32;
    int k0 = (lt % ktiles) * 32, n0 = (lt / ktiles) * 32;
    int tx = threadIdx.x, ty = threadIdx.y;  // 32 x 8
    for (int r = ty; r < 32; r += 8) tile[r][tx] = J.W[(size_t)(k0 + r) * J.N + n0 + tx];
    __syncthreads();
    for (int r = ty; r < 32; r += 8) J.Wt[(size_t)(n0 + r) * J.K + k0 + tx] = __float2half_rn(tile[tx][r]);
}

__global__ void copyround_h(const float* __restrict__ W, __half* __restrict__ Wh, int n) {
    int i = blockIdx.x * blockDim.x + threadIdx.x;
    if (i < n) Wh[i] = __float2half_rn(W[i]);
}

// bcomb[n] = sum_j proj_b[j] * tfc_w[j,n] + tfc_b[n]  — warp per n
__global__ void bias_comb(const float* __restrict__ proj_b, const float* __restrict__ tfc_w,
                          const float* __restrict__ tfc_b, float* __restrict__ bcomb) {
    int warp = (blockIdx.x * blockDim.x + threadIdx.x) >> 5;
    int lane = threadIdx.x & 31;
    if (warp >= D) return;
    float s = 0.f;
    for (int j = lane; j < D; j += 32) s += proj_b[j] * tfc_w[(size_t)j * D + warp];
    #pragma unroll
    for (int o = 16; o; o >>= 1) s += __shfl_xor_sync(0xffffffffu, s, o);
    if (lane == 0) bcomb[warp] = s + tfc_b[warp];
}

// ---------------- fp16 tensor-core GEMM (proven mainloop) ----------------
// EPI: 0=none 1=+bias 2=+bias+residual 3=+bias+gelu
//      4=+bias, scatter x_new build: row r -> (bt=r/197, j=r%197);
//        j==0 -> Aux[bt] row; j>0 -> C row b*(1+Np)+1+n with Res row b*Np+n added.
constexpr int TILE_B    = 128 * 128;
constexpr int STAGE_B   = 2 * TILE_B;
constexpr int GS        = 3;
constexpr int GEMM_SMEM = GS * STAGE_B;

template <int EPI, typename TO>
__global__ void __launch_bounds__(256, 2) gemm_hmma(
    int Mreal, int N, int K,
    const __half* __restrict__ A, const __half* __restrict__ Bt,
    const float* __restrict__ bias, const float* __restrict__ Res,
    TO* __restrict__ C, float* __restrict__ Aux)
{
    extern __shared__ char smbuf[];
    const uint32_t sb = smem_u32(smbuf);
    const int tid  = threadIdx.x;
    const int wid  = tid >> 5, lane = tid & 31;
    const int wm   = wid & 3,  wn   = wid >> 2;
    const int n0   = blockIdx.x * 128, m0 = blockIdx.y * 128;

    auto load_stage = [&](int chunk, int st) {
        uint32_t base = sb + st * STAGE_B;
        const __half* asrc = A  + (size_t)m0 * K + chunk * 64;
        const __half* bsrc = Bt + (size_t)n0 * K + chunk * 64;
        #pragma unroll
        for (int i = 0; i < 4; i++) {
            int idx = tid + i * 256;
            int r = idx >> 3, c = idx & 7;
            uint32_t sw = (uint32_t)((c ^ (r & 7)) << 4);
            CP_ASYNC16(base + r * 128 + sw,          asrc + (size_t)r * K + c * 8);
            CP_ASYNC16(base + TILE_B + r * 128 + sw, bsrc + (size_t)r * K + c * 8);
        }
    };

    const int NC = K / 64;
    load_stage(0, 0); CP_COMMIT();
    load_stage(1, 1); CP_COMMIT();

    float acc[2][8][4];
    #pragma unroll
    for (int i = 0; i < 2; i++)
        #pragma unroll
        for (int j = 0; j < 8; j++)
            #pragma unroll
            for (int q = 0; q < 4; q++) acc[i][j][q] = 0.f;

    const int arow = wm * 32 + (lane & 15);
    const int brow = wn * 64 + (lane & 15);
    const uint32_t aterm = arow * 128, axr = arow & 7;
    const uint32_t bterm = brow * 128, bxr = brow & 7;
    const uint32_t csel  = (lane >> 4) & 1;

    for (int i = 0; i < NC; i++) {
        if (i == NC - 1) CP_WAIT0(); else CP_WAIT1();
        __syncthreads();
        if (i + 2 < NC) { load_stage(i + 2, (i + 2) % GS); CP_COMMIT(); }

        uint32_t As = sb + (i % GS) * STAGE_B;
        uint32_t Bs = As + TILE_B;

        #pragma unroll
        for (int ks = 0; ks < 4; ks++) {
            uint32_t c   = ks * 2 + csel;
            uint32_t asw = ((c ^ axr) << 4);
            uint32_t bsw = ((c ^ bxr) << 4);
            uint32_t a0[4], a1[4];
            LDSM4(a0, As + aterm + asw);
            LDSM4(a1, As + aterm + 16 * 128 + asw);
            uint32_t bf[4][4];
            #pragma unroll
            for (int p = 0; p < 4; p++)
                LDSM4(bf[p], Bs + bterm + p * 16 * 128 + bsw);
            #pragma unroll
            for (int nt = 0; nt < 8; nt++) {
                uint32_t b0 = bf[nt >> 1][nt & 1];
                uint32_t b1 = bf[nt >> 1][(nt & 1) + 2];
                MMA16816(acc[0][nt], a0, b0, b1);
                MMA16816(acc[1][nt], a1, b0, b1);
            }
        }
    }

    const int rbase = m0 + wm * 32 + (lane >> 2);
    const int cbase = n0 + wn * 64 + (lane & 3) * 2;
    #pragma unroll
    for (int mt = 0; mt < 2; mt++) {
        #pragma unroll
        for (int half_r = 0; half_r < 2; half_r++) {
            int row = rbase + mt * 16 + half_r * 8;
            if (row >= Mreal) continue;
            if (EPI == 4) {
                int bt = row / SSP, j = row % SSP;
                int b = bt >> 4, t = bt & 15;
                if (j == 0) {
                    float* dst = Aux + (size_t)bt * D;
                    #pragma unroll
                    for (int nt = 0; nt < 8; nt++) {
                        int col = cbase + nt * 8;
                        float v0 = acc[mt][nt][half_r * 2 + 0] + __ldg(&bias[col]);
                        float v1 = acc[mt][nt][half_r * 2 + 1] + __ldg(&bias[col + 1]);
                        *(float2*)(dst + col) = make_float2(v0, v1);
                    }
                } else {
                    int n = (j - 1) * Tt + t;
                    const float* rsrc = Res + (size_t)(b * Np + n) * D;
                    float* dst = (float*)C + (size_t)(b * (1 + Np) + 1 + n) * D;
                    #pragma unroll
                    for (int nt = 0; nt < 8; nt++) {
                        int col = cbase + nt * 8;
                        const float2 rv = *(const float2*)(rsrc + col);
                        float v0 = acc[mt][nt][half_r * 2 + 0] + __ldg(&bias[col]) + rv.x;
                        float v1 = acc[mt][nt][half_r * 2 + 1] + __ldg(&bias[col + 1]) + rv.y;
                        *(float2*)(dst + col) = make_float2(v0, v1);
                    }
                }
            } else {
                #pragma unroll
                for (int nt = 0; nt < 8; nt++) {
                    int col = cbase + nt * 8;
                    float v0 = acc[mt][nt][half_r * 2 + 0];
                    float v1 = acc[mt][nt][half_r * 2 + 1];
                    if (EPI >= 1) { v0 += __ldg(&bias[col]); v1 += __ldg(&bias[col + 1]); }
                    if (EPI == 2) {
                        const float2 rv = *(const float2*)(Res + (size_t)row * N + col);
                        v0 += rv.x; v1 += rv.y;
                    }
                    if (EPI == 3) { v0 = gelu_exact(v0); v1 = gelu_exact(v1); }
                    if (sizeof(TO) == 2) {
                        *(__half2*)((__half*)C + (size_t)row * N + col) = __floats2half2_rn(v0, v1);
                    } else {
                        *(float2*)((float*)C + (size_t)row * N + col) = make_float2(v0, v1);
                    }
                }
            }
        }
    }
}

// ---------------- warp-per-row LayerNorm core ----------------
__device__ __forceinline__ void ln_warp(const float4 v[6],
                                        const float* __restrict__ w,
                                        const float* __restrict__ bvec,
                                        __half* __restrict__ dst, int lane) {
    float s = 0.f, ss = 0.f;
    #pragma unroll
    for (int i = 0; i < 6; i++) {
        s  += v[i].x + v[i].y + v[i].z + v[i].w;
        ss += v[i].x * v[i].x + v[i].y * v[i].y + v[i].z * v[i].z + v[i].w * v[i].w;
    }
    #pragma unroll
    for (int o = 16; o; o >>= 1) {
        s  += __shfl_xor_sync(0xffffffffu, s,  o);
        ss += __shfl_xor_sync(0xffffffffu, ss, o);
    }
    float mean = s * (1.0f / 768.0f);
    float var  = ss * (1.0f / 768.0f) - mean * mean;
    float rstd = rsqrtf(var + 1e-5f);
    #pragma unroll
    for (int i = 0; i < 6; i++) {
        int c4 = (lane + 32 * i) * 4;
        float4 wv = *(const float4*)(w + c4);
        float4 bv = *(const float4*)(bvec + c4);
        float o0 = (v[i].x - mean) * rstd * wv.x + bv.x;
        float o1 = (v[i].y - mean) * rstd * wv.y + bv.y;
        float o2 = (v[i].z - mean) * rstd * wv.z + bv.z;
        float o3 = (v[i].w - mean) * rstd * wv.w + bv.w;
        uint2 pk = make_uint2(pack_h2(o0, o1), pack_h2(o2, o3));
        *(uint2*)(dst + c4) = pk;
    }
}

__global__ void ln_gather_t(const float* __restrict__ x,
                            const float* __restrict__ w, const float* __restrict__ bvec,
                            float* __restrict__ xnc, __half* __restrict__ lnh) {
    int row = blockIdx.x * 8 + (threadIdx.x >> 5);
    int lane = threadIdx.x & 31;
    if (row >= MT) return;
    int b = row / Np, n = row % Np;
    const float4* src4 = (const float4*)(x + (size_t)(b * (1 + Np) + 1 + n) * D);
    float4 v[6];
    #pragma unroll
    for (int i = 0; i < 6; i++) v[i] = src4[lane + 32 * i];
    float4* dstx = (float4*)(xnc + (size_t)row * D);
    #pragma unroll
    for (int i = 0; i < 6; i++) dstx[lane + 32 * i] = v[i];
    ln_warp(v, w, bvec, lnh + (size_t)row * D, lane);
}

__global__ void ln_xs_kernel(const float* __restrict__ x,
                             const float* __restrict__ xt2,
                             const float* __restrict__ w, const float* __restrict__ bvec,
                             __half* __restrict__ lnh) {
    int row = blockIdx.x * 8 + (threadIdx.x >> 5);
    int lane = threadIdx.x & 31;
    if (row >= MS) return;
    int bt = row / SSP, j = row % SSP;
    int b = bt >> 4, t = bt & 15;
    const float* src = (j == 0)
        ? (x + (size_t)b * (1 + Np) * D)
        : (xt2 + (size_t)(b * Np + (j - 1) * Tt + t) * D);
    const float4* src4 = (const float4*)src;
    float4 v[6];
    #pragma unroll
    for (int i = 0; i < 6; i++) v[i] = src4[lane + 32 * i];
    ln_warp(v, w, bvec, lnh + (size_t)row * D, lane);
}

// final LN over x_new; x_new rows p>0 already complete (written by EPI4 GEMM);
// p==0 rows assembled here from x + mean_t(clsb) and written to xnew.
__global__ void ln_build(const float* __restrict__ x,
                         const float* __restrict__ xnew_in,
                         const float* __restrict__ clsb,
                         const float* __restrict__ w, const float* __restrict__ bvec,
                         float* __restrict__ xnew, __half* __restrict__ lnh) {
    int row = blockIdx.x * 8 + (threadIdx.x >> 5);
    int lane = threadIdx.x & 31;
    if (row >= MX) return;
    int b = row / (1 + Np), p = row % (1 + Np);
    float4 v[6];
    if (p == 0) {
        const float4* a4 = (const float4*)(x + (size_t)row * D);
        #pragma unroll
        for (int i = 0; i < 6; i++) {
            float4 a = a4[lane + 32 * i];
            float4 c = make_float4(0.f, 0.f, 0.f, 0.f);
            for (int t = 0; t < Tt; t++) {
                const float4* r4 = (const float4*)(clsb + (size_t)(b * Tt + t) * D);
                float4 r = r4[lane + 32 * i];
                c.x += r.x; c.y += r.y; c.z += r.z; c.w += r.w;
            }
            const float inv16 = 1.0f / 16.0f;
            v[i] = make_float4(a.x + c.x * inv16, a.y + c.y * inv16,
                               a.z + c.z * inv16, a.w + c.w * inv16);
        }
        float4* dx = (float4*)(xnew + (size_t)row * D);
        #pragma unroll
        for (int i = 0; i < 6; i++) dx[lane + 32 * i] = v[i];
    } else {
        const float4* a4 = (const float4*)(xnew_in + (size_t)row * D);
        #pragma unroll
        for (int i = 0; i < 6; i++) v[i] = a4[lane + 32 * i];
    }
    ln_warp(v, w, bvec, lnh + (size_t)row * D, lane);
}

// ---------------- temporal attention: tensor-core, warp per (R,h) ----------------
__global__ void __launch_bounds__(128) attn_t_mma(const __half* __restrict__ qkv,
                                                  __half* __restrict__ out) {
    __shared__ char sm[4 * 6144];
    const int warp = threadIdx.x >> 5, lane = threadIdx.x & 31;
    const int R = blockIdx.x;
    const int h = blockIdx.y * 4 + warp;
    const uint32_t sQ = smem_u32(sm) + warp * 6144;
    const uint32_t sK = sQ + 2048;
    const uint32_t sV = sQ + 4096;

    const __half* base = qkv + (size_t)(R * 16) * (3 * D) + h * 64;
    #pragma unroll
    for (int i = 0; i < 4; i++) {
        int idx = lane + i * 32;
        int r = idx >> 3, c = idx & 7;
        uint32_t sw = r * 128 + ((c ^ (r & 7)) << 4);
        const __half* rp = base + (size_t)r * (3 * D) + c * 8;
        CP_ASYNC16(sQ + sw, rp);
        CP_ASYNC16(sK + sw, rp + D);
        CP_ASYNC16(sV + sw, rp + 2 * D);
    }
    CP_COMMIT(); CP_WAIT0();
    __syncwarp();

    const uint32_t csel = (lane >> 4) & 1;
    const int fr = lane & 15;
    const uint32_t fterm = fr * 128, fxr = fr & 7;

    uint32_t aq[4][4];
    float s[2][4] = {};
    #pragma unroll
    for (int kc = 0; kc < 4; kc++) {
        uint32_t c = kc * 2 + csel;
        LDSM4(aq[kc], sQ + fterm + ((c ^ fxr) << 4));
        uint32_t bf[4];
        LDSM4(bf, sK + fterm + ((c ^ fxr) << 4));
        MMA16816(s[0], aq[kc], bf[0], bf[2]);
        MMA16816(s[1], aq[kc], bf[1], bf[3]);
    }

    const float scale = 0.125f;
    #pragma unroll
    for (int t = 0; t < 2; t++)
        #pragma unroll
        for (int q = 0; q < 4; q++) s[t][q] *= scale;
    float mx0 = fmaxf(fmaxf(s[0][0], s[0][1]), fmaxf(s[1][0], s[1][1]));
    float mx1 = fmaxf(fmaxf(s[0][2], s[0][3]), fmaxf(s[1][2], s[1][3]));
    #pragma unroll
    for (int o = 1; o <= 2; o <<= 1) {
        mx0 = fmaxf(mx0, __shfl_xor_sync(0xffffffffu, mx0, o));
        mx1 = fmaxf(mx1, __shfl_xor_sync(0xffffffffu, mx1, o));
    }
    float sum0 = 0.f, sum1 = 0.f;
    #pragma unroll
    for (int t = 0; t < 2; t++) {
        s[t][0] = __expf(s[t][0] - mx0); sum0 += s[t][0];
        s[t][1] = __expf(s[t][1] - mx0); sum0 += s[t][1];
        s[t][2] = __expf(s[t][2] - mx1); sum1 += s[t][2];
        s[t][3] = __expf(s[t][3] - mx1); sum1 += s[t][3];
    }
    #pragma unroll
    for (int o = 1; o <= 2; o <<= 1) {
        sum0 += __shfl_xor_sync(0xffffffffu, sum0, o);
        sum1 += __shfl_xor_sync(0xffffffffu, sum1, o);
    }
    float inv0 = 1.0f / sum0, inv1 = 1.0f / sum1;

    uint32_t pa[4];
    pa[0] = pack_h2(s[0][0], s[0][1]);
    pa[1] = pack_h2(s[0][2], s[0][3]);
    pa[2] = pack_h2(s[1][0], s[1][1]);
    pa[3] = pack_h2(s[1][2], s[1][3]);

    float o[8][4] = {};
    #pragma unroll
    for (int dt2 = 0; dt2 < 4; dt2++) {
        uint32_t c = dt2 * 2 + csel;
        uint32_t vf[4];
        LDSM4T(vf, sV + fterm + ((c ^ fxr) << 4));
        MMA16816(o[2 * dt2],     pa, vf[0], vf[1]);
        MMA16816(o[2 * dt2 + 1], pa, vf[2], vf[3]);
    }

    int r0 = lane >> 2;
    #pragma unroll
    for (int dt = 0; dt < 8; dt++) {
        int col = h * 64 + dt * 8 + (lane & 3) * 2;
        *(__half2*)(out + (size_t)(R * 16 + r0) * D + col) =
            __floats2half2_rn(o[dt][0] * inv0, o[dt][1] * inv0);
        *(__half2*)(out + (size_t)(R * 16 + r0 + 8) * D + col) =
            __floats2half2_rn(o[dt][2] * inv1, o[dt][3] * inv1);
    }
}

// ---------------- spatial attention: tensor-core FA2-style ----------------
constexpr int Lp = 208;
constexpr int ATTN_SMEM = Lp * 128 * 2 + 64 * 128;

__global__ void __launch_bounds__(128) attn_s_mma(const __half* __restrict__ qkv,
                                                  __half* __restrict__ out) {
    int bt = blockIdx.x, h = blockIdx.y;
    extern __shared__ char sm[];
    const uint32_t sK = smem_u32(sm);
    const uint32_t sV = sK + Lp * 128;
    const uint32_t sQ = sV + Lp * 128;
    const int tid = threadIdx.x, warp = tid >> 5, lane = tid & 31;

    const __half* base = qkv + (size_t)bt * SSP * (3 * D) + h * 64;

    for (int idx = tid; idx < 11 * 8; idx += 128) {
        int r = 197 + (idx >> 3), c = idx & 7;
        uint32_t sw = r * 128 + ((c ^ (r & 7)) << 4);
        *(uint4*)(sm + sw) = make_uint4(0, 0, 0, 0);
        *(uint4*)(sm + Lp * 128 + sw) = make_uint4(0, 0, 0, 0);
    }
    for (int idx = tid; idx < 197 * 8; idx += 128) {
        int r = idx >> 3, c = idx & 7;
        uint32_t sw = r * 128 + ((c ^ (r & 7)) << 4);
        CP_ASYNC16(sK + sw, base + (size_t)r * (3 * D) + D + c * 8);
        CP_ASYNC16(sV + sw, base + (size_t)r * (3 * D) + 2 * D + c * 8);
    }
    CP_COMMIT();

    const uint32_t csel = (lane >> 4) & 1;
    const float scale = 0.125f;

    for (int qt = 0; qt < 4; qt++) {
        int q0 = qt * 64;
        __syncthreads();
        for (int idx = tid; idx < 64 * 8; idx += 128) {
            int r = idx >> 3, c = idx & 7;
            int gr = min(q0 + r, 196);
            uint32_t sw = r * 128 + ((c ^ (r & 7)) << 4);
            CP_ASYNC16(sQ + sw, base + (size_t)gr * (3 * D) + c * 8);
        }
        CP_COMMIT(); CP_WAIT0();
        __syncthreads();

        // last Q tile: warps 1-3 produce only rows >= 197 — skip their compute
        if (q0 + warp * 16 >= SSP) continue;

        uint32_t aq[4][4];
        {
            int arow = warp * 16 + (lane & 15);
            uint32_t aterm = arow * 128, axr = arow & 7;
            #pragma unroll
            for (int kc = 0; kc < 4; kc++) {
                uint32_t c = kc * 2 + csel;
                LDSM4(aq[kc], sQ + aterm + ((c ^ axr) << 4));
            }
        }

        float s[26][4];
        #pragma unroll
        for (int t = 0; t < 26; t++)
            #pragma unroll
            for (int q = 0; q < 4; q++) s[t][q] = 0.f;

        for (int nt2 = 0; nt2 < 13; nt2++) {
            int brow = nt2 * 16 + (lane & 15);
            uint32_t bterm = brow * 128, bxr = brow & 7;
            #pragma unroll
            for (int kc = 0; kc < 4; kc++) {
                uint32_t c = kc * 2 + csel;
                uint32_t bf[4];
                LDSM4(bf, sK + bterm + ((c ^ bxr) << 4));
                MMA16816(s[2 * nt2],     aq[kc], bf[0], bf[2]);
                MMA16816(s[2 * nt2 + 1], aq[kc], bf[1], bf[3]);
            }
        }

        float mx0 = -1e30f, mx1 = -1e30f;
        #pragma unroll
        for (int t = 0; t < 26; t++) {
            int col = t * 8 + (lane & 3) * 2;
            if (col     >= 197) { s[t][0] = -1e30f; s[t][2] = -1e30f; } else { s[t][0] *= scale; s[t][2] *= scale; }
            if (col + 1 >= 197) { s[t][1] = -1e30f; s[t][3] = -1e30f; } else { s[t][1] *= scale; s[t][3] *= scale; }
            mx0 = fmaxf(mx0, fmaxf(s[t][0], s[t][1]));
            mx1 = fmaxf(mx1, fmaxf(s[t][2], s[t][3]));
        }
        #pragma unroll
        for (int o = 1; o <= 2; o <<= 1) {
            mx0 = fmaxf(mx0, __shfl_xor_sync(0xffffffffu, mx0, o));
            mx1 = fmaxf(mx1, __shfl_xor_sync(0xffffffffu, mx1, o));
        }
        float sum0 = 0.f, sum1 = 0.f;
        #pragma unroll
        for (int t = 0; t < 26; t++) {
            s[t][0] = __expf(s[t][0] - mx0); sum0 += s[t][0];
            s[t][1] = __expf(s[t][1] - mx0); sum0 += s[t][1];
            s[t][2] = __expf(s[t][2] - mx1); sum1 += s[t][2];
            s[t][3] = __expf(s[t][3] - mx1); sum1 += s[t][3];
        }
        #pragma unroll
        for (int o = 1; o <= 2; o <<= 1) {
            sum0 += __shfl_xor_sync(0xffffffffu, sum0, o);
            sum1 += __shfl_xor_sync(0xffffffffu, sum1, o);
        }
        float inv0 = 1.0f / sum0, inv1 = 1.0f / sum1;

        uint32_t pa[13][4];
        #pragma unroll
        for (int k = 0; k < 13; k++) {
            pa[k][0] = pack_h2(s[2 * k][0],     s[2 * k][1]);
            pa[k][1] = pack_h2(s[2 * k][2],     s[2 * k][3]);
            pa[k][2] = pack_h2(s[2 * k + 1][0], s[2 * k + 1][1]);
            pa[k][3] = pack_h2(s[2 * k + 1][2], s[2 * k + 1][3]);
        }

        float o[8][4];
        #pragma unroll
        for (int t = 0; t < 8; t++)
            #pragma unroll
            for (int q = 0; q < 4; q++) o[t][q] = 0.f;

        for (int kc = 0; kc < 13; kc++) {
            int vrow = kc * 16 + (lane & 15);
            uint32_t vterm = vrow * 128, vxr = vrow & 7;
            #pragma unroll
            for (int dt2 = 0; dt2 < 4; dt2++) {
                uint32_t c = dt2 * 2 + csel;
                uint32_t vf[4];
                LDSM4T(vf, sV + vterm + ((c ^ vxr) << 4));
                MMA16816(o[2 * dt2],     pa[kc], vf[0], vf[1]);
                MMA16816(o[2 * dt2 + 1], pa[kc], vf[2], vf[3]);
            }
        }

        int r0 = q0 + warp * 16 + (lane >> 2);
        #pragma unroll
        for (int dt = 0; dt < 8; dt++) {
            int col = h * 64 + dt * 8 + (lane & 3) * 2;
            if (r0 < 197)
                *(__half2*)(out + (size_t)(bt * SSP + r0) * D + col) =
                    __floats2half2_rn(o[dt][0] * inv0, o[dt][1] * inv0);
            if (r0 + 8 < 197)
                *(__half2*)(out + (size_t)(bt * SSP + r0 + 8) * D + col) =
                    __floats2half2_rn(o[dt][2] * inv1, o[dt][3] * inv1);
        }
    }
}

// ---------------- launch ----------------
extern "C" void kernel_launch(void* const* d_in, const int* in_sizes, int n_in,
                              void* d_out, int out_size) {
    const float* x        = (const float*)d_in[0];
    const float* tn1_w    = (const float*)d_in[1];
    const float* tn1_b    = (const float*)d_in[2];
    const float* t_qkv_w  = (const float*)d_in[3];
    const float* t_proj_w = (const float*)d_in[4];
    const float* t_proj_b = (const float*)d_in[5];
    const float* tfc_w    = (const float*)d_in[6];
    const float* tfc_b    = (const float*)d_in[7];
    const float* n1_w     = (const float*)d_in[8];
    const float* n1_b     = (const float*)d_in[9];
    const float* s_qkv_w  = (const float*)d_in[10];
    const float* s_proj_w = (const float*)d_in[11];
    const float* s_proj_b = (const float*)d_in[12];
    const float* n2_w     = (const float*)d_in[13];
    const float* n2_b     = (const float*)d_in[14];
    const float* fc1_w    = (const float*)d_in[15];
    const float* fc1_b    = (const float*)d_in[16];
    const float* fc2_w    = (const float*)d_in[17];
    const float* fc2_b    = (const float*)d_in[18];
    float* out = (float*)d_out;

    float  *p_xnc, *p_xt2, *p_xnew, *p_clsb, *p_bcomb;
    __half *p_lnh, *p_qkvh, *p_atth, *p_hidh;
    __half *w_tqkv, *w_comb, *w_tfc, *w_projh, *w_sqkv, *w_sproj, *w_fc1, *w_fc2;
    cudaGetSymbolAddress((void**)&p_xnc,  g_xnc);
    cudaGetSymbolAddress((void**)&p_lnh,  g_lnh);
    cudaGetSymbolAddress((void**)&p_qkvh, g_qkvh);
    cudaGetSymbolAddress((void**)&p_atth, g_atth);
    cudaGetSymbolAddress((void**)&p_xt2,  g_xt2);
    cudaGetSymbolAddress((void**)&p_xnew, g_xnew);
    cudaGetSymbolAddress((void**)&p_hidh, g_hidh);
    cudaGetSymbolAddress((void**)&p_clsb, g_clsb);
    cudaGetSymbolAddress((void**)&p_bcomb,g_bcomb);
    cudaGetSymbolAddress((void**)&w_tqkv, g_w_tqkv);
    cudaGetSymbolAddress((void**)&w_comb, g_w_comb);
    cudaGetSymbolAddress((void**)&w_tfc,  g_w_tfc);
    cudaGetSymbolAddress((void**)&w_projh,g_projw_h);
    cudaGetSymbolAddress((void**)&w_sqkv, g_w_sqkv);
    cudaGetSymbolAddress((void**)&w_sproj,g_w_sproj);
    cudaGetSymbolAddress((void**)&w_fc1,  g_w_fc1);
    cudaGetSymbolAddress((void**)&w_fc2,  g_w_fc2);

    cudaFuncSetAttribute(attn_s_mma, cudaFuncAttributeMaxDynamicSharedMemorySize, ATTN_SMEM);
    cudaFuncSetAttribute(gemm_hmma<0, __half>, cudaFuncAttributeMaxDynamicSharedMemorySize, GEMM_SMEM);
    cudaFuncSetAttribute(gemm_hmma<2, float >, cudaFuncAttributeMaxDynamicSharedMemorySize, GEMM_SMEM);
    cudaFuncSetAttribute(gemm_hmma<3, __half>, cudaFuncAttributeMaxDynamicSharedMemorySize, GEMM_SMEM);
    cudaFuncSetAttribute(gemm_hmma<4, float >, cudaFuncAttributeMaxDynamicSharedMemorySize, GEMM_SMEM);

    // side stream + events for prologue overlap
    static cudaStream_t s2 = nullptr;
    static cudaEvent_t evFork = nullptr, evJoin = nullptr;
    if (!s2) {
        cudaStreamCreateWithFlags(&s2, cudaStreamNonBlocking);
        cudaEventCreateWithFlags(&evFork, cudaEventDisableTiming);
        cudaEventCreateWithFlags(&evJoin, cudaEventDisableTiming);
    }

    // 0) weight transposes (one launch)
    TransJobs jobs;
    auto mkjob = [](const float* W, __half* Wt, int K, int N, int tile0) {
        TransJob j; j.W = W; j.Wt = Wt; j.K = K; j.N = N; j.tile0 = tile0; return j;
    };
    int t0 = 0;
    jobs.j[0] = mkjob(t_qkv_w, w_tqkv, D,   3 * D, t0); t0 += (D / 32) * (3 * D / 32);
    jobs.j[1] = mkjob(tfc_w,   w_tfc,  D,   D,     t0); t0 += (D / 32) * (D / 32);
    jobs.j[2] = mkjob(s_qkv_w, w_sqkv, D,   3 * D, t0); t0 += (D / 32) * (3 * D / 32);
    jobs.j[3] = mkjob(s_proj_w,w_sproj,D,   D,     t0); t0 += (D / 32) * (D / 32);
    jobs.j[4] = mkjob(fc1_w,   w_fc1,  D,   HID,   t0); t0 += (D / 32) * (HID / 32);
    jobs.j[5] = mkjob(fc2_w,   w_fc2,  HID, D,     t0); t0 += (HID / 32) * (D / 32);
    jobs.total = t0;
    transpose_all<<<t0, dim3(32, 8)>>>(jobs);

    // fork: composite-weight chain on s2, overlapping steps 1-3
    cudaEventRecord(evFork, 0);
    cudaStreamWaitEvent(s2, evFork, 0);
    copyround_h<<<(D * D + 255) / 256, 256, 0, s2>>>(t_proj_w, w_projh, D * D);
    gemm_hmma<0, __half><<<dim3(D / 128, D / 128), 256, GEMM_SMEM, s2>>>(D, D, D, w_tfc, w_projh, nullptr, nullptr, w_comb, nullptr);
    bias_comb<<<(D * 32 + 255) / 256, 256, 0, s2>>>(t_proj_b, tfc_w, tfc_b, p_bcomb);
    cudaEventRecord(evJoin, s2);

    // 1) gather + temporal LN
    ln_gather_t<<<(MT + 7) / 8, 256>>>(x, tn1_w, tn1_b, p_xnc, p_lnh);

    // 2) temporal qkv -> half
    gemm_hmma<0, __half><<<dim3(3 * D / 128, MT / 128), 256, GEMM_SMEM>>>(MT, 3 * D, D, p_lnh, w_tqkv, nullptr, nullptr, p_qkvh, nullptr);

    // 3) temporal attention (tensor cores) -> half
    attn_t_mma<<<dim3(Bn * Hh * Ww, 3), 128>>>(p_qkvh, p_atth);

    // join before using w_comb / bcomb
    cudaStreamWaitEvent(0, evJoin, 0);

    // 4) combined proj+tfc + residual(xnc) -> xt2 fp32
    gemm_hmma<2, float><<<dim3(D / 128, MT / 128), 256, GEMM_SMEM>>>(MT, D, D, p_atth, w_comb, p_bcomb, p_xnc, p_xt2, nullptr);

    // 5) spatial LN -> half
    ln_xs_kernel<<<(MS + 7) / 8, 256>>>(x, p_xt2, n1_w, n1_b, p_lnh);

    // 6) spatial qkv -> half
    gemm_hmma<0, __half><<<dim3(3 * D / 128, MS / 128), 256, GEMM_SMEM>>>(MS, 3 * D, D, p_lnh, w_sqkv, nullptr, nullptr, p_qkvh, nullptr);

    // 7) spatial attention (tensor cores) -> half
    attn_s_mma<<<dim3(Bn * Tt, NHh), 128, ATTN_SMEM>>>(p_qkvh, p_atth);

    // 8) spatial proj, fused x_new scatter: xnew[p>0] = xt2 + proj+bias; cls rows -> clsb
    gemm_hmma<4, float><<<dim3(D / 128, MS / 128), 256, GEMM_SMEM>>>(MS, D, D, p_atth, w_sproj, s_proj_b, p_xt2, p_xnew, p_clsb);

    // 9) finish x_new cls rows + final LN over all rows
    ln_build<<<(MX + 7) / 8, 256>>>(x, p_xnew, p_clsb, n2_w, n2_b, p_xnew, p_lnh);

    // 10) fc1 + gelu -> half hid
    gemm_hmma<3, __half><<<dim3(HID / 128, MXP / 128), 256, GEMM_SMEM>>>(MXP, HID, D, p_lnh, w_fc1, fc1_b, nullptr, p_hidh, nullptr);

    // 11) fc2 + residual -> out
    gemm_hmma<2, float><<<dim3(D / 128, MXP / 128), 256, GEMM_SMEM>>>(MX, D, HID, p_hidh, w_fc2, fc2_b, p_xnew, out, nullptr);
}